// round 2
// baseline (speedup 1.0000x reference)
#include <cuda_runtime.h>

#define Bb 4
#define Tt 2048
#define Ee 1024
#define Hh 16
#define Dd 64

// Scratch (allocation-free rule: __device__ globals)
__device__ float g_q[(size_t)Bb * Hh * Tt * Dd];
__device__ float g_k[(size_t)Bb * Hh * Tt * Dd];
__device__ float g_v[(size_t)Bb * Hh * Tt * Dd];
__device__ float g_attn[(size_t)Bb * Tt * Hh * Dd];  // [B,T,H*D]

// Transposed-tile smem index with XOR swizzle on float4 granularity:
// logical (row, col) -> row*64 + 4*(((col/4) ^ (row/4)) & 15) + col%4
__device__ __forceinline__ int tpx(int row, int col) {
    return (row << 6) + ((((col >> 2) ^ (row >> 2)) & 15) << 2) + (col & 3);
}

// Fast exp on the FMA pipe (no MUFU). Valid for x <= ~0 (clamped at -87).
// max rel err ~6e-5.
__device__ __forceinline__ float fexp(float x) {
    x = fmaxf(x, -87.0f);
    float z = fmaf(x, 1.4426950408889634f, 12582912.0f);  // round(x*log2e) in mantissa
    int n = __float_as_int(z) - 0x4B400000;
    float t = z - 12582912.0f;
    float f = fmaf(x, 1.4426950408889634f, -t);  // frac in [-0.5, 0.5]
    float p = 9.6181291e-3f;
    p = fmaf(p, f, 5.5504109e-2f);
    p = fmaf(p, f, 2.4022651e-1f);
    p = fmaf(p, f, 6.9314718e-1f);
    p = fmaf(p, f, 1.0f);
    return p * __int_as_float(0x3F800000 + (n << 23));
}

// ---------------------------------------------------------------------------
// Kernel 1: fused QKV projection.
// grid (H=16, (B*T)/64=128, 3), block 256.
// Each block computes a 64x64 tile of one of q/k/v for one head.
// Output layout: [(b*H+h)*T + t]*D + d
// ---------------------------------------------------------------------------
__global__ void __launch_bounds__(256) qkv_proj(
    const float* __restrict__ x, const float* __restrict__ Wq,
    const float* __restrict__ Wk, const float* __restrict__ Wv)
{
    __shared__ float As[16 * 64];  // transposed+swizzled: [e][r]
    __shared__ float Bs[16 * 64];  // natural: [e][d]

    int h = blockIdx.x;
    int row0 = blockIdx.y << 6;
    const float* W;
    float* outp;
    if (blockIdx.z == 0) { W = Wq; outp = g_q; }
    else if (blockIdx.z == 1) { W = Wk; outp = g_k; }
    else { W = Wv; outp = g_v; }
    W += (size_t)h * Ee * Dd;

    int tid = threadIdx.x;
    int tx = tid & 15, ty = tid >> 4;
    int r0 = ty << 2, c0 = tx << 2;
    int ar = tid >> 2, ae4 = (tid & 3) << 2;   // A-tile load coords
    int be = tid >> 4, bd4 = (tid & 15) << 2;  // B-tile load coords

    float acc[4][4] = {};

    for (int k0 = 0; k0 < Ee; k0 += 16) {
        float4 av = *(const float4*)&x[(size_t)(row0 + ar) * Ee + k0 + ae4];
        float4 bv = *(const float4*)&W[(size_t)(k0 + be) * Dd + bd4];
        __syncthreads();  // previous iteration's reads complete
        As[tpx(ae4 + 0, ar)] = av.x;
        As[tpx(ae4 + 1, ar)] = av.y;
        As[tpx(ae4 + 2, ar)] = av.z;
        As[tpx(ae4 + 3, ar)] = av.w;
        *(float4*)&Bs[be * 64 + bd4] = bv;
        __syncthreads();
#pragma unroll
        for (int e = 0; e < 16; e++) {
            float4 a4 = *(const float4*)&As[tpx(e, r0)];
            float4 b4 = *(const float4*)&Bs[e * 64 + c0];
            float a[4] = {a4.x, a4.y, a4.z, a4.w};
            float b[4] = {b4.x, b4.y, b4.z, b4.w};
#pragma unroll
            for (int i = 0; i < 4; i++)
#pragma unroll
                for (int jj = 0; jj < 4; jj++)
                    acc[i][jj] = fmaf(a[i], b[jj], acc[i][jj]);
        }
    }

#pragma unroll
    for (int i = 0; i < 4; i++) {
        int row = row0 + r0 + i;
        int b = row >> 11;           // row / T
        int t = row & (Tt - 1);
        float4 ov = make_float4(acc[i][0], acc[i][1], acc[i][2], acc[i][3]);
        size_t off = (((size_t)b * Hh + h) * Tt + t) * Dd + c0;
        *(float4*)&outp[off] = ov;
    }
}

// ---------------------------------------------------------------------------
// Kernel 2: causal flash attention, fp32.
// grid (T/64=32, B*H=64), block 256 (16x16 micro-tiling, 4x4 per thread).
// 48KB static smem: q (transposed), k (transposed; reused as P), v (natural).
// ---------------------------------------------------------------------------
__global__ void __launch_bounds__(256) attn_kernel()
{
    __shared__ float q_s[64 * 64];   // [e][r], swizzled, pre-scaled by D^-0.5
    __shared__ float kp_s[64 * 64];  // K: [e][c] swizzled; then P: [c][r] swizzled
    __shared__ float v_s[64 * 64];   // [c][d] natural

    int qi = blockIdx.x;
    int bh = blockIdx.y;
    const float* qb = g_q + ((size_t)bh * Tt + ((size_t)qi << 6)) * Dd;
    const float* kb = g_k + (size_t)bh * Tt * Dd;
    const float* vb = g_v + (size_t)bh * Tt * Dd;

    int tid = threadIdx.x;
    int tx = tid & 15, ty = tid >> 4;
    int r0 = ty << 2, c0 = tx << 2;
    int lr = tid >> 4;              // load row base
    int ld4 = (tid & 15) << 2;      // load col base

    // Load Q tile, scaled, transposed+swizzled
#pragma unroll
    for (int it = 0; it < 4; it++) {
        int r = lr + (it << 4);
        float4 v = *(const float4*)&qb[(size_t)r * Dd + ld4];
        q_s[tpx(ld4 + 0, r)] = v.x * 0.125f;
        q_s[tpx(ld4 + 1, r)] = v.y * 0.125f;
        q_s[tpx(ld4 + 2, r)] = v.z * 0.125f;
        q_s[tpx(ld4 + 3, r)] = v.w * 0.125f;
    }

    float o[4][4] = {};
    float m[4] = {-1e30f, -1e30f, -1e30f, -1e30f};
    float l[4] = {0.f, 0.f, 0.f, 0.f};

    for (int j = 0; j <= qi; j++) {
        __syncthreads();  // previous PV reads done; also covers Q-load on iter 0
        const float* kt = kb + (((size_t)j << 6)) * Dd;
        const float* vt = vb + (((size_t)j << 6)) * Dd;
#pragma unroll
        for (int it = 0; it < 4; it++) {
            int r = lr + (it << 4);
            float4 kv = *(const float4*)&kt[(size_t)r * Dd + ld4];
            kp_s[tpx(ld4 + 0, r)] = kv.x;
            kp_s[tpx(ld4 + 1, r)] = kv.y;
            kp_s[tpx(ld4 + 2, r)] = kv.z;
            kp_s[tpx(ld4 + 3, r)] = kv.w;
            *(float4*)&v_s[r * 64 + ld4] = *(const float4*)&vt[(size_t)r * Dd + ld4];
        }
        __syncthreads();

        // S = (Q * D^-0.5) . K^T  (64 e-steps, 2x LDS.128 + 16 FFMA each)
        float s[4][4] = {};
#pragma unroll 16
        for (int e = 0; e < 64; e++) {
            float4 a4 = *(const float4*)&q_s[tpx(e, r0)];
            float4 b4 = *(const float4*)&kp_s[tpx(e, c0)];
            float a[4] = {a4.x, a4.y, a4.z, a4.w};
            float b[4] = {b4.x, b4.y, b4.z, b4.w};
#pragma unroll
            for (int i = 0; i < 4; i++)
#pragma unroll
                for (int jj = 0; jj < 4; jj++)
                    s[i][jj] = fmaf(a[i], b[jj], s[i][jj]);
        }

        if (j == qi) {  // causal mask on diagonal tile
#pragma unroll
            for (int i = 0; i < 4; i++)
#pragma unroll
                for (int jj = 0; jj < 4; jj++)
                    if (c0 + jj > r0 + i) s[i][jj] = -1e30f;
        }

        __syncthreads();  // all K reads done before overwriting kp_s with P

        // Online softmax (row groups = 16 lanes sharing ty)
        float scl[4];
#pragma unroll
        for (int i = 0; i < 4; i++) {
            float mx = fmaxf(fmaxf(s[i][0], s[i][1]), fmaxf(s[i][2], s[i][3]));
            mx = fmaxf(mx, __shfl_xor_sync(0xffffffffu, mx, 8));
            mx = fmaxf(mx, __shfl_xor_sync(0xffffffffu, mx, 4));
            mx = fmaxf(mx, __shfl_xor_sync(0xffffffffu, mx, 2));
            mx = fmaxf(mx, __shfl_xor_sync(0xffffffffu, mx, 1));
            float mn = fmaxf(m[i], mx);
            float sc = fexp(m[i] - mn);
            float rs = 0.f;
#pragma unroll
            for (int jj = 0; jj < 4; jj++) {
                float pv = fexp(s[i][jj] - mn);
                s[i][jj] = pv;
                rs += pv;
            }
            rs += __shfl_xor_sync(0xffffffffu, rs, 8);
            rs += __shfl_xor_sync(0xffffffffu, rs, 4);
            rs += __shfl_xor_sync(0xffffffffu, rs, 2);
            rs += __shfl_xor_sync(0xffffffffu, rs, 1);
            l[i] = l[i] * sc + rs;
            m[i] = mn;
            scl[i] = sc;
        }

        // Store P transposed into kp_s; rescale O
#pragma unroll
        for (int i = 0; i < 4; i++) {
#pragma unroll
            for (int jj = 0; jj < 4; jj++) {
                kp_s[tpx(c0 + jj, r0 + i)] = s[i][jj];
                o[i][jj] *= scl[i];
            }
        }
        __syncthreads();

        // O += P . V
#pragma unroll 16
        for (int c = 0; c < 64; c++) {
            float4 a4 = *(const float4*)&kp_s[tpx(c, r0)];
            float4 b4 = *(const float4*)&v_s[c * 64 + c0];
            float a[4] = {a4.x, a4.y, a4.z, a4.w};
            float b[4] = {b4.x, b4.y, b4.z, b4.w};
#pragma unroll
            for (int i = 0; i < 4; i++)
#pragma unroll
                for (int jj = 0; jj < 4; jj++)
                    o[i][jj] = fmaf(a[i], b[jj], o[i][jj]);
        }
    }

    // Epilogue: normalize + write concat-head layout [B,T,H*D]
    int b = bh >> 4, h = bh & 15;
    int tbase = (qi << 6) + r0;
#pragma unroll
    for (int i = 0; i < 4; i++) {
        float inv = 1.0f / l[i];
        float4 ov = make_float4(o[i][0] * inv, o[i][1] * inv,
                                o[i][2] * inv, o[i][3] * inv);
        size_t off = (((size_t)b * Tt + (tbase + i)) * Hh + h) * Dd + c0;
        *(float4*)&g_attn[off] = ov;
    }
}

// ---------------------------------------------------------------------------
// Kernel 3: output projection  out = g_attn[8192,1024] @ Wo[1024,1024]
// grid (E/64=16, 8192/64=128), block 256.
// ---------------------------------------------------------------------------
__global__ void __launch_bounds__(256) out_proj(
    const float* __restrict__ Wo, float* __restrict__ out)
{
    __shared__ float As[16 * 64];
    __shared__ float Bs[16 * 64];

    int cb = blockIdx.x << 6;
    int row0 = blockIdx.y << 6;

    int tid = threadIdx.x;
    int tx = tid & 15, ty = tid >> 4;
    int r0 = ty << 2, c0 = tx << 2;
    int ar = tid >> 2, ae4 = (tid & 3) << 2;
    int be = tid >> 4, bd4 = (tid & 15) << 2;

    float acc[4][4] = {};

    for (int k0 = 0; k0 < Hh * Dd; k0 += 16) {
        float4 av = *(const float4*)&g_attn[(size_t)(row0 + ar) * (Hh * Dd) + k0 + ae4];
        float4 bv = *(const float4*)&Wo[(size_t)(k0 + be) * Ee + cb + bd4];
        __syncthreads();
        As[tpx(ae4 + 0, ar)] = av.x;
        As[tpx(ae4 + 1, ar)] = av.y;
        As[tpx(ae4 + 2, ar)] = av.z;
        As[tpx(ae4 + 3, ar)] = av.w;
        *(float4*)&Bs[be * 64 + bd4] = bv;
        __syncthreads();
#pragma unroll
        for (int e = 0; e < 16; e++) {
            float4 a4 = *(const float4*)&As[tpx(e, r0)];
            float4 b4 = *(const float4*)&Bs[e * 64 + c0];
            float a[4] = {a4.x, a4.y, a4.z, a4.w};
            float b[4] = {b4.x, b4.y, b4.z, b4.w};
#pragma unroll
            for (int i = 0; i < 4; i++)
#pragma unroll
                for (int jj = 0; jj < 4; jj++)
                    acc[i][jj] = fmaf(a[i], b[jj], acc[i][jj]);
        }
    }

#pragma unroll
    for (int i = 0; i < 4; i++) {
        float4 ov = make_float4(acc[i][0], acc[i][1], acc[i][2], acc[i][3]);
        *(float4*)&out[(size_t)(row0 + r0 + i) * Ee + cb + c0] = ov;
    }
}

// ---------------------------------------------------------------------------
extern "C" void kernel_launch(void* const* d_in, const int* in_sizes, int n_in,
                              void* d_out, int out_size) {
    const float* x  = (const float*)d_in[0];
    const float* Wq = (const float*)d_in[1];
    const float* Wk = (const float*)d_in[2];
    const float* Wv = (const float*)d_in[3];
    const float* Wo = (const float*)d_in[4];
    float* out = (float*)d_out;

    qkv_proj<<<dim3(Hh, (Bb * Tt) / 64, 3), 256>>>(x, Wq, Wk, Wv);
    attn_kernel<<<dim3(Tt / 64, Bb * Hh), 256>>>();
    out_proj<<<dim3(Ee / 64, (Bb * Tt) / 64), 256>>>(Wo, out);
}

// round 3
// speedup vs baseline: 1.3369x; 1.3369x over previous
#include <cuda_runtime.h>

#define Bb 4
#define Tt 2048
#define Ee 1024
#define Hh 16
#define Dd 64

typedef unsigned long long ull;

// Scratch (allocation-free rule: __device__ globals)
__device__ float g_q[(size_t)Bb * Hh * Tt * Dd];
__device__ float g_k[(size_t)Bb * Hh * Tt * Dd];
__device__ float g_v[(size_t)Bb * Hh * Tt * Dd];
__device__ float g_attn[(size_t)Bb * Tt * Hh * Dd];  // [B,T,H*D]

// ---- packed fp32x2 helpers (sm_103a FFMA2 path) ----
__device__ __forceinline__ ull pk2(float x, float y) {
    ull r; asm("mov.b64 %0,{%1,%2};" : "=l"(r) : "f"(x), "f"(y)); return r;
}
__device__ __forceinline__ void upk2(ull v, float& x, float& y) {
    asm("mov.b64 {%0,%1},%2;" : "=f"(x), "=f"(y) : "l"(v));
}
__device__ __forceinline__ void ffma2(ull& d, ull a, ull b) {
    asm("fma.rn.f32x2 %0,%1,%2,%3;" : "=l"(d) : "l"(a), "l"(b), "l"(d));
}
__device__ __forceinline__ ull fmul2(ull a, ull b) {
    ull d; asm("mul.rn.f32x2 %0,%1,%2;" : "=l"(d) : "l"(a), "l"(b)); return d;
}

// Swizzled index for row width 128 floats: quad-XOR keeps LDS.128 conflict-free
__device__ __forceinline__ int swz(int r, int c) {
    int j = c >> 2;
    j ^= (j >> 3);
    return (r << 7) + (j << 2) + (c & 3);
}

// Fast exp on the FMA pipe (no MUFU), x <= 0 expected, clamped at -87.
__device__ __forceinline__ float fexp(float x) {
    x = fmaxf(x, -87.0f);
    float z = fmaf(x, 1.4426950408889634f, 12582912.0f);
    int n = __float_as_int(z) - 0x4B400000;
    float t = z - 12582912.0f;
    float f = fmaf(x, 1.4426950408889634f, -t);
    float p = 9.6181291e-3f;
    p = fmaf(p, f, 5.5504109e-2f);
    p = fmaf(p, f, 2.4022651e-1f);
    p = fmaf(p, f, 6.9314718e-1f);
    p = fmaf(p, f, 1.0f);
    return p * __int_as_float(0x3F800000 + (n << 23));
}

// ---------------------------------------------------------------------------
// Kernel 1: fused QKV projection. 128x128 tiles, 8x8 micro, FFMA2.
// grid (HD/128=8, (B*T)/128=64, 3), block 256.
// ---------------------------------------------------------------------------
__global__ void __launch_bounds__(256, 2) qkv_proj(
    const float* __restrict__ x, const float* __restrict__ Wq,
    const float* __restrict__ Wk, const float* __restrict__ Wv)
{
    __shared__ float As[16 * 128];  // [k][m], swizzled
    __shared__ float Bs[16 * 128];  // [k][n], swizzled

    int cb = blockIdx.x << 7;   // col tile base in H*D
    int row0 = blockIdx.y << 7;
    const float* W;
    float* outp;
    if (blockIdx.z == 0) { W = Wq; outp = g_q; }
    else if (blockIdx.z == 1) { W = Wk; outp = g_k; }
    else { W = Wv; outp = g_v; }

    int tid = threadIdx.x;
    int tx = tid & 15, ty = tid >> 4;
    int m0 = ty << 3, n0 = tx << 3;
    int am = tid >> 1;                 // A load: row m (pairs of threads share m)
    int bk = tid >> 4;                 // B load: k row
    int bn = (tid & 15) << 3;          // B load: col base

    // B gmem addressing: global col = cb + bn -> head h, within-head d
    int nng = cb + bn;
    int bh_ = nng >> 6, bd_ = nng & 63;
    const float* Wb = W + (size_t)bh_ * Ee * Dd + bd_;

    ull acc[8][4];
#pragma unroll
    for (int i = 0; i < 8; i++)
#pragma unroll
        for (int p = 0; p < 4; p++) acc[i][p] = 0ull;

    for (int k0 = 0; k0 < Ee; k0 += 16) {
        float4 a_ld[2], b_ld[2];
#pragma unroll
        for (int it = 0; it < 2; it++) {
            int k4 = ((tid & 1) << 2) + (it << 3);
            a_ld[it] = *(const float4*)&x[(size_t)(row0 + am) * Ee + k0 + k4];
        }
        b_ld[0] = *(const float4*)&Wb[(size_t)(k0 + bk) * Dd];
        b_ld[1] = *(const float4*)&Wb[(size_t)(k0 + bk) * Dd + 4];

        __syncthreads();
#pragma unroll
        for (int it = 0; it < 2; it++) {
            int k4 = ((tid & 1) << 2) + (it << 3);
            float av[4] = {a_ld[it].x, a_ld[it].y, a_ld[it].z, a_ld[it].w};
#pragma unroll
            for (int u = 0; u < 4; u++) As[swz(k4 + u, am)] = av[u];
        }
        *(float4*)&Bs[swz(bk, bn)] = b_ld[0];
        *(float4*)&Bs[swz(bk, bn + 4)] = b_ld[1];
        __syncthreads();

#pragma unroll
        for (int e = 0; e < 16; e++) {
            float4 a0 = *(const float4*)&As[swz(e, m0)];
            float4 a1 = *(const float4*)&As[swz(e, m0 + 4)];
            float4 b0 = *(const float4*)&Bs[swz(e, n0)];
            float4 b1 = *(const float4*)&Bs[swz(e, n0 + 4)];
            ull bp[4] = {pk2(b0.x, b0.y), pk2(b0.z, b0.w),
                         pk2(b1.x, b1.y), pk2(b1.z, b1.w)};
            float aa[8] = {a0.x, a0.y, a0.z, a0.w, a1.x, a1.y, a1.z, a1.w};
#pragma unroll
            for (int i = 0; i < 8; i++) {
                ull ad = pk2(aa[i], aa[i]);
#pragma unroll
                for (int p = 0; p < 4; p++) ffma2(acc[i][p], ad, bp[p]);
            }
        }
    }

    // Epilogue: out layout [(b*H+h)*T + t]*D + d
    int oh = (cb + n0) >> 6, od = (cb + n0) & 63;
#pragma unroll
    for (int i = 0; i < 8; i++) {
        int row = row0 + m0 + i;
        int b = row >> 11, t = row & (Tt - 1);
        float v0, v1, v2, v3, v4, v5, v6, v7;
        upk2(acc[i][0], v0, v1); upk2(acc[i][1], v2, v3);
        upk2(acc[i][2], v4, v5); upk2(acc[i][3], v6, v7);
        size_t off = (((size_t)b * Hh + oh) * Tt + t) * Dd + od;
        *(float4*)&outp[off] = make_float4(v0, v1, v2, v3);
        *(float4*)&outp[off + 4] = make_float4(v4, v5, v6, v7);
    }
}

// ---------------------------------------------------------------------------
// Kernel 2: causal flash attention. 128x128 Q/K tiles, 8x8 micro QK, 8x4 PV.
// grid (T/128=16 reversed, B*H=64), block 256, 160KB dynamic smem.
// ---------------------------------------------------------------------------
__global__ void __launch_bounds__(256, 1) attn_kernel()
{
    extern __shared__ float sm[];
    float* q_s = sm;             // [d][m] 64x128 swizzled, pre-scaled
    float* k_s = sm + 8192;      // [d][c] 64x128 swizzled
    float* v_s = sm + 16384;     // [c][d] 128x64 natural
    float* p_s = sm + 24576;     // [m][c] 128x128 swizzled

    int qi = (gridDim.x - 1) - blockIdx.x;  // long blocks first
    int bh = blockIdx.y;
    const float* qb = g_q + ((size_t)bh * Tt + ((size_t)qi << 7)) * Dd;
    const float* kb = g_k + (size_t)bh * Tt * Dd;
    const float* vb = g_v + (size_t)bh * Tt * Dd;

    int tid = threadIdx.x;
    int tx = tid & 15, ty = tid >> 4;
    int m0 = ty << 3, n0 = tx << 3, d0 = tx << 2;

    // ---- load Q transposed+scaled: thread pairs share row c, 32B contiguous
    {
        int qr = tid >> 1;
#pragma unroll
        for (int it = 0; it < 8; it++) {
            int d4 = ((tid & 1) << 2) + (it << 3);
            float4 v = *(const float4*)&qb[(size_t)qr * Dd + d4];
            float av[4] = {v.x, v.y, v.z, v.w};
#pragma unroll
            for (int u = 0; u < 4; u++) q_s[swz(d4 + u, qr)] = av[u] * 0.125f;
        }
    }

    ull o2[8][2];
    float m[8], l[8];
#pragma unroll
    for (int i = 0; i < 8; i++) { o2[i][0] = 0ull; o2[i][1] = 0ull; m[i] = -1e30f; l[i] = 0.f; }

    for (int j = 0; j <= qi; j++) {
        const float* kt = kb + ((size_t)j << 7) * Dd;
        const float* vt = vb + ((size_t)j << 7) * Dd;

        __syncthreads();  // prior PV reads done; covers Q store on j==0

        // K transposed: same pair-mapping as Q
        {
            int kr = tid >> 1;
#pragma unroll
            for (int it = 0; it < 8; it++) {
                int d4 = ((tid & 1) << 2) + (it << 3);
                float4 v = *(const float4*)&kt[(size_t)kr * Dd + d4];
                float av[4] = {v.x, v.y, v.z, v.w};
#pragma unroll
                for (int u = 0; u < 4; u++) k_s[swz(d4 + u, kr)] = av[u];
            }
        }
        // V natural copy (fully coalesced)
#pragma unroll
        for (int it = 0; it < 8; it++) {
            int fi = (it << 8) + tid;
            int vr = fi >> 4, vd = (fi & 15) << 2;
            *(float4*)&v_s[vr * 64 + vd] = *(const float4*)&vt[(size_t)vr * Dd + vd];
        }
        __syncthreads();

        // ---- S = Q . K^T
        ull s2[8][4];
#pragma unroll
        for (int i = 0; i < 8; i++)
#pragma unroll
            for (int p = 0; p < 4; p++) s2[i][p] = 0ull;

#pragma unroll 8
        for (int e = 0; e < 64; e++) {
            float4 a0 = *(const float4*)&q_s[swz(e, m0)];
            float4 a1 = *(const float4*)&q_s[swz(e, m0 + 4)];
            float4 b0 = *(const float4*)&k_s[swz(e, n0)];
            float4 b1 = *(const float4*)&k_s[swz(e, n0 + 4)];
            ull bp[4] = {pk2(b0.x, b0.y), pk2(b0.z, b0.w),
                         pk2(b1.x, b1.y), pk2(b1.z, b1.w)};
            float aa[8] = {a0.x, a0.y, a0.z, a0.w, a1.x, a1.y, a1.z, a1.w};
#pragma unroll
            for (int i = 0; i < 8; i++) {
                ull ad = pk2(aa[i], aa[i]);
#pragma unroll
                for (int p = 0; p < 4; p++) ffma2(s2[i][p], ad, bp[p]);
            }
        }

        float s[8][8];
#pragma unroll
        for (int i = 0; i < 8; i++)
#pragma unroll
            for (int p = 0; p < 4; p++) upk2(s2[i][p], s[i][2 * p], s[i][2 * p + 1]);

        if (j == qi) {  // causal mask on diagonal tile
#pragma unroll
            for (int i = 0; i < 8; i++)
#pragma unroll
                for (int jj = 0; jj < 8; jj++)
                    if (n0 + jj > m0 + i) s[i][jj] = -1e30f;
        }

        // ---- online softmax (rows shared across 16 tx lanes)
#pragma unroll
        for (int i = 0; i < 8; i++) {
            float mx = s[i][0];
#pragma unroll
            for (int jj = 1; jj < 8; jj++) mx = fmaxf(mx, s[i][jj]);
            mx = fmaxf(mx, __shfl_xor_sync(0xffffffffu, mx, 8));
            mx = fmaxf(mx, __shfl_xor_sync(0xffffffffu, mx, 4));
            mx = fmaxf(mx, __shfl_xor_sync(0xffffffffu, mx, 2));
            mx = fmaxf(mx, __shfl_xor_sync(0xffffffffu, mx, 1));
            float mn = fmaxf(m[i], mx);
            float sc = fexp(m[i] - mn);
            float rs = 0.f;
#pragma unroll
            for (int jj = 0; jj < 8; jj++) {
                float pv = fexp(s[i][jj] - mn);
                s[i][jj] = pv;
                rs += pv;
            }
            rs += __shfl_xor_sync(0xffffffffu, rs, 8);
            rs += __shfl_xor_sync(0xffffffffu, rs, 4);
            rs += __shfl_xor_sync(0xffffffffu, rs, 2);
            rs += __shfl_xor_sync(0xffffffffu, rs, 1);
            l[i] = l[i] * sc + rs;
            m[i] = mn;
            ull sd = pk2(sc, sc);
            o2[i][0] = fmul2(o2[i][0], sd);
            o2[i][1] = fmul2(o2[i][1], sd);
            // P row-major [m][c]: conflict-free swizzled STS.128
            *(float4*)&p_s[swz(m0 + i, n0)] = make_float4(s[i][0], s[i][1], s[i][2], s[i][3]);
            *(float4*)&p_s[swz(m0 + i, n0 + 4)] = make_float4(s[i][4], s[i][5], s[i][6], s[i][7]);
        }
        __syncthreads();

        // ---- O += P . V  (8 rows x 4 d-cols per thread, c in chunks of 4)
#pragma unroll 4
        for (int c4 = 0; c4 < 128; c4 += 4) {
            float pav[8][4];
#pragma unroll
            for (int i = 0; i < 8; i++) {
                float4 pa = *(const float4*)&p_s[swz(m0 + i, c4)];
                pav[i][0] = pa.x; pav[i][1] = pa.y; pav[i][2] = pa.z; pav[i][3] = pa.w;
            }
            float4 vr[4];
#pragma unroll
            for (int cc = 0; cc < 4; cc++)
                vr[cc] = *(const float4*)&v_s[(c4 + cc) * 64 + d0];
#pragma unroll
            for (int cc = 0; cc < 4; cc++) {
                ull vp0 = pk2(vr[cc].x, vr[cc].y);
                ull vp1 = pk2(vr[cc].z, vr[cc].w);
#pragma unroll
                for (int i = 0; i < 8; i++) {
                    ull ad = pk2(pav[i][cc], pav[i][cc]);
                    ffma2(o2[i][0], ad, vp0);
                    ffma2(o2[i][1], ad, vp1);
                }
            }
        }
    }

    // ---- epilogue: normalize, write [B,T,H*D]
    int b = bh >> 4, h = bh & 15;
#pragma unroll
    for (int i = 0; i < 8; i++) {
        float inv = 1.0f / l[i];
        float v0, v1, v2, v3;
        upk2(o2[i][0], v0, v1);
        upk2(o2[i][1], v2, v3);
        int t = (qi << 7) + m0 + i;
        size_t off = (((size_t)b * Tt + t) * (Hh * Dd)) + h * Dd + d0;
        *(float4*)&g_attn[off] = make_float4(v0 * inv, v1 * inv, v2 * inv, v3 * inv);
    }
}

// ---------------------------------------------------------------------------
// Kernel 3: output projection  out = g_attn[8192,1024] @ Wo[1024,1024]
// grid (E/128=8, 8192/128=64), block 256.
// ---------------------------------------------------------------------------
__global__ void __launch_bounds__(256, 2) out_proj(
    const float* __restrict__ Wo, float* __restrict__ out)
{
    __shared__ float As[16 * 128];
    __shared__ float Bs[16 * 128];

    int cb = blockIdx.x << 7;
    int row0 = blockIdx.y << 7;

    int tid = threadIdx.x;
    int tx = tid & 15, ty = tid >> 4;
    int m0 = ty << 3, n0 = tx << 3;
    int am = tid >> 1;
    int bk = tid >> 4;
    int bn = (tid & 15) << 3;

    ull acc[8][4];
#pragma unroll
    for (int i = 0; i < 8; i++)
#pragma unroll
        for (int p = 0; p < 4; p++) acc[i][p] = 0ull;

    for (int k0 = 0; k0 < Hh * Dd; k0 += 16) {
        float4 a_ld[2], b_ld[2];
#pragma unroll
        for (int it = 0; it < 2; it++) {
            int k4 = ((tid & 1) << 2) + (it << 3);
            a_ld[it] = *(const float4*)&g_attn[(size_t)(row0 + am) * (Hh * Dd) + k0 + k4];
        }
        b_ld[0] = *(const float4*)&Wo[(size_t)(k0 + bk) * Ee + cb + bn];
        b_ld[1] = *(const float4*)&Wo[(size_t)(k0 + bk) * Ee + cb + bn + 4];

        __syncthreads();
#pragma unroll
        for (int it = 0; it < 2; it++) {
            int k4 = ((tid & 1) << 2) + (it << 3);
            float av[4] = {a_ld[it].x, a_ld[it].y, a_ld[it].z, a_ld[it].w};
#pragma unroll
            for (int u = 0; u < 4; u++) As[swz(k4 + u, am)] = av[u];
        }
        *(float4*)&Bs[swz(bk, bn)] = b_ld[0];
        *(float4*)&Bs[swz(bk, bn + 4)] = b_ld[1];
        __syncthreads();

#pragma unroll
        for (int e = 0; e < 16; e++) {
            float4 a0 = *(const float4*)&As[swz(e, m0)];
            float4 a1 = *(const float4*)&As[swz(e, m0 + 4)];
            float4 b0 = *(const float4*)&Bs[swz(e, n0)];
            float4 b1 = *(const float4*)&Bs[swz(e, n0 + 4)];
            ull bp[4] = {pk2(b0.x, b0.y), pk2(b0.z, b0.w),
                         pk2(b1.x, b1.y), pk2(b1.z, b1.w)};
            float aa[8] = {a0.x, a0.y, a0.z, a0.w, a1.x, a1.y, a1.z, a1.w};
#pragma unroll
            for (int i = 0; i < 8; i++) {
                ull ad = pk2(aa[i], aa[i]);
#pragma unroll
                for (int p = 0; p < 4; p++) ffma2(acc[i][p], ad, bp[p]);
            }
        }
    }

#pragma unroll
    for (int i = 0; i < 8; i++) {
        float v0, v1, v2, v3, v4, v5, v6, v7;
        upk2(acc[i][0], v0, v1); upk2(acc[i][1], v2, v3);
        upk2(acc[i][2], v4, v5); upk2(acc[i][3], v6, v7);
        size_t off = (size_t)(row0 + m0 + i) * Ee + cb + n0;
        *(float4*)&out[off] = make_float4(v0, v1, v2, v3);
        *(float4*)&out[off + 4] = make_float4(v4, v5, v6, v7);
    }
}

// ---------------------------------------------------------------------------
extern "C" void kernel_launch(void* const* d_in, const int* in_sizes, int n_in,
                              void* d_out, int out_size) {
    const float* x  = (const float*)d_in[0];
    const float* Wq = (const float*)d_in[1];
    const float* Wk = (const float*)d_in[2];
    const float* Wv = (const float*)d_in[3];
    const float* Wo = (const float*)d_in[4];
    float* out = (float*)d_out;

    const int ATTN_SMEM = 40960 * sizeof(float);  // 160 KB
    cudaFuncSetAttribute(attn_kernel, cudaFuncAttributeMaxDynamicSharedMemorySize, ATTN_SMEM);

    qkv_proj<<<dim3(8, (Bb * Tt) / 128, 3), 256>>>(x, Wq, Wk, Wv);
    attn_kernel<<<dim3(Tt / 128, Bb * Hh), 256, ATTN_SMEM>>>();
    out_proj<<<dim3(8, (Bb * Tt) / 128), 256>>>(Wo, out);
}

// round 5
// speedup vs baseline: 2.1251x; 1.5896x over previous
#include <cuda_runtime.h>
#include <cuda_bf16.h>

#define Bb 4
#define Tt 2048
#define Ee 1024
#define Hh 16
#define Dd 64
#define MT (Bb * Tt)   // 8192 rows

typedef unsigned long long ull;
typedef unsigned int u32;

// ---------------- device scratch (allocation-free rule) ----------------
__device__ __align__(16) float g_q[(size_t)Bb * Hh * Tt * Dd];
__device__ __align__(16) float g_k[(size_t)Bb * Hh * Tt * Dd];
__device__ __align__(16) float g_v[(size_t)Bb * Hh * Tt * Dd];
__device__ __align__(16) __nv_bfloat16 g_xhi[(size_t)MT * Ee];
__device__ __align__(16) __nv_bfloat16 g_xlo[(size_t)MT * Ee];
__device__ __align__(16) __nv_bfloat16 g_wt_hi[(size_t)3 * Hh * Dd * Ee];  // [mat][h*64+d][e]
__device__ __align__(16) __nv_bfloat16 g_wt_lo[(size_t)3 * Hh * Dd * Ee];
__device__ __align__(16) __nv_bfloat16 g_wot_hi[(size_t)Ee * Ee];          // [n][e]
__device__ __align__(16) __nv_bfloat16 g_wot_lo[(size_t)Ee * Ee];
__device__ __align__(16) __nv_bfloat16 g_ahi[(size_t)MT * Ee];
__device__ __align__(16) __nv_bfloat16 g_alo[(size_t)MT * Ee];

// ---------------- PTX helpers (all non-"a" features: sm_80-safe) ----------------
__device__ __forceinline__ u32 smem_u32(const void* p) {
    u32 a;
    asm("{ .reg .u64 t; cvta.to.shared.u64 t, %1; cvt.u32.u64 %0, t; }"
        : "=r"(a) : "l"(p));
    return a;
}
__device__ __forceinline__ void cpa16(u32 dst, const void* src) {
    asm volatile("cp.async.cg.shared.global [%0], [%1], 16;"
                 :: "r"(dst), "l"(src) : "memory");
}
#define CP_COMMIT() asm volatile("cp.async.commit_group;" ::: "memory")
#define CP_WAIT1()  asm volatile("cp.async.wait_group 1;" ::: "memory")
#define CP_WAIT0()  asm volatile("cp.async.wait_group 0;" ::: "memory")

__device__ __forceinline__ void ldsm4(u32 addr, u32& r0, u32& r1, u32& r2, u32& r3) {
    asm volatile("ldmatrix.sync.aligned.m8n8.x4.shared.b16 {%0,%1,%2,%3}, [%4];"
                 : "=r"(r0), "=r"(r1), "=r"(r2), "=r"(r3) : "r"(addr));
}
__device__ __forceinline__ void mma16816(float* d, u32 a0, u32 a1, u32 a2, u32 a3,
                                         u32 b0, u32 b1) {
    asm volatile(
        "mma.sync.aligned.m16n8k16.row.col.f32.bf16.bf16.f32 "
        "{%0,%1,%2,%3},{%4,%5,%6,%7},{%8,%9},{%0,%1,%2,%3};"
        : "+f"(d[0]), "+f"(d[1]), "+f"(d[2]), "+f"(d[3])
        : "r"(a0), "r"(a1), "r"(a2), "r"(a3), "r"(b0), "r"(b1));
}

// ---- packed fp32x2 helpers (attn SIMT kernel) ----
__device__ __forceinline__ ull pk2(float x, float y) {
    ull r; asm("mov.b64 %0,{%1,%2};" : "=l"(r) : "f"(x), "f"(y)); return r;
}
__device__ __forceinline__ void upk2(ull v, float& x, float& y) {
    asm("mov.b64 {%0,%1},%2;" : "=f"(x), "=f"(y) : "l"(v));
}
__device__ __forceinline__ void ffma2(ull& d, ull a, ull b) {
    asm("fma.rn.f32x2 %0,%1,%2,%3;" : "=l"(d) : "l"(a), "l"(b), "l"(d));
}
__device__ __forceinline__ ull fmul2(ull a, ull b) {
    ull d; asm("mul.rn.f32x2 %0,%1,%2;" : "=l"(d) : "l"(a), "l"(b)); return d;
}
__device__ __forceinline__ int swz(int r, int c) {
    int j = c >> 2;
    j ^= (j >> 3);
    return (r << 7) + (j << 2) + (c & 3);
}
__device__ __forceinline__ float fexp(float x) {
    x = fmaxf(x, -87.0f);
    float z = fmaf(x, 1.4426950408889634f, 12582912.0f);
    int n = __float_as_int(z) - 0x4B400000;
    float t = z - 12582912.0f;
    float f = fmaf(x, 1.4426950408889634f, -t);
    float p = 9.6181291e-3f;
    p = fmaf(p, f, 5.5504109e-2f);
    p = fmaf(p, f, 2.4022651e-1f);
    p = fmaf(p, f, 6.9314718e-1f);
    p = fmaf(p, f, 1.0f);
    return p * __int_as_float(0x3F800000 + (n << 23));
}
__device__ __forceinline__ void split_bf16(float v, __nv_bfloat16& hi, __nv_bfloat16& lo) {
    hi = __float2bfloat16(v);
    lo = __float2bfloat16(v - __bfloat162float(hi));
}

// ---------------------------------------------------------------------------
// Prep kernels
// ---------------------------------------------------------------------------
__global__ void __launch_bounds__(256) conv_x(const float* __restrict__ x) {
    size_t i = ((size_t)blockIdx.x * 256 + threadIdx.x) * 4;
    float4 v = *(const float4*)&x[i];
    __nv_bfloat16 h0, h1, h2, h3, l0, l1, l2, l3;
    split_bf16(v.x, h0, l0); split_bf16(v.y, h1, l1);
    split_bf16(v.z, h2, l2); split_bf16(v.w, h3, l3);
    ((__nv_bfloat162*)(g_xhi + i))[0] = __halves2bfloat162(h0, h1);
    ((__nv_bfloat162*)(g_xhi + i))[1] = __halves2bfloat162(h2, h3);
    ((__nv_bfloat162*)(g_xlo + i))[0] = __halves2bfloat162(l0, l1);
    ((__nv_bfloat162*)(g_xlo + i))[1] = __halves2bfloat162(l2, l3);
}

__global__ void __launch_bounds__(256) prep_wqkv(
    const float* __restrict__ Wq, const float* __restrict__ Wk,
    const float* __restrict__ Wv)
{
    __shared__ float tile[32][33];
    int z = blockIdx.z;
    int mat = z >> 4, h = z & 15;
    const float* W = (mat == 0 ? Wq : (mat == 1 ? Wk : Wv)) + (size_t)h * Ee * Dd;
    __nv_bfloat16* dhi = g_wt_hi + ((size_t)mat * Hh + h) * Dd * Ee;
    __nv_bfloat16* dlo = g_wt_lo + ((size_t)mat * Hh + h) * Dd * Ee;
    int e0 = blockIdx.y << 5, d0 = blockIdx.x << 5;
    int tx = threadIdx.x & 31, ty = threadIdx.x >> 5;
#pragma unroll
    for (int j = 0; j < 4; j++)
        tile[ty + j * 8][tx] = W[(size_t)(e0 + ty + j * 8) * Dd + d0 + tx];
    __syncthreads();
#pragma unroll
    for (int j = 0; j < 4; j++) {
        int rr = ty + j * 8;
        float v = tile[tx][rr];
        __nv_bfloat16 hi, lo;
        split_bf16(v, hi, lo);
        size_t off = (size_t)(d0 + rr) * Ee + e0 + tx;
        dhi[off] = hi;
        dlo[off] = lo;
    }
}

__global__ void __launch_bounds__(256) prep_wo(const float* __restrict__ Wo) {
    __shared__ float tile[32][33];
    int n0 = blockIdx.x << 5, e0 = blockIdx.y << 5;
    int tx = threadIdx.x & 31, ty = threadIdx.x >> 5;
#pragma unroll
    for (int j = 0; j < 4; j++)
        tile[ty + j * 8][tx] = Wo[(size_t)(e0 + ty + j * 8) * Ee + n0 + tx];
    __syncthreads();
#pragma unroll
    for (int j = 0; j < 4; j++) {
        int rr = ty + j * 8;
        float v = tile[tx][rr];
        __nv_bfloat16 hi, lo;
        split_bf16(v, hi, lo);
        size_t off = (size_t)(n0 + rr) * Ee + e0 + tx;
        g_wot_hi[off] = hi;
        g_wot_lo[off] = lo;
    }
}

// ---------------------------------------------------------------------------
// mma.sync GEMM machinery: 128x128x64 CTA tiles, split-bf16 3-pass.
// smem tile: 128 rows x 64 bf16 (128B rows), per-row chunk-XOR swizzle.
// Buffers: [buf][Ah|Al|Bh|Bl] each 16KB -> 2*64KB = 128KB dynamic smem.
// ---------------------------------------------------------------------------
#define TILE_B   16384u
#define BUF_B    65536u
#define GEMM_SMEM (2u * BUF_B)

__device__ __forceinline__ void copy_tile_async(u32 tb, const __nv_bfloat16* sp, int tid) {
#pragma unroll
    for (int it = 0; it < 4; it++) {
        int cid = it * 256 + tid;
        int row = cid >> 3, c = cid & 7;
        u32 dst = tb + (u32)(row << 7) + (u32)(((c ^ (row & 7))) << 4);
        cpa16(dst, sp + (size_t)row * Ee + c * 8);
    }
}

// per-chunk compute: 4 ksteps x (12 ldmatrix.x4 + 48 HMMA)
__device__ __forceinline__ void gemm_chunk(
    u32 sb,                       // buffer base (Ah at +0, Al +16K, Bh +32K, Bl +48K)
    const u32* aoff, const u32* a7, u32 cA,
    const u32* boff, const u32* b7, u32 cB,
    float acc[4][4][4])
{
    u32 sAh = sb, sAl = sb + TILE_B, sBh = sb + 2 * TILE_B, sBl = sb + 3 * TILE_B;
#pragma unroll
    for (int s = 0; s < 4; s++) {
        u32 ah[4][4], al[4][4], bh[2][4], bl[2][4];
#pragma unroll
        for (int mt = 0; mt < 4; mt++) {
            u32 ca = (u32)(((2 * s + cA) ^ a7[mt]) << 4);
            ldsm4(sAh + aoff[mt] + ca, ah[mt][0], ah[mt][1], ah[mt][2], ah[mt][3]);
            ldsm4(sAl + aoff[mt] + ca, al[mt][0], al[mt][1], al[mt][2], al[mt][3]);
        }
#pragma unroll
        for (int np = 0; np < 2; np++) {
            u32 cb = (u32)(((2 * s + cB) ^ b7[np]) << 4);
            ldsm4(sBh + boff[np] + cb, bh[np][0], bh[np][1], bh[np][2], bh[np][3]);
            ldsm4(sBl + boff[np] + cb, bl[np][0], bl[np][1], bl[np][2], bl[np][3]);
        }
#pragma unroll
        for (int mt = 0; mt < 4; mt++) {
#pragma unroll
            for (int nt = 0; nt < 4; nt++) {
                int np = nt >> 1, sel = (nt & 1) << 1;
                mma16816(acc[mt][nt], ah[mt][0], ah[mt][1], ah[mt][2], ah[mt][3],
                         bh[np][sel], bh[np][sel + 1]);
                mma16816(acc[mt][nt], ah[mt][0], ah[mt][1], ah[mt][2], ah[mt][3],
                         bl[np][sel], bl[np][sel + 1]);
                mma16816(acc[mt][nt], al[mt][0], al[mt][1], al[mt][2], al[mt][3],
                         bh[np][sel], bh[np][sel + 1]);
            }
        }
    }
}

// setup lane fragment offsets
__device__ __forceinline__ void frag_setup(int lane, int Wm, int Wn,
                                           u32* aoff, u32* a7, u32& cA,
                                           u32* boff, u32* b7, u32& cB) {
#pragma unroll
    for (int mt = 0; mt < 4; mt++) {
        int r = Wm + mt * 16 + (lane & 15);
        aoff[mt] = (u32)(r << 7);
        a7[mt] = (u32)(r & 7);
    }
#pragma unroll
    for (int np = 0; np < 2; np++) {
        int r = Wn + np * 16 + ((lane >> 4) << 3) + (lane & 7);
        boff[np] = (u32)(r << 7);
        b7[np] = (u32)(r & 7);
    }
    cA = (u32)(lane >> 4);
    cB = (u32)((lane >> 3) & 1);
}

// ---------------------------------------------------------------------------
// QKV projection: C[8192, 3072] = X * [Wq|Wk|Wv]^T. grid (24, 64), block 256.
// ---------------------------------------------------------------------------
__global__ void __launch_bounds__(256, 1) qkv_mma() {
    extern __shared__ char smraw[];
    u32 sbase = smem_u32(smraw);

    int tid = threadIdx.x;
    int lane = tid & 31, w = tid >> 5;
    int Wm = (w & 1) << 6, Wn = (w >> 1) << 5;

    int n0 = blockIdx.x << 7;          // 0..3071
    int m0 = blockIdx.y << 7;
    int mat = n0 >> 10;
    int nb = n0 & 1023;

    const __nv_bfloat16* Ah = g_xhi + (size_t)m0 * Ee;
    const __nv_bfloat16* Al = g_xlo + (size_t)m0 * Ee;
    size_t wbase = (size_t)mat * Hh * Dd * Ee + (size_t)nb * Ee;
    const __nv_bfloat16* Bh = g_wt_hi + wbase;
    const __nv_bfloat16* Bl = g_wt_lo + wbase;

    u32 aoff[4], a7[4], boff[2], b7[2], cA, cB;
    frag_setup(lane, Wm, Wn, aoff, a7, cA, boff, b7, cB);

    float acc[4][4][4] = {};

    // prologue: chunk 0 -> buf 0
    copy_tile_async(sbase + 0 * TILE_B, Ah, tid);
    copy_tile_async(sbase + 1 * TILE_B, Al, tid);
    copy_tile_async(sbase + 2 * TILE_B, Bh, tid);
    copy_tile_async(sbase + 3 * TILE_B, Bl, tid);
    CP_COMMIT();

    for (int c = 0; c < 16; c++) {
        if (c < 15) {
            u32 nb_ = sbase + ((u32)(c + 1) & 1u) * BUF_B;
            int k0 = (c + 1) << 6;
            copy_tile_async(nb_ + 0 * TILE_B, Ah + k0, tid);
            copy_tile_async(nb_ + 1 * TILE_B, Al + k0, tid);
            copy_tile_async(nb_ + 2 * TILE_B, Bh + k0, tid);
            copy_tile_async(nb_ + 3 * TILE_B, Bl + k0, tid);
            CP_COMMIT();
            CP_WAIT1();
        } else {
            CP_WAIT0();
        }
        __syncthreads();
        gemm_chunk(sbase + ((u32)c & 1u) * BUF_B, aoff, a7, cA, boff, b7, cB, acc);
        __syncthreads();
    }

    // epilogue -> g_q/g_k/g_v, layout [(b*H+h)*T+t]*64+d
    float* outp = (mat == 0) ? g_q : (mat == 1) ? g_k : g_v;
#pragma unroll
    for (int mt = 0; mt < 4; mt++) {
#pragma unroll
        for (int nt = 0; nt < 4; nt++) {
            int n = nb + Wn + nt * 8 + ((lane & 3) << 1);
            int h = n >> 6, d = n & 63;
            int m = m0 + Wm + mt * 16 + (lane >> 2);
            int b = m >> 11, t = m & 2047;
            size_t base = (((size_t)b * Hh + h) * Tt + t) * Dd + d;
            *(float2*)&outp[base] = make_float2(acc[mt][nt][0], acc[mt][nt][1]);
            size_t base2 = base + (size_t)8 * Dd;   // m+8, same (b) tile interior
            *(float2*)&outp[base2] = make_float2(acc[mt][nt][2], acc[mt][nt][3]);
        }
    }
}

// ---------------------------------------------------------------------------
// Out projection: out[8192,1024] = A * Wo. grid (8, 64), block 256.
// ---------------------------------------------------------------------------
__global__ void __launch_bounds__(256, 1) out_mma(float* __restrict__ out) {
    extern __shared__ char smraw[];
    u32 sbase = smem_u32(smraw);

    int tid = threadIdx.x;
    int lane = tid & 31, w = tid >> 5;
    int Wm = (w & 1) << 6, Wn = (w >> 1) << 5;

    int n0 = blockIdx.x << 7;
    int m0 = blockIdx.y << 7;

    const __nv_bfloat16* Ah = g_ahi + (size_t)m0 * Ee;
    const __nv_bfloat16* Al = g_alo + (size_t)m0 * Ee;
    const __nv_bfloat16* Bh = g_wot_hi + (size_t)n0 * Ee;
    const __nv_bfloat16* Bl = g_wot_lo + (size_t)n0 * Ee;

    u32 aoff[4], a7[4], boff[2], b7[2], cA, cB;
    frag_setup(lane, Wm, Wn, aoff, a7, cA, boff, b7, cB);

    float acc[4][4][4] = {};

    copy_tile_async(sbase + 0 * TILE_B, Ah, tid);
    copy_tile_async(sbase + 1 * TILE_B, Al, tid);
    copy_tile_async(sbase + 2 * TILE_B, Bh, tid);
    copy_tile_async(sbase + 3 * TILE_B, Bl, tid);
    CP_COMMIT();

    for (int c = 0; c < 16; c++) {
        if (c < 15) {
            u32 nb_ = sbase + ((u32)(c + 1) & 1u) * BUF_B;
            int k0 = (c + 1) << 6;
            copy_tile_async(nb_ + 0 * TILE_B, Ah + k0, tid);
            copy_tile_async(nb_ + 1 * TILE_B, Al + k0, tid);
            copy_tile_async(nb_ + 2 * TILE_B, Bh + k0, tid);
            copy_tile_async(nb_ + 3 * TILE_B, Bl + k0, tid);
            CP_COMMIT();
            CP_WAIT1();
        } else {
            CP_WAIT0();
        }
        __syncthreads();
        gemm_chunk(sbase + ((u32)c & 1u) * BUF_B, aoff, a7, cA, boff, b7, cB, acc);
        __syncthreads();
    }

#pragma unroll
    for (int mt = 0; mt < 4; mt++) {
#pragma unroll
        for (int nt = 0; nt < 4; nt++) {
            int n = n0 + Wn + nt * 8 + ((lane & 3) << 1);
            int m = m0 + Wm + mt * 16 + (lane >> 2);
            *(float2*)&out[(size_t)m * Ee + n] = make_float2(acc[mt][nt][0], acc[mt][nt][1]);
            *(float2*)&out[(size_t)(m + 8) * Ee + n] = make_float2(acc[mt][nt][2], acc[mt][nt][3]);
        }
    }
}

// ---------------------------------------------------------------------------
// Causal flash attention (SIMT FFMA2). Emits bf16 hi/lo for out_mma.
// ---------------------------------------------------------------------------
__global__ void __launch_bounds__(256, 1) attn_kernel()
{
    extern __shared__ float sm[];
    float* q_s = sm;             // [d][m] 64x128 swizzled, pre-scaled
    float* k_s = sm + 8192;      // [d][c] 64x128 swizzled
    float* v_s = sm + 16384;     // [c][d] 128x64 natural
    float* p_s = sm + 24576;     // [m][c] 128x128 swizzled

    int qi = (gridDim.x - 1) - blockIdx.x;
    int bh = blockIdx.y;
    const float* qb = g_q + ((size_t)bh * Tt + ((size_t)qi << 7)) * Dd;
    const float* kb = g_k + (size_t)bh * Tt * Dd;
    const float* vb = g_v + (size_t)bh * Tt * Dd;

    int tid = threadIdx.x;
    int tx = tid & 15, ty = tid >> 4;
    int m0 = ty << 3, n0 = tx << 3, d0 = tx << 2;

    {
        int qr = tid >> 1;
#pragma unroll
        for (int it = 0; it < 8; it++) {
            int d4 = ((tid & 1) << 2) + (it << 3);
            float4 v = *(const float4*)&qb[(size_t)qr * Dd + d4];
            float av[4] = {v.x, v.y, v.z, v.w};
#pragma unroll
            for (int u = 0; u < 4; u++) q_s[swz(d4 + u, qr)] = av[u] * 0.125f;
        }
    }

    ull o2[8][2];
    float m[8], l[8];
#pragma unroll
    for (int i = 0; i < 8; i++) { o2[i][0] = 0ull; o2[i][1] = 0ull; m[i] = -1e30f; l[i] = 0.f; }

    for (int j = 0; j <= qi; j++) {
        const float* kt = kb + ((size_t)j << 7) * Dd;
        const float* vt = vb + ((size_t)j << 7) * Dd;

        __syncthreads();

        {
            int kr = tid >> 1;
#pragma unroll
            for (int it = 0; it < 8; it++) {
                int d4 = ((tid & 1) << 2) + (it << 3);
                float4 v = *(const float4*)&kt[(size_t)kr * Dd + d4];
                float av[4] = {v.x, v.y, v.z, v.w};
#pragma unroll
                for (int u = 0; u < 4; u++) k_s[swz(d4 + u, kr)] = av[u];
            }
        }
#pragma unroll
        for (int it = 0; it < 8; it++) {
            int fi = (it << 8) + tid;
            int vr = fi >> 4, vd = (fi & 15) << 2;
            *(float4*)&v_s[vr * 64 + vd] = *(const float4*)&vt[(size_t)vr * Dd + vd];
        }
        __syncthreads();

        ull s2[8][4];
#pragma unroll
        for (int i = 0; i < 8; i++)
#pragma unroll
            for (int p = 0; p < 4; p++) s2[i][p] = 0ull;

#pragma unroll 8
        for (int e = 0; e < 64; e++) {
            float4 a0 = *(const float4*)&q_s[swz(e, m0)];
            float4 a1 = *(const float4*)&q_s[swz(e, m0 + 4)];
            float4 b0 = *(const float4*)&k_s[swz(e, n0)];
            float4 b1 = *(const float4*)&k_s[swz(e, n0 + 4)];
            ull bp[4] = {pk2(b0.x, b0.y), pk2(b0.z, b0.w),
                         pk2(b1.x, b1.y), pk2(b1.z, b1.w)};
            float aa[8] = {a0.x, a0.y, a0.z, a0.w, a1.x, a1.y, a1.z, a1.w};
#pragma unroll
            for (int i = 0; i < 8; i++) {
                ull ad = pk2(aa[i], aa[i]);
#pragma unroll
                for (int p = 0; p < 4; p++) ffma2(s2[i][p], ad, bp[p]);
            }
        }

        float s[8][8];
#pragma unroll
        for (int i = 0; i < 8; i++)
#pragma unroll
            for (int p = 0; p < 4; p++) upk2(s2[i][p], s[i][2 * p], s[i][2 * p + 1]);

        if (j == qi) {
#pragma unroll
            for (int i = 0; i < 8; i++)
#pragma unroll
                for (int jj = 0; jj < 8; jj++)
                    if (n0 + jj > m0 + i) s[i][jj] = -1e30f;
        }

#pragma unroll
        for (int i = 0; i < 8; i++) {
            float mx = s[i][0];
#pragma unroll
            for (int jj = 1; jj < 8; jj++) mx = fmaxf(mx, s[i][jj]);
            mx = fmaxf(mx, __shfl_xor_sync(0xffffffffu, mx, 8));
            mx = fmaxf(mx, __shfl_xor_sync(0xffffffffu, mx, 4));
            mx = fmaxf(mx, __shfl_xor_sync(0xffffffffu, mx, 2));
            mx = fmaxf(mx, __shfl_xor_sync(0xffffffffu, mx, 1));
            float mn = fmaxf(m[i], mx);
            float sc = fexp(m[i] - mn);
            float rs = 0.f;
#pragma unroll
            for (int jj = 0; jj < 8; jj++) {
                float pv = fexp(s[i][jj] - mn);
                s[i][jj] = pv;
                rs += pv;
            }
            rs += __shfl_xor_sync(0xffffffffu, rs, 8);
            rs += __shfl_xor_sync(0xffffffffu, rs, 4);
            rs += __shfl_xor_sync(0xffffffffu, rs, 2);
            rs += __shfl_xor_sync(0xffffffffu, rs, 1);
            l[i] = l[i] * sc + rs;
            m[i] = mn;
            ull sd = pk2(sc, sc);
            o2[i][0] = fmul2(o2[i][0], sd);
            o2[i][1] = fmul2(o2[i][1], sd);
            *(float4*)&p_s[swz(m0 + i, n0)] = make_float4(s[i][0], s[i][1], s[i][2], s[i][3]);
            *(float4*)&p_s[swz(m0 + i, n0 + 4)] = make_float4(s[i][4], s[i][5], s[i][6], s[i][7]);
        }
        __syncthreads();

#pragma unroll 4
        for (int c4 = 0; c4 < 128; c4 += 4) {
            float pav[8][4];
#pragma unroll
            for (int i = 0; i < 8; i++) {
                float4 pa = *(const float4*)&p_s[swz(m0 + i, c4)];
                pav[i][0] = pa.x; pav[i][1] = pa.y; pav[i][2] = pa.z; pav[i][3] = pa.w;
            }
            float4 vr[4];
#pragma unroll
            for (int cc = 0; cc < 4; cc++)
                vr[cc] = *(const float4*)&v_s[(c4 + cc) * 64 + d0];
#pragma unroll
            for (int cc = 0; cc < 4; cc++) {
                ull vp0 = pk2(vr[cc].x, vr[cc].y);
                ull vp1 = pk2(vr[cc].z, vr[cc].w);
#pragma unroll
                for (int i = 0; i < 8; i++) {
                    ull ad = pk2(pav[i][cc], pav[i][cc]);
                    ffma2(o2[i][0], ad, vp0);
                    ffma2(o2[i][1], ad, vp1);
                }
            }
        }
    }

    // Epilogue: normalize, split to bf16 hi/lo, write [B*T, H*D]
    int b = bh >> 4, h = bh & 15;
#pragma unroll
    for (int i = 0; i < 8; i++) {
        float inv = 1.0f / l[i];
        float v0, v1, v2, v3;
        upk2(o2[i][0], v0, v1);
        upk2(o2[i][1], v2, v3);
        v0 *= inv; v1 *= inv; v2 *= inv; v3 *= inv;
        __nv_bfloat16 h0, h1, h2, h3, l0_, l1_, l2_, l3_;
        split_bf16(v0, h0, l0_); split_bf16(v1, h1, l1_);
        split_bf16(v2, h2, l2_); split_bf16(v3, h3, l3_);
        int t = (qi << 7) + m0 + i;
        size_t base = ((size_t)(b * Tt + t)) * (Hh * Dd) + h * Dd + d0;
        ((__nv_bfloat162*)(g_ahi + base))[0] = __halves2bfloat162(h0, h1);
        ((__nv_bfloat162*)(g_ahi + base))[1] = __halves2bfloat162(h2, h3);
        ((__nv_bfloat162*)(g_alo + base))[0] = __halves2bfloat162(l0_, l1_);
        ((__nv_bfloat162*)(g_alo + base))[1] = __halves2bfloat162(l2_, l3_);
    }
}

// ---------------------------------------------------------------------------
extern "C" void kernel_launch(void* const* d_in, const int* in_sizes, int n_in,
                              void* d_out, int out_size) {
    const float* x  = (const float*)d_in[0];
    const float* Wq = (const float*)d_in[1];
    const float* Wk = (const float*)d_in[2];
    const float* Wv = (const float*)d_in[3];
    const float* Wo = (const float*)d_in[4];
    float* out = (float*)d_out;

    const int ATTN_SMEM = 40960 * sizeof(float);  // 160 KB
    cudaFuncSetAttribute(attn_kernel, cudaFuncAttributeMaxDynamicSharedMemorySize, ATTN_SMEM);
    cudaFuncSetAttribute(qkv_mma, cudaFuncAttributeMaxDynamicSharedMemorySize, GEMM_SMEM);
    cudaFuncSetAttribute(out_mma, cudaFuncAttributeMaxDynamicSharedMemorySize, GEMM_SMEM);

    conv_x<<<8192, 256>>>(x);
    prep_wqkv<<<dim3(2, 32, 48), 256>>>(Wq, Wk, Wv);
    prep_wo<<<dim3(32, 32), 256>>>(Wo);
    qkv_mma<<<dim3(24, 64), 256, GEMM_SMEM>>>();
    attn_kernel<<<dim3(Tt / 128, Bb * Hh), 256, ATTN_SMEM>>>();
    out_mma<<<dim3(8, 64), 256, GEMM_SMEM>>>(out);
}

// round 6
// speedup vs baseline: 3.2331x; 1.5214x over previous
#include <cuda_runtime.h>
#include <cuda_bf16.h>

#define Bb 4
#define Tt 2048
#define Ee 1024
#define Hh 16
#define Dd 64
#define MT (Bb * Tt)   // 8192 rows

typedef unsigned long long ull;
typedef unsigned int u32;

// ---------------- device scratch (allocation-free rule) ----------------
__device__ __align__(16) __nv_bfloat16 g_xhi[(size_t)MT * Ee];
__device__ __align__(16) __nv_bfloat16 g_xlo[(size_t)MT * Ee];
__device__ __align__(16) __nv_bfloat16 g_wt_hi[(size_t)3 * Hh * Dd * Ee];  // [mat][h*64+d][e]
__device__ __align__(16) __nv_bfloat16 g_wt_lo[(size_t)3 * Hh * Dd * Ee];
__device__ __align__(16) __nv_bfloat16 g_wot_hi[(size_t)Ee * Ee];          // [n][e]
__device__ __align__(16) __nv_bfloat16 g_wot_lo[(size_t)Ee * Ee];
__device__ __align__(16) __nv_bfloat16 g_ahi[(size_t)MT * Ee];
__device__ __align__(16) __nv_bfloat16 g_alo[(size_t)MT * Ee];
// q/k/v in bf16 hi/lo, layout [bh][t][d]
__device__ __align__(16) __nv_bfloat16 g_qhi[(size_t)Bb * Hh * Tt * Dd];
__device__ __align__(16) __nv_bfloat16 g_qlo[(size_t)Bb * Hh * Tt * Dd];
__device__ __align__(16) __nv_bfloat16 g_khi[(size_t)Bb * Hh * Tt * Dd];
__device__ __align__(16) __nv_bfloat16 g_klo[(size_t)Bb * Hh * Tt * Dd];
__device__ __align__(16) __nv_bfloat16 g_vhi[(size_t)Bb * Hh * Tt * Dd];
__device__ __align__(16) __nv_bfloat16 g_vlo[(size_t)Bb * Hh * Tt * Dd];

// ---------------- PTX helpers (sm_80/75-safe, no "a" features) ----------------
__device__ __forceinline__ u32 smem_u32(const void* p) {
    u32 a;
    asm("{ .reg .u64 t; cvta.to.shared.u64 t, %1; cvt.u32.u64 %0, t; }"
        : "=r"(a) : "l"(p));
    return a;
}
__device__ __forceinline__ void cpa16(u32 dst, const void* src) {
    asm volatile("cp.async.cg.shared.global [%0], [%1], 16;"
                 :: "r"(dst), "l"(src) : "memory");
}
#define CP_COMMIT() asm volatile("cp.async.commit_group;" ::: "memory")
#define CP_WAIT1()  asm volatile("cp.async.wait_group 1;" ::: "memory")
#define CP_WAIT0()  asm volatile("cp.async.wait_group 0;" ::: "memory")

__device__ __forceinline__ void ldsm4(u32 addr, u32& r0, u32& r1, u32& r2, u32& r3) {
    asm volatile("ldmatrix.sync.aligned.m8n8.x4.shared.b16 {%0,%1,%2,%3}, [%4];"
                 : "=r"(r0), "=r"(r1), "=r"(r2), "=r"(r3) : "r"(addr));
}
__device__ __forceinline__ void ldsm4t(u32 addr, u32& r0, u32& r1, u32& r2, u32& r3) {
    asm volatile("ldmatrix.sync.aligned.m8n8.x4.trans.shared.b16 {%0,%1,%2,%3}, [%4];"
                 : "=r"(r0), "=r"(r1), "=r"(r2), "=r"(r3) : "r"(addr));
}
__device__ __forceinline__ void mma16816(float* d, u32 a0, u32 a1, u32 a2, u32 a3,
                                         u32 b0, u32 b1) {
    asm volatile(
        "mma.sync.aligned.m16n8k16.row.col.f32.bf16.bf16.f32 "
        "{%0,%1,%2,%3},{%4,%5,%6,%7},{%8,%9},{%0,%1,%2,%3};"
        : "+f"(d[0]), "+f"(d[1]), "+f"(d[2]), "+f"(d[3])
        : "r"(a0), "r"(a1), "r"(a2), "r"(a3), "r"(b0), "r"(b1));
}
__device__ __forceinline__ float ex2f(float x) {
    float r; asm("ex2.approx.f32 %0,%1;" : "=f"(r) : "f"(x)); return r;
}
__device__ __forceinline__ void split_bf16(float v, __nv_bfloat16& hi, __nv_bfloat16& lo) {
    hi = __float2bfloat16(v);
    lo = __float2bfloat16(v - __bfloat162float(hi));
}
__device__ __forceinline__ u32 pack_bf2(__nv_bfloat16 a, __nv_bfloat16 b) {
    __nv_bfloat162 t = __halves2bfloat162(a, b);
    return *(u32*)&t;
}

#define L2E 1.4426950408889634f

// ---------------------------------------------------------------------------
// Prep kernels
// ---------------------------------------------------------------------------
__global__ void __launch_bounds__(256) conv_x(const float* __restrict__ x) {
    size_t i = ((size_t)blockIdx.x * 256 + threadIdx.x) * 4;
    float4 v = *(const float4*)&x[i];
    __nv_bfloat16 h0, h1, h2, h3, l0, l1, l2, l3;
    split_bf16(v.x, h0, l0); split_bf16(v.y, h1, l1);
    split_bf16(v.z, h2, l2); split_bf16(v.w, h3, l3);
    ((__nv_bfloat162*)(g_xhi + i))[0] = __halves2bfloat162(h0, h1);
    ((__nv_bfloat162*)(g_xhi + i))[1] = __halves2bfloat162(h2, h3);
    ((__nv_bfloat162*)(g_xlo + i))[0] = __halves2bfloat162(l0, l1);
    ((__nv_bfloat162*)(g_xlo + i))[1] = __halves2bfloat162(l2, l3);
}

__global__ void __launch_bounds__(256) prep_wqkv(
    const float* __restrict__ Wq, const float* __restrict__ Wk,
    const float* __restrict__ Wv)
{
    __shared__ float tile[32][33];
    int z = blockIdx.z;
    int mat = z >> 4, h = z & 15;
    const float* W = (mat == 0 ? Wq : (mat == 1 ? Wk : Wv)) + (size_t)h * Ee * Dd;
    __nv_bfloat16* dhi = g_wt_hi + ((size_t)mat * Hh + h) * Dd * Ee;
    __nv_bfloat16* dlo = g_wt_lo + ((size_t)mat * Hh + h) * Dd * Ee;
    int e0 = blockIdx.y << 5, d0 = blockIdx.x << 5;
    int tx = threadIdx.x & 31, ty = threadIdx.x >> 5;
#pragma unroll
    for (int j = 0; j < 4; j++)
        tile[ty + j * 8][tx] = W[(size_t)(e0 + ty + j * 8) * Dd + d0 + tx];
    __syncthreads();
#pragma unroll
    for (int j = 0; j < 4; j++) {
        int rr = ty + j * 8;
        float v = tile[tx][rr];
        __nv_bfloat16 hi, lo;
        split_bf16(v, hi, lo);
        size_t off = (size_t)(d0 + rr) * Ee + e0 + tx;
        dhi[off] = hi;
        dlo[off] = lo;
    }
}

__global__ void __launch_bounds__(256) prep_wo(const float* __restrict__ Wo) {
    __shared__ float tile[32][33];
    int n0 = blockIdx.x << 5, e0 = blockIdx.y << 5;
    int tx = threadIdx.x & 31, ty = threadIdx.x >> 5;
#pragma unroll
    for (int j = 0; j < 4; j++)
        tile[ty + j * 8][tx] = Wo[(size_t)(e0 + ty + j * 8) * Ee + n0 + tx];
    __syncthreads();
#pragma unroll
    for (int j = 0; j < 4; j++) {
        int rr = ty + j * 8;
        float v = tile[tx][rr];
        __nv_bfloat16 hi, lo;
        split_bf16(v, hi, lo);
        size_t off = (size_t)(n0 + rr) * Ee + e0 + tx;
        g_wot_hi[off] = hi;
        g_wot_lo[off] = lo;
    }
}

// ---------------------------------------------------------------------------
// mma.sync GEMM machinery (as R4, gemm_chunk generalized to 4 bases)
// ---------------------------------------------------------------------------
#define TILE_B   16384u
#define BUF_B    65536u
#define GEMM_SMEM (2u * BUF_B)

// strided copy (row stride Ee elements)
__device__ __forceinline__ void copy_tile_async(u32 tb, const __nv_bfloat16* sp, int tid) {
#pragma unroll
    for (int it = 0; it < 4; it++) {
        int cid = it * 256 + tid;
        int row = cid >> 3, c = cid & 7;
        u32 dst = tb + (u32)(row << 7) + (u32)(((c ^ (row & 7))) << 4);
        cpa16(dst, sp + (size_t)row * Ee + c * 8);
    }
}
// contiguous copy (row stride 64 elements = 128B rows, tile contiguous)
__device__ __forceinline__ void copy_tile_c(u32 tb, const __nv_bfloat16* sp, int tid) {
#pragma unroll
    for (int it = 0; it < 4; it++) {
        int cid = it * 256 + tid;
        int row = cid >> 3, c = cid & 7;
        u32 dst = tb + (u32)(row << 7) + (u32)(((c ^ (row & 7))) << 4);
        cpa16(dst, sp + (size_t)cid * 8);
    }
}

__device__ __forceinline__ void gemm_chunk(
    u32 sAh, u32 sAl, u32 sBh, u32 sBl,
    const u32* aoff, const u32* a7, u32 cA,
    const u32* boff, const u32* b7, u32 cB,
    float acc[4][4][4])
{
#pragma unroll
    for (int s = 0; s < 4; s++) {
        u32 ah[4][4], al[4][4], bh[2][4], bl[2][4];
#pragma unroll
        for (int mt = 0; mt < 4; mt++) {
            u32 ca = (u32)(((2 * s + cA) ^ a7[mt]) << 4);
            ldsm4(sAh + aoff[mt] + ca, ah[mt][0], ah[mt][1], ah[mt][2], ah[mt][3]);
            ldsm4(sAl + aoff[mt] + ca, al[mt][0], al[mt][1], al[mt][2], al[mt][3]);
        }
#pragma unroll
        for (int np = 0; np < 2; np++) {
            u32 cb = (u32)(((2 * s + cB) ^ b7[np]) << 4);
            ldsm4(sBh + boff[np] + cb, bh[np][0], bh[np][1], bh[np][2], bh[np][3]);
            ldsm4(sBl + boff[np] + cb, bl[np][0], bl[np][1], bl[np][2], bl[np][3]);
        }
#pragma unroll
        for (int mt = 0; mt < 4; mt++) {
#pragma unroll
            for (int nt = 0; nt < 4; nt++) {
                int np = nt >> 1, sel = (nt & 1) << 1;
                mma16816(acc[mt][nt], ah[mt][0], ah[mt][1], ah[mt][2], ah[mt][3],
                         bh[np][sel], bh[np][sel + 1]);
                mma16816(acc[mt][nt], ah[mt][0], ah[mt][1], ah[mt][2], ah[mt][3],
                         bl[np][sel], bl[np][sel + 1]);
                mma16816(acc[mt][nt], al[mt][0], al[mt][1], al[mt][2], al[mt][3],
                         bh[np][sel], bh[np][sel + 1]);
            }
        }
    }
}

__device__ __forceinline__ void frag_setup(int lane, int Wm, int Wn,
                                           u32* aoff, u32* a7, u32& cA,
                                           u32* boff, u32* b7, u32& cB) {
#pragma unroll
    for (int mt = 0; mt < 4; mt++) {
        int r = Wm + mt * 16 + (lane & 15);
        aoff[mt] = (u32)(r << 7);
        a7[mt] = (u32)(r & 7);
    }
#pragma unroll
    for (int np = 0; np < 2; np++) {
        int r = Wn + np * 16 + ((lane >> 4) << 3) + (lane & 7);
        boff[np] = (u32)(r << 7);
        b7[np] = (u32)(r & 7);
    }
    cA = (u32)(lane >> 4);
    cB = (u32)((lane >> 3) & 1);
}

// ---------------------------------------------------------------------------
// QKV projection -> bf16 hi/lo q/k/v. grid (24, 64), block 256.
// ---------------------------------------------------------------------------
__global__ void __launch_bounds__(256, 1) qkv_mma() {
    extern __shared__ char smraw[];
    u32 sbase = smem_u32(smraw);

    int tid = threadIdx.x;
    int lane = tid & 31, w = tid >> 5;
    int Wm = (w & 1) << 6, Wn = (w >> 1) << 5;

    int n0 = blockIdx.x << 7;
    int m0 = blockIdx.y << 7;
    int mat = n0 >> 10;
    int nb = n0 & 1023;

    const __nv_bfloat16* Ah = g_xhi + (size_t)m0 * Ee;
    const __nv_bfloat16* Al = g_xlo + (size_t)m0 * Ee;
    size_t wbase = (size_t)mat * Hh * Dd * Ee + (size_t)nb * Ee;
    const __nv_bfloat16* Bh = g_wt_hi + wbase;
    const __nv_bfloat16* Bl = g_wt_lo + wbase;

    u32 aoff[4], a7[4], boff[2], b7[2], cA, cB;
    frag_setup(lane, Wm, Wn, aoff, a7, cA, boff, b7, cB);

    float acc[4][4][4] = {};

    copy_tile_async(sbase + 0 * TILE_B, Ah, tid);
    copy_tile_async(sbase + 1 * TILE_B, Al, tid);
    copy_tile_async(sbase + 2 * TILE_B, Bh, tid);
    copy_tile_async(sbase + 3 * TILE_B, Bl, tid);
    CP_COMMIT();

    for (int c = 0; c < 16; c++) {
        if (c < 15) {
            u32 nb_ = sbase + ((u32)(c + 1) & 1u) * BUF_B;
            int k0 = (c + 1) << 6;
            copy_tile_async(nb_ + 0 * TILE_B, Ah + k0, tid);
            copy_tile_async(nb_ + 1 * TILE_B, Al + k0, tid);
            copy_tile_async(nb_ + 2 * TILE_B, Bh + k0, tid);
            copy_tile_async(nb_ + 3 * TILE_B, Bl + k0, tid);
            CP_COMMIT();
            CP_WAIT1();
        } else {
            CP_WAIT0();
        }
        __syncthreads();
        u32 sb = sbase + ((u32)c & 1u) * BUF_B;
        gemm_chunk(sb, sb + TILE_B, sb + 2 * TILE_B, sb + 3 * TILE_B,
                   aoff, a7, cA, boff, b7, cB, acc);
        __syncthreads();
    }

    // epilogue: split to bf16 hi/lo; layout [bh][t][d]; Q scaled by 1/8.
    __nv_bfloat16* outh = (mat == 0) ? g_qhi : (mat == 1) ? g_khi : g_vhi;
    __nv_bfloat16* outl = (mat == 0) ? g_qlo : (mat == 1) ? g_klo : g_vlo;
    float qsc = (mat == 0) ? 0.125f : 1.0f;
#pragma unroll
    for (int mt = 0; mt < 4; mt++) {
#pragma unroll
        for (int nt = 0; nt < 4; nt++) {
            int n = nb + Wn + nt * 8 + ((lane & 3) << 1);
            int h = n >> 6, d = n & 63;
            int m = m0 + Wm + mt * 16 + (lane >> 2);
            int b = m >> 11, t = m & 2047;
            size_t base = (((size_t)(b * Hh + h)) * Tt + t) * Dd + d;
            __nv_bfloat16 h0, h1, l0, l1;
            split_bf16(acc[mt][nt][0] * qsc, h0, l0);
            split_bf16(acc[mt][nt][1] * qsc, h1, l1);
            *(u32*)(outh + base) = pack_bf2(h0, h1);
            *(u32*)(outl + base) = pack_bf2(l0, l1);
            split_bf16(acc[mt][nt][2] * qsc, h0, l0);
            split_bf16(acc[mt][nt][3] * qsc, h1, l1);
            *(u32*)(outh + base + 8 * Dd) = pack_bf2(h0, h1);
            *(u32*)(outl + base + 8 * Dd) = pack_bf2(l0, l1);
        }
    }
}

// ---------------------------------------------------------------------------
// Out projection: out[8192,1024] = A * Wo. grid (8, 64), block 256.
// ---------------------------------------------------------------------------
__global__ void __launch_bounds__(256, 1) out_mma(float* __restrict__ out) {
    extern __shared__ char smraw[];
    u32 sbase = smem_u32(smraw);

    int tid = threadIdx.x;
    int lane = tid & 31, w = tid >> 5;
    int Wm = (w & 1) << 6, Wn = (w >> 1) << 5;

    int n0 = blockIdx.x << 7;
    int m0 = blockIdx.y << 7;

    const __nv_bfloat16* Ah = g_ahi + (size_t)m0 * Ee;
    const __nv_bfloat16* Al = g_alo + (size_t)m0 * Ee;
    const __nv_bfloat16* Bh = g_wot_hi + (size_t)n0 * Ee;
    const __nv_bfloat16* Bl = g_wot_lo + (size_t)n0 * Ee;

    u32 aoff[4], a7[4], boff[2], b7[2], cA, cB;
    frag_setup(lane, Wm, Wn, aoff, a7, cA, boff, b7, cB);

    float acc[4][4][4] = {};

    copy_tile_async(sbase + 0 * TILE_B, Ah, tid);
    copy_tile_async(sbase + 1 * TILE_B, Al, tid);
    copy_tile_async(sbase + 2 * TILE_B, Bh, tid);
    copy_tile_async(sbase + 3 * TILE_B, Bl, tid);
    CP_COMMIT();

    for (int c = 0; c < 16; c++) {
        if (c < 15) {
            u32 nb_ = sbase + ((u32)(c + 1) & 1u) * BUF_B;
            int k0 = (c + 1) << 6;
            copy_tile_async(nb_ + 0 * TILE_B, Ah + k0, tid);
            copy_tile_async(nb_ + 1 * TILE_B, Al + k0, tid);
            copy_tile_async(nb_ + 2 * TILE_B, Bh + k0, tid);
            copy_tile_async(nb_ + 3 * TILE_B, Bl + k0, tid);
            CP_COMMIT();
            CP_WAIT1();
        } else {
            CP_WAIT0();
        }
        __syncthreads();
        u32 sb = sbase + ((u32)c & 1u) * BUF_B;
        gemm_chunk(sb, sb + TILE_B, sb + 2 * TILE_B, sb + 3 * TILE_B,
                   aoff, a7, cA, boff, b7, cB, acc);
        __syncthreads();
    }

#pragma unroll
    for (int mt = 0; mt < 4; mt++) {
#pragma unroll
        for (int nt = 0; nt < 4; nt++) {
            int n = n0 + Wn + nt * 8 + ((lane & 3) << 1);
            int m = m0 + Wm + mt * 16 + (lane >> 2);
            *(float2*)&out[(size_t)m * Ee + n] = make_float2(acc[mt][nt][0], acc[mt][nt][1]);
            *(float2*)&out[(size_t)(m + 8) * Ee + n] = make_float2(acc[mt][nt][2], acc[mt][nt][3]);
        }
    }
}

// ---------------------------------------------------------------------------
// Tensor-core causal flash attention.
// grid (16 reversed, 64), block 256, ~197.5KB dynamic smem.
// ---------------------------------------------------------------------------
#define AQH 0u
#define AQL 16384u
#define AKH0 32768u
#define AKL0 49152u
#define AKH1 65536u
#define AKL1 81920u
#define AVH 98304u
#define AVL 114688u
#define APH 131072u
#define APL 163840u
#define ASMM 196608u
#define ASML 197120u
#define ASSC 197632u
#define APM  198144u
#define APS  200192u
#define ATTN_SMEM 202240u

__global__ void __launch_bounds__(256, 1) attn_mma() {
    extern __shared__ char smraw[];
    u32 sb = smem_u32(smraw);
    float* smM = (float*)(smraw + ASMM);
    float* smL = (float*)(smraw + ASML);
    float* smSC = (float*)(smraw + ASSC);
    float* smPM = (float*)(smraw + APM);
    float* smPS = (float*)(smraw + APS);

    int tid = threadIdx.x, lane = tid & 31, w = tid >> 5;
    int qi = (int)gridDim.x - 1 - (int)blockIdx.x;
    int bh = blockIdx.y;
    size_t tbase = (size_t)bh * Tt * Dd;
    const __nv_bfloat16* qhp = g_qhi + tbase + ((size_t)qi << 7) * Dd;
    const __nv_bfloat16* qlp = g_qlo + tbase + ((size_t)qi << 7) * Dd;
    const __nv_bfloat16* khp = g_khi + tbase;
    const __nv_bfloat16* klp = g_klo + tbase;
    const __nv_bfloat16* vhp = g_vhi + tbase;
    const __nv_bfloat16* vlp = g_vlo + tbase;

    // S-phase warp tiling (64m x 32n per warp)
    int Wm = (w & 1) << 6, Wn = (w >> 1) << 5;
    u32 aoff[4], a7[4], boff[2], b7[2], cA, cB;
    frag_setup(lane, Wm, Wn, aoff, a7, cA, boff, b7, cB);
    int wn = w >> 1;   // n-group 0..3

    // PV-phase warp tiling (32m x 32d per warp)
    int Wm2 = (w & 3) << 5, Wd = (w >> 2) << 5;
    u32 p_aoff[2], p_a7[2];
#pragma unroll
    for (int mt2 = 0; mt2 < 2; mt2++) {
        int r = Wm2 + mt2 * 16 + (lane & 15);
        p_aoff[mt2] = (u32)(r << 8);   // 256B rows
        p_a7[mt2] = (u32)(r & 7);
    }
    u32 p_cA = (u32)(lane >> 4);
    int vj = lane >> 3;
    int v_rbase = ((vj & 1) << 3) + (lane & 7);
    u32 v_cb = (u32)(Wd >> 3) + (u32)(vj >> 1);

    if (tid < 128) { smM[tid] = -1e30f; smL[tid] = 0.f; }

    // prologue: Q + K(0) in one group
    copy_tile_c(sb + AQH, qhp, tid);
    copy_tile_c(sb + AQL, qlp, tid);
    copy_tile_c(sb + AKH0, khp, tid);
    copy_tile_c(sb + AKL0, klp, tid);
    CP_COMMIT();

    float acc2[2][4][4] = {};

    for (int j = 0; j <= qi; j++) {
        int kb = j & 1;
        CP_WAIT0();                 // K(j) (and Q on j=0) complete
        __syncthreads();            // K/V buffers safe to (re)use

        // issue V(j) (overlaps S mma + softmax)
        copy_tile_c(sb + AVH, vhp + ((size_t)j << 7) * Dd, tid);
        copy_tile_c(sb + AVL, vlp + ((size_t)j << 7) * Dd, tid);
        CP_COMMIT();

        // ---- S = Q . K^T (3-pass split-bf16)
        float sacc[4][4][4] = {};
        u32 khB = sb + (kb ? AKH1 : AKH0);
        u32 klB = sb + (kb ? AKL1 : AKL0);
        gemm_chunk(sb + AQH, sb + AQL, khB, klB,
                   aoff, a7, cA, boff, b7, cB, sacc);

        // prefetch K(j+1)
        if (j < qi) {
            copy_tile_c(sb + (kb ? AKH0 : AKH1), khp + ((size_t)(j + 1) << 7) * Dd, tid);
            copy_tile_c(sb + (kb ? AKL0 : AKL1), klp + ((size_t)(j + 1) << 7) * Dd, tid);
            CP_COMMIT();
        }

        // ---- causal mask on diagonal tile
        if (j == qi) {
#pragma unroll
            for (int mt = 0; mt < 4; mt++)
#pragma unroll
                for (int nt = 0; nt < 4; nt++)
#pragma unroll
                    for (int rg = 0; rg < 4; rg++) {
                        int r = Wm + mt * 16 + (lane >> 2) + ((rg >> 1) << 3);
                        int c = Wn + nt * 8 + ((lane & 3) << 1) + (rg & 1);
                        if (c > r) sacc[mt][nt][rg] = -1e30f;
                    }
        }

        // ---- softmax step 1: per-warp partial row max
#pragma unroll
        for (int mt = 0; mt < 4; mt++) {
#pragma unroll
            for (int rh = 0; rh < 2; rh++) {
                float mx = sacc[mt][0][rh * 2];
#pragma unroll
                for (int nt = 0; nt < 4; nt++) {
                    mx = fmaxf(mx, sacc[mt][nt][rh * 2]);
                    mx = fmaxf(mx, sacc[mt][nt][rh * 2 + 1]);
                }
                mx = fmaxf(mx, __shfl_xor_sync(0xffffffffu, mx, 1));
                mx = fmaxf(mx, __shfl_xor_sync(0xffffffffu, mx, 2));
                if ((lane & 3) == 0)
                    smPM[wn * 128 + Wm + mt * 16 + (lane >> 2) + rh * 8] = mx;
            }
        }
        __syncthreads();

        // ---- step 2: row max/scale update (warps 0-3)
        if (tid < 128) {
            float old = smM[tid];
            float mn = fmaxf(fmaxf(smPM[tid], smPM[128 + tid]),
                             fmaxf(smPM[256 + tid], smPM[384 + tid]));
            mn = fmaxf(mn, old);
            smSC[tid] = ex2f((old - mn) * L2E);
            smM[tid] = mn;
        }
        __syncthreads();

        // ---- step 3: exp, P hi/lo store, partial row sums
#pragma unroll
        for (int mt = 0; mt < 4; mt++) {
#pragma unroll
            for (int rh = 0; rh < 2; rh++) {
                int r = Wm + mt * 16 + (lane >> 2) + rh * 8;
                float mnl = smM[r] * L2E;
                float rowsum = 0.f;
#pragma unroll
                for (int nt = 0; nt < 4; nt++) {
                    float p0 = ex2f(fmaf(sacc[mt][nt][rh * 2], L2E, -mnl));
                    float p1 = ex2f(fmaf(sacc[mt][nt][rh * 2 + 1], L2E, -mnl));
                    rowsum += p0 + p1;
                    __nv_bfloat16 h0, l0, h1, l1;
                    split_bf16(p0, h0, l0);
                    split_bf16(p1, h1, l1);
                    u32 ch = ((u32)((Wn >> 3) + nt) ^ (u32)(r & 7)) << 4;
                    u32 off = (u32)(r << 8) + ch + ((u32)(lane & 3) << 2);
                    *(u32*)(smraw + APH + off) = pack_bf2(h0, h1);
                    *(u32*)(smraw + APL + off) = pack_bf2(l0, l1);
                }
                rowsum += __shfl_xor_sync(0xffffffffu, rowsum, 1);
                rowsum += __shfl_xor_sync(0xffffffffu, rowsum, 2);
                if ((lane & 3) == 0) smPS[wn * 128 + r] = rowsum;
            }
        }
        if (j < qi) { CP_WAIT1(); } else { CP_WAIT0(); }  // V(j) done
        __syncthreads();

        // ---- step 4: l update (warps 0-3); others proceed to PV safely
        if (tid < 128) {
            smL[tid] = smL[tid] * smSC[tid] +
                       (smPS[tid] + smPS[128 + tid] + smPS[256 + tid] + smPS[384 + tid]);
        }

        // ---- rescale O
#pragma unroll
        for (int mt2 = 0; mt2 < 2; mt2++) {
            float sc0 = smSC[Wm2 + mt2 * 16 + (lane >> 2)];
            float sc1 = smSC[Wm2 + mt2 * 16 + (lane >> 2) + 8];
#pragma unroll
            for (int nt = 0; nt < 4; nt++) {
                acc2[mt2][nt][0] *= sc0;
                acc2[mt2][nt][1] *= sc0;
                acc2[mt2][nt][2] *= sc1;
                acc2[mt2][nt][3] *= sc1;
            }
        }

        // ---- O += P . V (3-pass split-bf16, V via ldmatrix.trans)
#pragma unroll
        for (int s = 0; s < 8; s++) {
            u32 ph_[2][4], pl_[2][4];
#pragma unroll
            for (int mt2 = 0; mt2 < 2; mt2++) {
                u32 ch = (((2 * (u32)s + p_cA) ^ p_a7[mt2]) << 4);
                ldsm4(sb + APH + p_aoff[mt2] + ch,
                      ph_[mt2][0], ph_[mt2][1], ph_[mt2][2], ph_[mt2][3]);
                ldsm4(sb + APL + p_aoff[mt2] + ch,
                      pl_[mt2][0], pl_[mt2][1], pl_[mt2][2], pl_[mt2][3]);
            }
            int vrow = (s << 4) + v_rbase;
            u32 vro = (u32)(vrow << 7);
            u32 v7 = (u32)(vrow & 7);
            u32 vh_[2][4], vl_[2][4];
#pragma unroll
            for (int g = 0; g < 2; g++) {
                u32 ch = (((v_cb + 2u * g) ^ v7) << 4);
                ldsm4t(sb + AVH + vro + ch, vh_[g][0], vh_[g][1], vh_[g][2], vh_[g][3]);
                ldsm4t(sb + AVL + vro + ch, vl_[g][0], vl_[g][1], vl_[g][2], vl_[g][3]);
            }
#pragma unroll
            for (int mt2 = 0; mt2 < 2; mt2++) {
#pragma unroll
                for (int nt = 0; nt < 4; nt++) {
                    int g = nt >> 1, su = (nt & 1) << 1;
                    mma16816(acc2[mt2][nt], ph_[mt2][0], ph_[mt2][1], ph_[mt2][2], ph_[mt2][3],
                             vh_[g][su], vh_[g][su + 1]);
                    mma16816(acc2[mt2][nt], ph_[mt2][0], ph_[mt2][1], ph_[mt2][2], ph_[mt2][3],
                             vl_[g][su], vl_[g][su + 1]);
                    mma16816(acc2[mt2][nt], pl_[mt2][0], pl_[mt2][1], pl_[mt2][2], pl_[mt2][3],
                             vh_[g][su], vh_[g][su + 1]);
                }
            }
        }
    }

    // ---- epilogue: normalize, split bf16 hi/lo, write [B*T, H*D]
    __syncthreads();
    int b = bh >> 4, h = bh & 15;
#pragma unroll
    for (int mt2 = 0; mt2 < 2; mt2++) {
#pragma unroll
        for (int rh = 0; rh < 2; rh++) {
            int r = Wm2 + mt2 * 16 + (lane >> 2) + rh * 8;
            float inv = 1.0f / smL[r];
            int t = (qi << 7) + r;
            size_t rowbase = ((size_t)(b * Tt + t)) * (Hh * Dd) + h * Dd;
#pragma unroll
            for (int nt = 0; nt < 4; nt++) {
                int d = Wd + nt * 8 + ((lane & 3) << 1);
                float v0 = acc2[mt2][nt][rh * 2] * inv;
                float v1 = acc2[mt2][nt][rh * 2 + 1] * inv;
                __nv_bfloat16 h0, l0, h1, l1;
                split_bf16(v0, h0, l0);
                split_bf16(v1, h1, l1);
                *(u32*)(g_ahi + rowbase + d) = pack_bf2(h0, h1);
                *(u32*)(g_alo + rowbase + d) = pack_bf2(l0, l1);
            }
        }
    }
}

// ---------------------------------------------------------------------------
extern "C" void kernel_launch(void* const* d_in, const int* in_sizes, int n_in,
                              void* d_out, int out_size) {
    const float* x  = (const float*)d_in[0];
    const float* Wq = (const float*)d_in[1];
    const float* Wk = (const float*)d_in[2];
    const float* Wv = (const float*)d_in[3];
    const float* Wo = (const float*)d_in[4];
    float* out = (float*)d_out;

    cudaFuncSetAttribute(qkv_mma, cudaFuncAttributeMaxDynamicSharedMemorySize, GEMM_SMEM);
    cudaFuncSetAttribute(out_mma, cudaFuncAttributeMaxDynamicSharedMemorySize, GEMM_SMEM);
    cudaFuncSetAttribute(attn_mma, cudaFuncAttributeMaxDynamicSharedMemorySize, ATTN_SMEM);

    conv_x<<<8192, 256>>>(x);
    prep_wqkv<<<dim3(2, 32, 48), 256>>>(Wq, Wk, Wv);
    prep_wo<<<dim3(32, 32), 256>>>(Wo);
    qkv_mma<<<dim3(24, 64), 256, GEMM_SMEM>>>();
    attn_mma<<<dim3(Tt / 128, Bb * Hh), 256, ATTN_SMEM>>>();
    out_mma<<<dim3(8, 64), 256, GEMM_SMEM>>>(out);
}

// round 7
// speedup vs baseline: 3.7619x; 1.1636x over previous
#include <cuda_runtime.h>
#include <cuda_fp16.h>

#define Bb 4
#define Tt 2048
#define Ee 1024
#define Hh 16
#define Dd 64
#define MT (Bb * Tt)   // 8192 rows

typedef unsigned long long ull;
typedef unsigned int u32;

// ---------------- device scratch (allocation-free rule) ----------------
__device__ __align__(16) __half g_xhi[(size_t)MT * Ee];
__device__ __align__(16) __half g_xlo[(size_t)MT * Ee];
__device__ __align__(16) __half g_wt_hi[(size_t)3 * Hh * Dd * Ee];  // [mat][h*64+d][e], Wq pre-scaled 1/8
__device__ __align__(16) __half g_wt_lo[(size_t)3 * Hh * Dd * Ee];
__device__ __align__(16) __half g_wot_hi[(size_t)Ee * Ee];          // [n][e]
__device__ __align__(16) __half g_wot_lo[(size_t)Ee * Ee];
__device__ __align__(16) __half g_a[(size_t)MT * Ee];               // attn out, single fp16
// q/k/v fp16 hi/lo, layout [bh][t][d]
__device__ __align__(16) __half g_qhi[(size_t)Bb * Hh * Tt * Dd];
__device__ __align__(16) __half g_qlo[(size_t)Bb * Hh * Tt * Dd];
__device__ __align__(16) __half g_khi[(size_t)Bb * Hh * Tt * Dd];
__device__ __align__(16) __half g_klo[(size_t)Bb * Hh * Tt * Dd];
__device__ __align__(16) __half g_vhi[(size_t)Bb * Hh * Tt * Dd];
__device__ __align__(16) __half g_vlo[(size_t)Bb * Hh * Tt * Dd];

// ---------------- PTX helpers ----------------
__device__ __forceinline__ u32 smem_u32(const void* p) {
    u32 a;
    asm("{ .reg .u64 t; cvta.to.shared.u64 t, %1; cvt.u32.u64 %0, t; }"
        : "=r"(a) : "l"(p));
    return a;
}
__device__ __forceinline__ void cpa16(u32 dst, const void* src) {
    asm volatile("cp.async.cg.shared.global [%0], [%1], 16;"
                 :: "r"(dst), "l"(src) : "memory");
}
#define CP_COMMIT() asm volatile("cp.async.commit_group;" ::: "memory")
#define CP_WAIT1()  asm volatile("cp.async.wait_group 1;" ::: "memory")
#define CP_WAIT0()  asm volatile("cp.async.wait_group 0;" ::: "memory")

__device__ __forceinline__ void ldsm4(u32 addr, u32& r0, u32& r1, u32& r2, u32& r3) {
    asm volatile("ldmatrix.sync.aligned.m8n8.x4.shared.b16 {%0,%1,%2,%3}, [%4];"
                 : "=r"(r0), "=r"(r1), "=r"(r2), "=r"(r3) : "r"(addr));
}
__device__ __forceinline__ void ldsm4t(u32 addr, u32& r0, u32& r1, u32& r2, u32& r3) {
    asm volatile("ldmatrix.sync.aligned.m8n8.x4.trans.shared.b16 {%0,%1,%2,%3}, [%4];"
                 : "=r"(r0), "=r"(r1), "=r"(r2), "=r"(r3) : "r"(addr));
}
__device__ __forceinline__ void mma16816(float* d, u32 a0, u32 a1, u32 a2, u32 a3,
                                         u32 b0, u32 b1) {
    asm volatile(
        "mma.sync.aligned.m16n8k16.row.col.f32.f16.f16.f32 "
        "{%0,%1,%2,%3},{%4,%5,%6,%7},{%8,%9},{%0,%1,%2,%3};"
        : "+f"(d[0]), "+f"(d[1]), "+f"(d[2]), "+f"(d[3])
        : "r"(a0), "r"(a1), "r"(a2), "r"(a3), "r"(b0), "r"(b1));
}
__device__ __forceinline__ float ex2f(float x) {
    float r; asm("ex2.approx.f32 %0,%1;" : "=f"(r) : "f"(x)); return r;
}
__device__ __forceinline__ void split_f16(float v, __half& hi, __half& lo) {
    hi = __float2half_rn(v);
    lo = __float2half_rn(v - __half2float(hi));
}
__device__ __forceinline__ u32 pack_f16(__half a, __half b) {
    __half2 t = __halves2half2(a, b);
    return *(u32*)&t;
}

#define L2E 1.4426950408889634f

// ---------------------------------------------------------------------------
// Prep kernels
// ---------------------------------------------------------------------------
__global__ void __launch_bounds__(256) conv_x(const float* __restrict__ x) {
    size_t i = ((size_t)blockIdx.x * 256 + threadIdx.x) * 4;
    float4 v = *(const float4*)&x[i];
    __half h0, h1, h2, h3, l0, l1, l2, l3;
    split_f16(v.x, h0, l0); split_f16(v.y, h1, l1);
    split_f16(v.z, h2, l2); split_f16(v.w, h3, l3);
    *(u32*)(g_xhi + i) = pack_f16(h0, h1);
    *(u32*)(g_xhi + i + 2) = pack_f16(h2, h3);
    *(u32*)(g_xlo + i) = pack_f16(l0, l1);
    *(u32*)(g_xlo + i + 2) = pack_f16(l2, l3);
}

__global__ void __launch_bounds__(256) prep_wqkv(
    const float* __restrict__ Wq, const float* __restrict__ Wk,
    const float* __restrict__ Wv)
{
    __shared__ float tile[32][33];
    int z = blockIdx.z;
    int mat = z >> 4, h = z & 15;
    const float* W = (mat == 0 ? Wq : (mat == 1 ? Wk : Wv)) + (size_t)h * Ee * Dd;
    float scale = (mat == 0) ? 0.125f : 1.0f;   // fold D^-1/2 into Wq
    __half* dhi = g_wt_hi + ((size_t)mat * Hh + h) * Dd * Ee;
    __half* dlo = g_wt_lo + ((size_t)mat * Hh + h) * Dd * Ee;
    int e0 = blockIdx.y << 5, d0 = blockIdx.x << 5;
    int tx = threadIdx.x & 31, ty = threadIdx.x >> 5;
#pragma unroll
    for (int j = 0; j < 4; j++)
        tile[ty + j * 8][tx] = W[(size_t)(e0 + ty + j * 8) * Dd + d0 + tx];
    __syncthreads();
#pragma unroll
    for (int j = 0; j < 4; j++) {
        int rr = ty + j * 8;
        float v = tile[tx][rr] * scale;
        __half hi, lo;
        split_f16(v, hi, lo);
        size_t off = (size_t)(d0 + rr) * Ee + e0 + tx;
        dhi[off] = hi;
        dlo[off] = lo;
    }
}

__global__ void __launch_bounds__(256) prep_wo(const float* __restrict__ Wo) {
    __shared__ float tile[32][33];
    int n0 = blockIdx.x << 5, e0 = blockIdx.y << 5;
    int tx = threadIdx.x & 31, ty = threadIdx.x >> 5;
#pragma unroll
    for (int j = 0; j < 4; j++)
        tile[ty + j * 8][tx] = Wo[(size_t)(e0 + ty + j * 8) * Ee + n0 + tx];
    __syncthreads();
#pragma unroll
    for (int j = 0; j < 4; j++) {
        int rr = ty + j * 8;
        float v = tile[tx][rr];
        __half hi, lo;
        split_f16(v, hi, lo);
        size_t off = (size_t)(n0 + rr) * Ee + e0 + tx;
        g_wot_hi[off] = hi;
        g_wot_lo[off] = lo;
    }
}

// ---------------------------------------------------------------------------
// mma.sync GEMM machinery
// ---------------------------------------------------------------------------
#define TILE_B   16384u
#define QKV_BUF  65536u
#define QKV_SMEM (2u * QKV_BUF)
#define OUT_BUF  49152u
#define OUT_SMEM (2u * OUT_BUF)

__device__ __forceinline__ void copy_tile_async(u32 tb, const __half* sp, int tid) {
#pragma unroll
    for (int it = 0; it < 4; it++) {
        int cid = it * 256 + tid;
        int row = cid >> 3, c = cid & 7;
        u32 dst = tb + (u32)(row << 7) + (u32)(((c ^ (row & 7))) << 4);
        cpa16(dst, sp + (size_t)row * Ee + c * 8);
    }
}
__device__ __forceinline__ void copy_tile_c(u32 tb, const __half* sp, int tid) {
#pragma unroll
    for (int it = 0; it < 4; it++) {
        int cid = it * 256 + tid;
        int row = cid >> 3, c = cid & 7;
        u32 dst = tb + (u32)(row << 7) + (u32)(((c ^ (row & 7))) << 4);
        cpa16(dst, sp + (size_t)cid * 8);
    }
}

__device__ __forceinline__ void frag_setup(int lane, int Wm, int Wn,
                                           u32* aoff, u32* a7, u32& cA,
                                           u32* boff, u32* b7, u32& cB) {
#pragma unroll
    for (int mt = 0; mt < 4; mt++) {
        int r = Wm + mt * 16 + (lane & 15);
        aoff[mt] = (u32)(r << 7);
        a7[mt] = (u32)(r & 7);
    }
#pragma unroll
    for (int np = 0; np < 2; np++) {
        int r = Wn + np * 16 + ((lane >> 4) << 3) + (lane & 7);
        boff[np] = (u32)(r << 7);
        b7[np] = (u32)(r & 7);
    }
    cA = (u32)(lane >> 4);
    cB = (u32)((lane >> 3) & 1);
}

// 3-pass chunk, no frag prefetch (used by attention S)
__device__ __forceinline__ void gemm_chunk(
    u32 sAh, u32 sAl, u32 sBh, u32 sBl,
    const u32* aoff, const u32* a7, u32 cA,
    const u32* boff, const u32* b7, u32 cB,
    float acc[4][4][4])
{
#pragma unroll
    for (int s = 0; s < 4; s++) {
        u32 ah[4][4], al[4][4], bh[2][4], bl[2][4];
#pragma unroll
        for (int mt = 0; mt < 4; mt++) {
            u32 ca = (u32)(((2 * s + cA) ^ a7[mt]) << 4);
            ldsm4(sAh + aoff[mt] + ca, ah[mt][0], ah[mt][1], ah[mt][2], ah[mt][3]);
            ldsm4(sAl + aoff[mt] + ca, al[mt][0], al[mt][1], al[mt][2], al[mt][3]);
        }
#pragma unroll
        for (int np = 0; np < 2; np++) {
            u32 cb = (u32)(((2 * s + cB) ^ b7[np]) << 4);
            ldsm4(sBh + boff[np] + cb, bh[np][0], bh[np][1], bh[np][2], bh[np][3]);
            ldsm4(sBl + boff[np] + cb, bl[np][0], bl[np][1], bl[np][2], bl[np][3]);
        }
#pragma unroll
        for (int mt = 0; mt < 4; mt++) {
#pragma unroll
            for (int nt = 0; nt < 4; nt++) {
                int np = nt >> 1, sel = (nt & 1) << 1;
                mma16816(acc[mt][nt], ah[mt][0], ah[mt][1], ah[mt][2], ah[mt][3],
                         bh[np][sel], bh[np][sel + 1]);
                mma16816(acc[mt][nt], ah[mt][0], ah[mt][1], ah[mt][2], ah[mt][3],
                         bl[np][sel], bl[np][sel + 1]);
                mma16816(acc[mt][nt], al[mt][0], al[mt][1], al[mt][2], al[mt][3],
                         bh[np][sel], bh[np][sel + 1]);
            }
        }
    }
}

// 3-pass chunk with fragment double-buffering (qkv)
__device__ __forceinline__ void gemm_chunk_pf(
    u32 sAh, u32 sAl, u32 sBh, u32 sBl,
    const u32* aoff, const u32* a7, u32 cA,
    const u32* boff, const u32* b7, u32 cB,
    float acc[4][4][4])
{
    u32 ah[2][4][4], al[2][4][4], bh[2][2][4], bl[2][2][4];
#define LDFR(dst, s)                                                          \
    {                                                                         \
        _Pragma("unroll")                                                     \
        for (int mt = 0; mt < 4; mt++) {                                      \
            u32 ca = (u32)(((2 * (s) + cA) ^ a7[mt]) << 4);                   \
            ldsm4(sAh + aoff[mt] + ca, ah[dst][mt][0], ah[dst][mt][1],        \
                  ah[dst][mt][2], ah[dst][mt][3]);                            \
            ldsm4(sAl + aoff[mt] + ca, al[dst][mt][0], al[dst][mt][1],        \
                  al[dst][mt][2], al[dst][mt][3]);                            \
        }                                                                     \
        _Pragma("unroll")                                                     \
        for (int np = 0; np < 2; np++) {                                      \
            u32 cb = (u32)(((2 * (s) + cB) ^ b7[np]) << 4);                   \
            ldsm4(sBh + boff[np] + cb, bh[dst][np][0], bh[dst][np][1],        \
                  bh[dst][np][2], bh[dst][np][3]);                            \
            ldsm4(sBl + boff[np] + cb, bl[dst][np][0], bl[dst][np][1],        \
                  bl[dst][np][2], bl[dst][np][3]);                            \
        }                                                                     \
    }
    LDFR(0, 0)
#pragma unroll
    for (int s = 0; s < 4; s++) {
        int cur = s & 1;
        if (s < 3) LDFR((s + 1) & 1, s + 1)
#pragma unroll
        for (int mt = 0; mt < 4; mt++) {
#pragma unroll
            for (int nt = 0; nt < 4; nt++) {
                int np = nt >> 1, sel = (nt & 1) << 1;
                mma16816(acc[mt][nt], ah[cur][mt][0], ah[cur][mt][1],
                         ah[cur][mt][2], ah[cur][mt][3],
                         bh[cur][np][sel], bh[cur][np][sel + 1]);
                mma16816(acc[mt][nt], ah[cur][mt][0], ah[cur][mt][1],
                         ah[cur][mt][2], ah[cur][mt][3],
                         bl[cur][np][sel], bl[cur][np][sel + 1]);
                mma16816(acc[mt][nt], al[cur][mt][0], al[cur][mt][1],
                         al[cur][mt][2], al[cur][mt][3],
                         bh[cur][np][sel], bh[cur][np][sel + 1]);
            }
        }
    }
#undef LDFR
}

// 2-pass chunk: single A, split B (out projection)
__device__ __forceinline__ void gemm_chunk2(
    u32 sA, u32 sBh, u32 sBl,
    const u32* aoff, const u32* a7, u32 cA,
    const u32* boff, const u32* b7, u32 cB,
    float acc[4][4][4])
{
#pragma unroll
    for (int s = 0; s < 4; s++) {
        u32 a_[4][4], bh[2][4], bl[2][4];
#pragma unroll
        for (int mt = 0; mt < 4; mt++) {
            u32 ca = (u32)(((2 * s + cA) ^ a7[mt]) << 4);
            ldsm4(sA + aoff[mt] + ca, a_[mt][0], a_[mt][1], a_[mt][2], a_[mt][3]);
        }
#pragma unroll
        for (int np = 0; np < 2; np++) {
            u32 cb = (u32)(((2 * s + cB) ^ b7[np]) << 4);
            ldsm4(sBh + boff[np] + cb, bh[np][0], bh[np][1], bh[np][2], bh[np][3]);
            ldsm4(sBl + boff[np] + cb, bl[np][0], bl[np][1], bl[np][2], bl[np][3]);
        }
#pragma unroll
        for (int mt = 0; mt < 4; mt++) {
#pragma unroll
            for (int nt = 0; nt < 4; nt++) {
                int np = nt >> 1, sel = (nt & 1) << 1;
                mma16816(acc[mt][nt], a_[mt][0], a_[mt][1], a_[mt][2], a_[mt][3],
                         bh[np][sel], bh[np][sel + 1]);
                mma16816(acc[mt][nt], a_[mt][0], a_[mt][1], a_[mt][2], a_[mt][3],
                         bl[np][sel], bl[np][sel + 1]);
            }
        }
    }
}

// ---------------------------------------------------------------------------
// QKV projection -> fp16 hi/lo q/k/v. grid (24, 64), block 256.
// ---------------------------------------------------------------------------
__global__ void __launch_bounds__(256, 1) qkv_mma() {
    extern __shared__ char smraw[];
    u32 sbase = smem_u32(smraw);

    int tid = threadIdx.x;
    int lane = tid & 31, w = tid >> 5;
    int Wm = (w & 1) << 6, Wn = (w >> 1) << 5;

    int n0 = blockIdx.x << 7;
    int m0 = blockIdx.y << 7;
    int mat = n0 >> 10;
    int nb = n0 & 1023;

    const __half* Ah = g_xhi + (size_t)m0 * Ee;
    const __half* Al = g_xlo + (size_t)m0 * Ee;
    size_t wbase = (size_t)mat * Hh * Dd * Ee + (size_t)nb * Ee;
    const __half* Bh = g_wt_hi + wbase;
    const __half* Bl = g_wt_lo + wbase;

    u32 aoff[4], a7[4], boff[2], b7[2], cA, cB;
    frag_setup(lane, Wm, Wn, aoff, a7, cA, boff, b7, cB);

    float acc[4][4][4] = {};

    copy_tile_async(sbase + 0 * TILE_B, Ah, tid);
    copy_tile_async(sbase + 1 * TILE_B, Al, tid);
    copy_tile_async(sbase + 2 * TILE_B, Bh, tid);
    copy_tile_async(sbase + 3 * TILE_B, Bl, tid);
    CP_COMMIT();

    for (int c = 0; c < 16; c++) {
        CP_WAIT0();
        __syncthreads();
        if (c < 15) {
            u32 nb_ = sbase + ((u32)(c + 1) & 1u) * QKV_BUF;
            int k0 = (c + 1) << 6;
            copy_tile_async(nb_ + 0 * TILE_B, Ah + k0, tid);
            copy_tile_async(nb_ + 1 * TILE_B, Al + k0, tid);
            copy_tile_async(nb_ + 2 * TILE_B, Bh + k0, tid);
            copy_tile_async(nb_ + 3 * TILE_B, Bl + k0, tid);
            CP_COMMIT();
        }
        u32 sb = sbase + ((u32)c & 1u) * QKV_BUF;
        gemm_chunk_pf(sb, sb + TILE_B, sb + 2 * TILE_B, sb + 3 * TILE_B,
                      aoff, a7, cA, boff, b7, cB, acc);
    }

    __half* outh = (mat == 0) ? g_qhi : (mat == 1) ? g_khi : g_vhi;
    __half* outl = (mat == 0) ? g_qlo : (mat == 1) ? g_klo : g_vlo;
#pragma unroll
    for (int mt = 0; mt < 4; mt++) {
#pragma unroll
        for (int nt = 0; nt < 4; nt++) {
            int n = nb + Wn + nt * 8 + ((lane & 3) << 1);
            int h = n >> 6, d = n & 63;
            int m = m0 + Wm + mt * 16 + (lane >> 2);
            int b = m >> 11, t = m & 2047;
            size_t base = (((size_t)(b * Hh + h)) * Tt + t) * Dd + d;
            __half h0, h1, l0, l1;
            split_f16(acc[mt][nt][0], h0, l0);
            split_f16(acc[mt][nt][1], h1, l1);
            *(u32*)(outh + base) = pack_f16(h0, h1);
            *(u32*)(outl + base) = pack_f16(l0, l1);
            split_f16(acc[mt][nt][2], h0, l0);
            split_f16(acc[mt][nt][3], h1, l1);
            *(u32*)(outh + base + 8 * Dd) = pack_f16(h0, h1);
            *(u32*)(outl + base + 8 * Dd) = pack_f16(l0, l1);
        }
    }
}

// ---------------------------------------------------------------------------
// Out projection (2-pass): out[8192,1024] = A_f16 * Wo. grid (8, 64), block 256.
// ---------------------------------------------------------------------------
__global__ void __launch_bounds__(256, 1) out_mma(float* __restrict__ out) {
    extern __shared__ char smraw[];
    u32 sbase = smem_u32(smraw);

    int tid = threadIdx.x;
    int lane = tid & 31, w = tid >> 5;
    int Wm = (w & 1) << 6, Wn = (w >> 1) << 5;

    int n0 = blockIdx.x << 7;
    int m0 = blockIdx.y << 7;

    const __half* A = g_a + (size_t)m0 * Ee;
    const __half* Bh = g_wot_hi + (size_t)n0 * Ee;
    const __half* Bl = g_wot_lo + (size_t)n0 * Ee;

    u32 aoff[4], a7[4], boff[2], b7[2], cA, cB;
    frag_setup(lane, Wm, Wn, aoff, a7, cA, boff, b7, cB);

    float acc[4][4][4] = {};

    copy_tile_async(sbase + 0 * TILE_B, A, tid);
    copy_tile_async(sbase + 1 * TILE_B, Bh, tid);
    copy_tile_async(sbase + 2 * TILE_B, Bl, tid);
    CP_COMMIT();

    for (int c = 0; c < 16; c++) {
        CP_WAIT0();
        __syncthreads();
        if (c < 15) {
            u32 nb_ = sbase + ((u32)(c + 1) & 1u) * OUT_BUF;
            int k0 = (c + 1) << 6;
            copy_tile_async(nb_ + 0 * TILE_B, A + k0, tid);
            copy_tile_async(nb_ + 1 * TILE_B, Bh + k0, tid);
            copy_tile_async(nb_ + 2 * TILE_B, Bl + k0, tid);
            CP_COMMIT();
        }
        u32 sb = sbase + ((u32)c & 1u) * OUT_BUF;
        gemm_chunk2(sb, sb + TILE_B, sb + 2 * TILE_B,
                    aoff, a7, cA, boff, b7, cB, acc);
    }

#pragma unroll
    for (int mt = 0; mt < 4; mt++) {
#pragma unroll
        for (int nt = 0; nt < 4; nt++) {
            int n = n0 + Wn + nt * 8 + ((lane & 3) << 1);
            int m = m0 + Wm + mt * 16 + (lane >> 2);
            *(float2*)&out[(size_t)m * Ee + n] = make_float2(acc[mt][nt][0], acc[mt][nt][1]);
            *(float2*)&out[(size_t)(m + 8) * Ee + n] = make_float2(acc[mt][nt][2], acc[mt][nt][3]);
        }
    }
}

// ---------------------------------------------------------------------------
// Tensor-core causal flash attention. S: 3-pass; PV: P single fp16 + V hi/lo (2-pass).
// grid (16 reversed, 64), block 256, ~165.5KB dynamic smem.
// ---------------------------------------------------------------------------
#define AQH 0u
#define AQL 16384u
#define AKH0 32768u
#define AKL0 49152u
#define AKH1 65536u
#define AKL1 81920u
#define AVH 98304u
#define AVL 114688u
#define APH 131072u
#define ASMM 163840u
#define ASML 164352u
#define ASSC 164864u
#define APM  165376u
#define APS  167424u
#define ATTN_SMEM 169472u

__global__ void __launch_bounds__(256, 1) attn_mma() {
    extern __shared__ char smraw[];
    u32 sb = smem_u32(smraw);
    float* smM = (float*)(smraw + ASMM);
    float* smL = (float*)(smraw + ASML);
    float* smSC = (float*)(smraw + ASSC);
    float* smPM = (float*)(smraw + APM);
    float* smPS = (float*)(smraw + APS);

    int tid = threadIdx.x, lane = tid & 31, w = tid >> 5;
    int qi = (int)gridDim.x - 1 - (int)blockIdx.x;
    int bh = blockIdx.y;
    size_t tbase = (size_t)bh * Tt * Dd;
    const __half* qhp = g_qhi + tbase + ((size_t)qi << 7) * Dd;
    const __half* qlp = g_qlo + tbase + ((size_t)qi << 7) * Dd;
    const __half* khp = g_khi + tbase;
    const __half* klp = g_klo + tbase;
    const __half* vhp = g_vhi + tbase;
    const __half* vlp = g_vlo + tbase;

    // S-phase warp tiling (64m x 32n per warp)
    int Wm = (w & 1) << 6, Wn = (w >> 1) << 5;
    u32 aoff[4], a7[4], boff[2], b7[2], cA, cB;
    frag_setup(lane, Wm, Wn, aoff, a7, cA, boff, b7, cB);
    int wn = w >> 1;

    // PV-phase warp tiling (32m x 32d per warp)
    int Wm2 = (w & 3) << 5, Wd = (w >> 2) << 5;
    u32 p_aoff[2], p_a7[2];
#pragma unroll
    for (int mt2 = 0; mt2 < 2; mt2++) {
        int r = Wm2 + mt2 * 16 + (lane & 15);
        p_aoff[mt2] = (u32)(r << 8);   // P rows are 256B (128 fp16)
        p_a7[mt2] = (u32)(r & 7);
    }
    u32 p_cA = (u32)(lane >> 4);
    int vj = lane >> 3;
    int v_rbase = ((vj & 1) << 3) + (lane & 7);
    u32 v_cb = (u32)(Wd >> 3) + (u32)(vj >> 1);

    if (tid < 128) { smM[tid] = -1e30f; smL[tid] = 0.f; }

    copy_tile_c(sb + AQH, qhp, tid);
    copy_tile_c(sb + AQL, qlp, tid);
    copy_tile_c(sb + AKH0, khp, tid);
    copy_tile_c(sb + AKL0, klp, tid);
    CP_COMMIT();

    float acc2[2][4][4] = {};

    for (int j = 0; j <= qi; j++) {
        int kb = j & 1;
        CP_WAIT0();
        __syncthreads();

        copy_tile_c(sb + AVH, vhp + ((size_t)j << 7) * Dd, tid);
        copy_tile_c(sb + AVL, vlp + ((size_t)j << 7) * Dd, tid);
        CP_COMMIT();

        // ---- S = Q . K^T (3-pass)
        float sacc[4][4][4] = {};
        u32 khB = sb + (kb ? AKH1 : AKH0);
        u32 klB = sb + (kb ? AKL1 : AKL0);
        gemm_chunk(sb + AQH, sb + AQL, khB, klB,
                   aoff, a7, cA, boff, b7, cB, sacc);

        if (j < qi) {
            copy_tile_c(sb + (kb ? AKH0 : AKH1), khp + ((size_t)(j + 1) << 7) * Dd, tid);
            copy_tile_c(sb + (kb ? AKL0 : AKL1), klp + ((size_t)(j + 1) << 7) * Dd, tid);
            CP_COMMIT();
        }

        if (j == qi) {
#pragma unroll
            for (int mt = 0; mt < 4; mt++)
#pragma unroll
                for (int nt = 0; nt < 4; nt++)
#pragma unroll
                    for (int rg = 0; rg < 4; rg++) {
                        int r = Wm + mt * 16 + (lane >> 2) + ((rg >> 1) << 3);
                        int c = Wn + nt * 8 + ((lane & 3) << 1) + (rg & 1);
                        if (c > r) sacc[mt][nt][rg] = -1e30f;
                    }
        }

        // ---- softmax step 1: per-warp partial row max
#pragma unroll
        for (int mt = 0; mt < 4; mt++) {
#pragma unroll
            for (int rh = 0; rh < 2; rh++) {
                float mx = sacc[mt][0][rh * 2];
#pragma unroll
                for (int nt = 0; nt < 4; nt++) {
                    mx = fmaxf(mx, sacc[mt][nt][rh * 2]);
                    mx = fmaxf(mx, sacc[mt][nt][rh * 2 + 1]);
                }
                mx = fmaxf(mx, __shfl_xor_sync(0xffffffffu, mx, 1));
                mx = fmaxf(mx, __shfl_xor_sync(0xffffffffu, mx, 2));
                if ((lane & 3) == 0)
                    smPM[wn * 128 + Wm + mt * 16 + (lane >> 2) + rh * 8] = mx;
            }
        }
        __syncthreads();

        // ---- step 2: row max/scale update
        if (tid < 128) {
            float old = smM[tid];
            float mn = fmaxf(fmaxf(smPM[tid], smPM[128 + tid]),
                             fmaxf(smPM[256 + tid], smPM[384 + tid]));
            mn = fmaxf(mn, old);
            smSC[tid] = ex2f((old - mn) * L2E);
            smM[tid] = mn;
        }
        __syncthreads();

        // ---- step 3: exp, single-fp16 P store, partial row sums
#pragma unroll
        for (int mt = 0; mt < 4; mt++) {
#pragma unroll
            for (int rh = 0; rh < 2; rh++) {
                int r = Wm + mt * 16 + (lane >> 2) + rh * 8;
                float mnl = smM[r] * L2E;
                float rowsum = 0.f;
#pragma unroll
                for (int nt = 0; nt < 4; nt++) {
                    float p0 = ex2f(fmaf(sacc[mt][nt][rh * 2], L2E, -mnl));
                    float p1 = ex2f(fmaf(sacc[mt][nt][rh * 2 + 1], L2E, -mnl));
                    rowsum += p0 + p1;
                    u32 ch = ((u32)((Wn >> 3) + nt) ^ (u32)(r & 7)) << 4;
                    u32 off = (u32)(r << 8) + ch + ((u32)(lane & 3) << 2);
                    *(u32*)(smraw + APH + off) =
                        pack_f16(__float2half_rn(p0), __float2half_rn(p1));
                }
                rowsum += __shfl_xor_sync(0xffffffffu, rowsum, 1);
                rowsum += __shfl_xor_sync(0xffffffffu, rowsum, 2);
                if ((lane & 3) == 0) smPS[wn * 128 + r] = rowsum;
            }
        }
        if (j < qi) { CP_WAIT1(); } else { CP_WAIT0(); }
        __syncthreads();

        // ---- step 4: l update
        if (tid < 128) {
            smL[tid] = smL[tid] * smSC[tid] +
                       (smPS[tid] + smPS[128 + tid] + smPS[256 + tid] + smPS[384 + tid]);
        }

        // ---- rescale O
#pragma unroll
        for (int mt2 = 0; mt2 < 2; mt2++) {
            float sc0 = smSC[Wm2 + mt2 * 16 + (lane >> 2)];
            float sc1 = smSC[Wm2 + mt2 * 16 + (lane >> 2) + 8];
#pragma unroll
            for (int nt = 0; nt < 4; nt++) {
                acc2[mt2][nt][0] *= sc0;
                acc2[mt2][nt][1] *= sc0;
                acc2[mt2][nt][2] *= sc1;
                acc2[mt2][nt][3] *= sc1;
            }
        }

        // ---- O += P . V  (P single, V hi/lo: 2 passes)
#pragma unroll
        for (int s = 0; s < 8; s++) {
            u32 p_[2][4];
#pragma unroll
            for (int mt2 = 0; mt2 < 2; mt2++) {
                u32 ch = (((2 * (u32)s + p_cA) ^ p_a7[mt2]) << 4);
                ldsm4(sb + APH + p_aoff[mt2] + ch,
                      p_[mt2][0], p_[mt2][1], p_[mt2][2], p_[mt2][3]);
            }
            int vrow = (s << 4) + v_rbase;
            u32 vro = (u32)(vrow << 7);
            u32 v7 = (u32)(vrow & 7);
            u32 vh_[2][4], vl_[2][4];
#pragma unroll
            for (int g = 0; g < 2; g++) {
                u32 ch = (((v_cb + 2u * g) ^ v7) << 4);
                ldsm4t(sb + AVH + vro + ch, vh_[g][0], vh_[g][1], vh_[g][2], vh_[g][3]);
                ldsm4t(sb + AVL + vro + ch, vl_[g][0], vl_[g][1], vl_[g][2], vl_[g][3]);
            }
#pragma unroll
            for (int mt2 = 0; mt2 < 2; mt2++) {
#pragma unroll
                for (int nt = 0; nt < 4; nt++) {
                    int g = nt >> 1, su = (nt & 1) << 1;
                    mma16816(acc2[mt2][nt], p_[mt2][0], p_[mt2][1], p_[mt2][2], p_[mt2][3],
                             vh_[g][su], vh_[g][su + 1]);
                    mma16816(acc2[mt2][nt], p_[mt2][0], p_[mt2][1], p_[mt2][2], p_[mt2][3],
                             vl_[g][su], vl_[g][su + 1]);
                }
            }
        }
    }

    // ---- epilogue: normalize, single fp16 write [B*T, H*D]
    __syncthreads();
    int b = bh >> 4, h = bh & 15;
#pragma unroll
    for (int mt2 = 0; mt2 < 2; mt2++) {
#pragma unroll
        for (int rh = 0; rh < 2; rh++) {
            int r = Wm2 + mt2 * 16 + (lane >> 2) + rh * 8;
            float inv = 1.0f / smL[r];
            int t = (qi << 7) + r;
            size_t rowbase = ((size_t)(b * Tt + t)) * (Hh * Dd) + h * Dd;
#pragma unroll
            for (int nt = 0; nt < 4; nt++) {
                int d = Wd + nt * 8 + ((lane & 3) << 1);
                float v0 = acc2[mt2][nt][rh * 2] * inv;
                float v1 = acc2[mt2][nt][rh * 2 + 1] * inv;
                *(u32*)(g_a + rowbase + d) =
                    pack_f16(__float2half_rn(v0), __float2half_rn(v1));
            }
        }
    }
}

// ---------------------------------------------------------------------------
extern "C" void kernel_launch(void* const* d_in, const int* in_sizes, int n_in,
                              void* d_out, int out_size) {
    const float* x  = (const float*)d_in[0];
    const float* Wq = (const float*)d_in[1];
    const float* Wk = (const float*)d_in[2];
    const float* Wv = (const float*)d_in[3];
    const float* Wo = (const float*)d_in[4];
    float* out = (float*)d_out;

    cudaFuncSetAttribute(qkv_mma, cudaFuncAttributeMaxDynamicSharedMemorySize, QKV_SMEM);
    cudaFuncSetAttribute(out_mma, cudaFuncAttributeMaxDynamicSharedMemorySize, OUT_SMEM);
    cudaFuncSetAttribute(attn_mma, cudaFuncAttributeMaxDynamicSharedMemorySize, ATTN_SMEM);

    conv_x<<<8192, 256>>>(x);
    prep_wqkv<<<dim3(2, 32, 48), 256>>>(Wq, Wk, Wv);
    prep_wo<<<dim3(32, 32), 256>>>(Wo);
    qkv_mma<<<dim3(24, 64), 256, QKV_SMEM>>>();
    attn_mma<<<dim3(Tt / 128, Bb * Hh), 256, ATTN_SMEM>>>();
    out_mma<<<dim3(8, 64), 256, OUT_SMEM>>>(out);
}

// round 8
// speedup vs baseline: 4.8803x; 1.2973x over previous
#include <cuda_runtime.h>
#include <cuda_fp16.h>

#define Bb 4
#define Tt 2048
#define Ee 1024
#define Hh 16
#define Dd 64
#define MT (Bb * Tt)   // 8192 rows

typedef unsigned long long ull;
typedef unsigned int u32;

// ---------------- device scratch (allocation-free rule) ----------------
__device__ __align__(16) __half g_xhi[(size_t)MT * Ee];
__device__ __align__(16) __half g_xlo[(size_t)MT * Ee];
__device__ __align__(16) __half g_wt[(size_t)3 * Hh * Dd * Ee];     // [mat][h*64+d][e], Wq pre-scaled 1/8, single fp16
__device__ __align__(16) __half g_wot_hi[(size_t)Ee * Ee];          // [n][e]
__device__ __align__(16) __half g_wot_lo[(size_t)Ee * Ee];
__device__ __align__(16) __half g_a[(size_t)MT * Ee];               // attn out, single fp16
// layout [bh][t][d]
__device__ __align__(16) __half g_qhi[(size_t)Bb * Hh * Tt * Dd];
__device__ __align__(16) __half g_qlo[(size_t)Bb * Hh * Tt * Dd];
__device__ __align__(16) __half g_kk[(size_t)Bb * Hh * Tt * Dd];    // K single fp16
__device__ __align__(16) __half g_vhi[(size_t)Bb * Hh * Tt * Dd];
__device__ __align__(16) __half g_vlo[(size_t)Bb * Hh * Tt * Dd];

// ---------------- PTX helpers ----------------
__device__ __forceinline__ u32 smem_u32(const void* p) {
    u32 a;
    asm("{ .reg .u64 t; cvta.to.shared.u64 t, %1; cvt.u32.u64 %0, t; }"
        : "=r"(a) : "l"(p));
    return a;
}
__device__ __forceinline__ void cpa16(u32 dst, const void* src) {
    asm volatile("cp.async.cg.shared.global [%0], [%1], 16;"
                 :: "r"(dst), "l"(src) : "memory");
}
#define CP_COMMIT() asm volatile("cp.async.commit_group;" ::: "memory")
#define CP_WAIT1()  asm volatile("cp.async.wait_group 1;" ::: "memory")
#define CP_WAIT0()  asm volatile("cp.async.wait_group 0;" ::: "memory")

__device__ __forceinline__ void ldsm4(u32 addr, u32& r0, u32& r1, u32& r2, u32& r3) {
    asm volatile("ldmatrix.sync.aligned.m8n8.x4.shared.b16 {%0,%1,%2,%3}, [%4];"
                 : "=r"(r0), "=r"(r1), "=r"(r2), "=r"(r3) : "r"(addr));
}
__device__ __forceinline__ void ldsm4t(u32 addr, u32& r0, u32& r1, u32& r2, u32& r3) {
    asm volatile("ldmatrix.sync.aligned.m8n8.x4.trans.shared.b16 {%0,%1,%2,%3}, [%4];"
                 : "=r"(r0), "=r"(r1), "=r"(r2), "=r"(r3) : "r"(addr));
}
__device__ __forceinline__ void mma16816(float* d, u32 a0, u32 a1, u32 a2, u32 a3,
                                         u32 b0, u32 b1) {
    asm volatile(
        "mma.sync.aligned.m16n8k16.row.col.f32.f16.f16.f32 "
        "{%0,%1,%2,%3},{%4,%5,%6,%7},{%8,%9},{%0,%1,%2,%3};"
        : "+f"(d[0]), "+f"(d[1]), "+f"(d[2]), "+f"(d[3])
        : "r"(a0), "r"(a1), "r"(a2), "r"(a3), "r"(b0), "r"(b1));
}
__device__ __forceinline__ float ex2f(float x) {
    float r; asm("ex2.approx.f32 %0,%1;" : "=f"(r) : "f"(x)); return r;
}
__device__ __forceinline__ void split_f16(float v, __half& hi, __half& lo) {
    hi = __float2half_rn(v);
    lo = __float2half_rn(v - __half2float(hi));
}
__device__ __forceinline__ u32 pack_f16(__half a, __half b) {
    __half2 t = __halves2half2(a, b);
    return *(u32*)&t;
}

#define L2E 1.4426950408889634f

// ---------------------------------------------------------------------------
// Prep kernels
// ---------------------------------------------------------------------------
__global__ void __launch_bounds__(256) conv_x(const float* __restrict__ x) {
    size_t i = ((size_t)blockIdx.x * 256 + threadIdx.x) * 4;
    float4 v = *(const float4*)&x[i];
    __half h0, h1, h2, h3, l0, l1, l2, l3;
    split_f16(v.x, h0, l0); split_f16(v.y, h1, l1);
    split_f16(v.z, h2, l2); split_f16(v.w, h3, l3);
    *(u32*)(g_xhi + i) = pack_f16(h0, h1);
    *(u32*)(g_xhi + i + 2) = pack_f16(h2, h3);
    *(u32*)(g_xlo + i) = pack_f16(l0, l1);
    *(u32*)(g_xlo + i + 2) = pack_f16(l2, l3);
}

__global__ void __launch_bounds__(256) prep_wqkv(
    const float* __restrict__ Wq, const float* __restrict__ Wk,
    const float* __restrict__ Wv)
{
    __shared__ float tile[32][33];
    int z = blockIdx.z;
    int mat = z >> 4, h = z & 15;
    const float* W = (mat == 0 ? Wq : (mat == 1 ? Wk : Wv)) + (size_t)h * Ee * Dd;
    float scale = (mat == 0) ? 0.125f : 1.0f;   // fold D^-1/2 into Wq
    __half* dst = g_wt + ((size_t)mat * Hh + h) * Dd * Ee;
    int e0 = blockIdx.y << 5, d0 = blockIdx.x << 5;
    int tx = threadIdx.x & 31, ty = threadIdx.x >> 5;
#pragma unroll
    for (int j = 0; j < 4; j++)
        tile[ty + j * 8][tx] = W[(size_t)(e0 + ty + j * 8) * Dd + d0 + tx];
    __syncthreads();
#pragma unroll
    for (int j = 0; j < 4; j++) {
        int rr = ty + j * 8;
        dst[(size_t)(d0 + rr) * Ee + e0 + tx] = __float2half_rn(tile[tx][rr] * scale);
    }
}

__global__ void __launch_bounds__(256) prep_wo(const float* __restrict__ Wo) {
    __shared__ float tile[32][33];
    int n0 = blockIdx.x << 5, e0 = blockIdx.y << 5;
    int tx = threadIdx.x & 31, ty = threadIdx.x >> 5;
#pragma unroll
    for (int j = 0; j < 4; j++)
        tile[ty + j * 8][tx] = Wo[(size_t)(e0 + ty + j * 8) * Ee + n0 + tx];
    __syncthreads();
#pragma unroll
    for (int j = 0; j < 4; j++) {
        int rr = ty + j * 8;
        float v = tile[tx][rr];
        __half hi, lo;
        split_f16(v, hi, lo);
        size_t off = (size_t)(n0 + rr) * Ee + e0 + tx;
        g_wot_hi[off] = hi;
        g_wot_lo[off] = lo;
    }
}

// ---------------------------------------------------------------------------
// mma.sync GEMM machinery
// ---------------------------------------------------------------------------
#define TILE_B   16384u
#define QKV_BUF  49152u
#define QKV_SMEM (2u * QKV_BUF)
#define OUT_BUF  49152u
#define OUT_SMEM (2u * OUT_BUF)

__device__ __forceinline__ void copy_tile_async(u32 tb, const __half* sp, int tid) {
#pragma unroll
    for (int it = 0; it < 4; it++) {
        int cid = it * 256 + tid;
        int row = cid >> 3, c = cid & 7;
        u32 dst = tb + (u32)(row << 7) + (u32)(((c ^ (row & 7))) << 4);
        cpa16(dst, sp + (size_t)row * Ee + c * 8);
    }
}
__device__ __forceinline__ void copy_tile_c(u32 tb, const __half* sp, int tid) {
#pragma unroll
    for (int it = 0; it < 4; it++) {
        int cid = it * 256 + tid;
        int row = cid >> 3, c = cid & 7;
        u32 dst = tb + (u32)(row << 7) + (u32)(((c ^ (row & 7))) << 4);
        cpa16(dst, sp + (size_t)cid * 8);
    }
}

__device__ __forceinline__ void frag_setup(int lane, int Wm, int Wn,
                                           u32* aoff, u32* a7, u32& cA,
                                           u32* boff, u32* b7, u32& cB) {
#pragma unroll
    for (int mt = 0; mt < 4; mt++) {
        int r = Wm + mt * 16 + (lane & 15);
        aoff[mt] = (u32)(r << 7);
        a7[mt] = (u32)(r & 7);
    }
#pragma unroll
    for (int np = 0; np < 2; np++) {
        int r = Wn + np * 16 + ((lane >> 4) << 3) + (lane & 7);
        boff[np] = (u32)(r << 7);
        b7[np] = (u32)(r & 7);
    }
    cA = (u32)(lane >> 4);
    cB = (u32)((lane >> 3) & 1);
}

// 2-pass chunk: A split hi/lo, B single (QKV, attention S)
__device__ __forceinline__ void gemm_chunk2A(
    u32 sAh, u32 sAl, u32 sB,
    const u32* aoff, const u32* a7, u32 cA,
    const u32* boff, const u32* b7, u32 cB,
    float acc[4][4][4])
{
#pragma unroll
    for (int s = 0; s < 4; s++) {
        u32 ah[4][4], al[4][4], b_[2][4];
#pragma unroll
        for (int mt = 0; mt < 4; mt++) {
            u32 ca = (u32)(((2 * s + cA) ^ a7[mt]) << 4);
            ldsm4(sAh + aoff[mt] + ca, ah[mt][0], ah[mt][1], ah[mt][2], ah[mt][3]);
            ldsm4(sAl + aoff[mt] + ca, al[mt][0], al[mt][1], al[mt][2], al[mt][3]);
        }
#pragma unroll
        for (int np = 0; np < 2; np++) {
            u32 cb = (u32)(((2 * s + cB) ^ b7[np]) << 4);
            ldsm4(sB + boff[np] + cb, b_[np][0], b_[np][1], b_[np][2], b_[np][3]);
        }
#pragma unroll
        for (int mt = 0; mt < 4; mt++) {
#pragma unroll
            for (int nt = 0; nt < 4; nt++) {
                int np = nt >> 1, sel = (nt & 1) << 1;
                mma16816(acc[mt][nt], ah[mt][0], ah[mt][1], ah[mt][2], ah[mt][3],
                         b_[np][sel], b_[np][sel + 1]);
                mma16816(acc[mt][nt], al[mt][0], al[mt][1], al[mt][2], al[mt][3],
                         b_[np][sel], b_[np][sel + 1]);
            }
        }
    }
}

// 2-pass chunk: single A, split B (out projection)
__device__ __forceinline__ void gemm_chunk2(
    u32 sA, u32 sBh, u32 sBl,
    const u32* aoff, const u32* a7, u32 cA,
    const u32* boff, const u32* b7, u32 cB,
    float acc[4][4][4])
{
#pragma unroll
    for (int s = 0; s < 4; s++) {
        u32 a_[4][4], bh[2][4], bl[2][4];
#pragma unroll
        for (int mt = 0; mt < 4; mt++) {
            u32 ca = (u32)(((2 * s + cA) ^ a7[mt]) << 4);
            ldsm4(sA + aoff[mt] + ca, a_[mt][0], a_[mt][1], a_[mt][2], a_[mt][3]);
        }
#pragma unroll
        for (int np = 0; np < 2; np++) {
            u32 cb = (u32)(((2 * s + cB) ^ b7[np]) << 4);
            ldsm4(sBh + boff[np] + cb, bh[np][0], bh[np][1], bh[np][2], bh[np][3]);
            ldsm4(sBl + boff[np] + cb, bl[np][0], bl[np][1], bl[np][2], bl[np][3]);
        }
#pragma unroll
        for (int mt = 0; mt < 4; mt++) {
#pragma unroll
            for (int nt = 0; nt < 4; nt++) {
                int np = nt >> 1, sel = (nt & 1) << 1;
                mma16816(acc[mt][nt], a_[mt][0], a_[mt][1], a_[mt][2], a_[mt][3],
                         bh[np][sel], bh[np][sel + 1]);
                mma16816(acc[mt][nt], a_[mt][0], a_[mt][1], a_[mt][2], a_[mt][3],
                         bl[np][sel], bl[np][sel + 1]);
            }
        }
    }
}

// ---------------------------------------------------------------------------
// QKV projection (2-pass, 2 CTA/SM) -> q hi/lo, k single, v hi/lo.
// grid (24, 64), block 256, 96KB smem.
// ---------------------------------------------------------------------------
__global__ void __launch_bounds__(256, 2) qkv_mma() {
    extern __shared__ char smraw[];
    u32 sbase = smem_u32(smraw);

    int tid = threadIdx.x;
    int lane = tid & 31, w = tid >> 5;
    int Wm = (w & 1) << 6, Wn = (w >> 1) << 5;

    int n0 = blockIdx.x << 7;
    int m0 = blockIdx.y << 7;
    int mat = n0 >> 10;
    int nb = n0 & 1023;

    const __half* Ah = g_xhi + (size_t)m0 * Ee;
    const __half* Al = g_xlo + (size_t)m0 * Ee;
    const __half* Bw = g_wt + (size_t)mat * Hh * Dd * Ee + (size_t)nb * Ee;

    u32 aoff[4], a7[4], boff[2], b7[2], cA, cB;
    frag_setup(lane, Wm, Wn, aoff, a7, cA, boff, b7, cB);

    float acc[4][4][4] = {};

    copy_tile_async(sbase + 0 * TILE_B, Ah, tid);
    copy_tile_async(sbase + 1 * TILE_B, Al, tid);
    copy_tile_async(sbase + 2 * TILE_B, Bw, tid);
    CP_COMMIT();

    for (int c = 0; c < 16; c++) {
        CP_WAIT0();
        __syncthreads();
        if (c < 15) {
            u32 nb_ = sbase + ((u32)(c + 1) & 1u) * QKV_BUF;
            int k0 = (c + 1) << 6;
            copy_tile_async(nb_ + 0 * TILE_B, Ah + k0, tid);
            copy_tile_async(nb_ + 1 * TILE_B, Al + k0, tid);
            copy_tile_async(nb_ + 2 * TILE_B, Bw + k0, tid);
            CP_COMMIT();
        }
        u32 sb = sbase + ((u32)c & 1u) * QKV_BUF;
        gemm_chunk2A(sb, sb + TILE_B, sb + 2 * TILE_B,
                     aoff, a7, cA, boff, b7, cB, acc);
    }

#pragma unroll
    for (int mt = 0; mt < 4; mt++) {
#pragma unroll
        for (int nt = 0; nt < 4; nt++) {
            int n = nb + Wn + nt * 8 + ((lane & 3) << 1);
            int h = n >> 6, d = n & 63;
            int m = m0 + Wm + mt * 16 + (lane >> 2);
            int b = m >> 11, t = m & 2047;
            size_t base = (((size_t)(b * Hh + h)) * Tt + t) * Dd + d;
            if (mat == 1) {
                *(u32*)(g_kk + base) = pack_f16(__float2half_rn(acc[mt][nt][0]),
                                                __float2half_rn(acc[mt][nt][1]));
                *(u32*)(g_kk + base + 8 * Dd) = pack_f16(__float2half_rn(acc[mt][nt][2]),
                                                         __float2half_rn(acc[mt][nt][3]));
            } else {
                __half* outh = (mat == 0) ? g_qhi : g_vhi;
                __half* outl = (mat == 0) ? g_qlo : g_vlo;
                __half h0, h1, l0, l1;
                split_f16(acc[mt][nt][0], h0, l0);
                split_f16(acc[mt][nt][1], h1, l1);
                *(u32*)(outh + base) = pack_f16(h0, h1);
                *(u32*)(outl + base) = pack_f16(l0, l1);
                split_f16(acc[mt][nt][2], h0, l0);
                split_f16(acc[mt][nt][3], h1, l1);
                *(u32*)(outh + base + 8 * Dd) = pack_f16(h0, h1);
                *(u32*)(outl + base + 8 * Dd) = pack_f16(l0, l1);
            }
        }
    }
}

// ---------------------------------------------------------------------------
// Out projection (2-pass, 2 CTA/SM): out[8192,1024] = A_f16 * Wo.
// grid (8, 64), block 256.
// ---------------------------------------------------------------------------
__global__ void __launch_bounds__(256, 2) out_mma(float* __restrict__ out) {
    extern __shared__ char smraw[];
    u32 sbase = smem_u32(smraw);

    int tid = threadIdx.x;
    int lane = tid & 31, w = tid >> 5;
    int Wm = (w & 1) << 6, Wn = (w >> 1) << 5;

    int n0 = blockIdx.x << 7;
    int m0 = blockIdx.y << 7;

    const __half* A = g_a + (size_t)m0 * Ee;
    const __half* Bh = g_wot_hi + (size_t)n0 * Ee;
    const __half* Bl = g_wot_lo + (size_t)n0 * Ee;

    u32 aoff[4], a7[4], boff[2], b7[2], cA, cB;
    frag_setup(lane, Wm, Wn, aoff, a7, cA, boff, b7, cB);

    float acc[4][4][4] = {};

    copy_tile_async(sbase + 0 * TILE_B, A, tid);
    copy_tile_async(sbase + 1 * TILE_B, Bh, tid);
    copy_tile_async(sbase + 2 * TILE_B, Bl, tid);
    CP_COMMIT();

    for (int c = 0; c < 16; c++) {
        CP_WAIT0();
        __syncthreads();
        if (c < 15) {
            u32 nb_ = sbase + ((u32)(c + 1) & 1u) * OUT_BUF;
            int k0 = (c + 1) << 6;
            copy_tile_async(nb_ + 0 * TILE_B, A + k0, tid);
            copy_tile_async(nb_ + 1 * TILE_B, Bh + k0, tid);
            copy_tile_async(nb_ + 2 * TILE_B, Bl + k0, tid);
            CP_COMMIT();
        }
        u32 sb = sbase + ((u32)c & 1u) * OUT_BUF;
        gemm_chunk2(sb, sb + TILE_B, sb + 2 * TILE_B,
                    aoff, a7, cA, boff, b7, cB, acc);
    }

#pragma unroll
    for (int mt = 0; mt < 4; mt++) {
#pragma unroll
        for (int nt = 0; nt < 4; nt++) {
            int n = n0 + Wn + nt * 8 + ((lane & 3) << 1);
            int m = m0 + Wm + mt * 16 + (lane >> 2);
            *(float2*)&out[(size_t)m * Ee + n] = make_float2(acc[mt][nt][0], acc[mt][nt][1]);
            *(float2*)&out[(size_t)(m + 8) * Ee + n] = make_float2(acc[mt][nt][2], acc[mt][nt][3]);
        }
    }
}

// ---------------------------------------------------------------------------
// Tensor-core causal flash attention.
// S: 2-pass (Q hi/lo, K single); PV: 2-pass (P single, V hi/lo).
// grid (16 reversed, 64), block 256, ~133.5KB dynamic smem.
// ---------------------------------------------------------------------------
#define AQH 0u
#define AQL 16384u
#define AKB0 32768u
#define AKB1 49152u
#define AVH 65536u
#define AVL 81920u
#define APH 98304u
#define ASMM 131072u
#define ASML 131584u
#define ASSC 132096u
#define APM  132608u
#define APS  134656u
#define ATTN_SMEM 136704u

__global__ void __launch_bounds__(256, 1) attn_mma() {
    extern __shared__ char smraw[];
    u32 sb = smem_u32(smraw);
    float* smM = (float*)(smraw + ASMM);
    float* smL = (float*)(smraw + ASML);
    float* smSC = (float*)(smraw + ASSC);
    float* smPM = (float*)(smraw + APM);
    float* smPS = (float*)(smraw + APS);

    int tid = threadIdx.x, lane = tid & 31, w = tid >> 5;
    int qi = (int)gridDim.x - 1 - (int)blockIdx.x;
    int bh = blockIdx.y;
    size_t tbase = (size_t)bh * Tt * Dd;
    const __half* qhp = g_qhi + tbase + ((size_t)qi << 7) * Dd;
    const __half* qlp = g_qlo + tbase + ((size_t)qi << 7) * Dd;
    const __half* kp  = g_kk  + tbase;
    const __half* vhp = g_vhi + tbase;
    const __half* vlp = g_vlo + tbase;

    // S-phase warp tiling (64m x 32n per warp)
    int Wm = (w & 1) << 6, Wn = (w >> 1) << 5;
    u32 aoff[4], a7[4], boff[2], b7[2], cA, cB;
    frag_setup(lane, Wm, Wn, aoff, a7, cA, boff, b7, cB);
    int wn = w >> 1;

    // PV-phase warp tiling (32m x 32d per warp)
    int Wm2 = (w & 3) << 5, Wd = (w >> 2) << 5;
    u32 p_aoff[2], p_a7[2];
#pragma unroll
    for (int mt2 = 0; mt2 < 2; mt2++) {
        int r = Wm2 + mt2 * 16 + (lane & 15);
        p_aoff[mt2] = (u32)(r << 8);   // P rows are 256B (128 fp16)
        p_a7[mt2] = (u32)(r & 7);
    }
    u32 p_cA = (u32)(lane >> 4);
    int vj = lane >> 3;
    int v_rbase = ((vj & 1) << 3) + (lane & 7);
    u32 v_cb = (u32)(Wd >> 3) + (u32)(vj >> 1);

    if (tid < 128) { smM[tid] = -1e30f; smL[tid] = 0.f; }

    copy_tile_c(sb + AQH, qhp, tid);
    copy_tile_c(sb + AQL, qlp, tid);
    copy_tile_c(sb + AKB0, kp, tid);
    CP_COMMIT();

    float acc2[2][4][4] = {};

    for (int j = 0; j <= qi; j++) {
        int kb = j & 1;
        CP_WAIT0();
        __syncthreads();

        copy_tile_c(sb + AVH, vhp + ((size_t)j << 7) * Dd, tid);
        copy_tile_c(sb + AVL, vlp + ((size_t)j << 7) * Dd, tid);
        CP_COMMIT();

        // ---- S = Q . K^T (2-pass: Q hi/lo, K single)
        float sacc[4][4][4] = {};
        gemm_chunk2A(sb + AQH, sb + AQL, sb + (kb ? AKB1 : AKB0),
                     aoff, a7, cA, boff, b7, cB, sacc);

        if (j < qi) {
            copy_tile_c(sb + (kb ? AKB0 : AKB1), kp + ((size_t)(j + 1) << 7) * Dd, tid);
            CP_COMMIT();
        }

        if (j == qi) {
#pragma unroll
            for (int mt = 0; mt < 4; mt++)
#pragma unroll
                for (int nt = 0; nt < 4; nt++)
#pragma unroll
                    for (int rg = 0; rg < 4; rg++) {
                        int r = Wm + mt * 16 + (lane >> 2) + ((rg >> 1) << 3);
                        int c = Wn + nt * 8 + ((lane & 3) << 1) + (rg & 1);
                        if (c > r) sacc[mt][nt][rg] = -1e30f;
                    }
        }

        // ---- softmax step 1: per-warp partial row max
#pragma unroll
        for (int mt = 0; mt < 4; mt++) {
#pragma unroll
            for (int rh = 0; rh < 2; rh++) {
                float mx = sacc[mt][0][rh * 2];
#pragma unroll
                for (int nt = 0; nt < 4; nt++) {
                    mx = fmaxf(mx, sacc[mt][nt][rh * 2]);
                    mx = fmaxf(mx, sacc[mt][nt][rh * 2 + 1]);
                }
                mx = fmaxf(mx, __shfl_xor_sync(0xffffffffu, mx, 1));
                mx = fmaxf(mx, __shfl_xor_sync(0xffffffffu, mx, 2));
                if ((lane & 3) == 0)
                    smPM[wn * 128 + Wm + mt * 16 + (lane >> 2) + rh * 8] = mx;
            }
        }
        __syncthreads();

        // ---- step 2: row max/scale update
        if (tid < 128) {
            float old = smM[tid];
            float mn = fmaxf(fmaxf(smPM[tid], smPM[128 + tid]),
                             fmaxf(smPM[256 + tid], smPM[384 + tid]));
            mn = fmaxf(mn, old);
            smSC[tid] = ex2f((old - mn) * L2E);
            smM[tid] = mn;
        }
        __syncthreads();

        // ---- step 3: exp, single-fp16 P store, partial row sums
#pragma unroll
        for (int mt = 0; mt < 4; mt++) {
#pragma unroll
            for (int rh = 0; rh < 2; rh++) {
                int r = Wm + mt * 16 + (lane >> 2) + rh * 8;
                float mnl = smM[r] * L2E;
                float rowsum = 0.f;
#pragma unroll
                for (int nt = 0; nt < 4; nt++) {
                    float p0 = ex2f(fmaf(sacc[mt][nt][rh * 2], L2E, -mnl));
                    float p1 = ex2f(fmaf(sacc[mt][nt][rh * 2 + 1], L2E, -mnl));
                    rowsum += p0 + p1;
                    u32 ch = ((u32)((Wn >> 3) + nt) ^ (u32)(r & 7)) << 4;
                    u32 off = (u32)(r << 8) + ch + ((u32)(lane & 3) << 2);
                    *(u32*)(smraw + APH + off) =
                        pack_f16(__float2half_rn(p0), __float2half_rn(p1));
                }
                rowsum += __shfl_xor_sync(0xffffffffu, rowsum, 1);
                rowsum += __shfl_xor_sync(0xffffffffu, rowsum, 2);
                if ((lane & 3) == 0) smPS[wn * 128 + r] = rowsum;
            }
        }
        if (j < qi) { CP_WAIT1(); } else { CP_WAIT0(); }
        __syncthreads();

        // ---- step 4: l update
        if (tid < 128) {
            smL[tid] = smL[tid] * smSC[tid] +
                       (smPS[tid] + smPS[128 + tid] + smPS[256 + tid] + smPS[384 + tid]);
        }

        // ---- rescale O
#pragma unroll
        for (int mt2 = 0; mt2 < 2; mt2++) {
            float sc0 = smSC[Wm2 + mt2 * 16 + (lane >> 2)];
            float sc1 = smSC[Wm2 + mt2 * 16 + (lane >> 2) + 8];
#pragma unroll
            for (int nt = 0; nt < 4; nt++) {
                acc2[mt2][nt][0] *= sc0;
                acc2[mt2][nt][1] *= sc0;
                acc2[mt2][nt][2] *= sc1;
                acc2[mt2][nt][3] *= sc1;
            }
        }

        // ---- O += P . V  (P single, V hi/lo: 2 passes)
#pragma unroll
        for (int s = 0; s < 8; s++) {
            u32 p_[2][4];
#pragma unroll
            for (int mt2 = 0; mt2 < 2; mt2++) {
                u32 ch = (((2 * (u32)s + p_cA) ^ p_a7[mt2]) << 4);
                ldsm4(sb + APH + p_aoff[mt2] + ch,
                      p_[mt2][0], p_[mt2][1], p_[mt2][2], p_[mt2][3]);
            }
            int vrow = (s << 4) + v_rbase;
            u32 vro = (u32)(vrow << 7);
            u32 v7 = (u32)(vrow & 7);
            u32 vh_[2][4], vl_[2][4];
#pragma unroll
            for (int g = 0; g < 2; g++) {
                u32 ch = (((v_cb + 2u * g) ^ v7) << 4);
                ldsm4t(sb + AVH + vro + ch, vh_[g][0], vh_[g][1], vh_[g][2], vh_[g][3]);
                ldsm4t(sb + AVL + vro + ch, vl_[g][0], vl_[g][1], vl_[g][2], vl_[g][3]);
            }
#pragma unroll
            for (int mt2 = 0; mt2 < 2; mt2++) {
#pragma unroll
                for (int nt = 0; nt < 4; nt++) {
                    int g = nt >> 1, su = (nt & 1) << 1;
                    mma16816(acc2[mt2][nt], p_[mt2][0], p_[mt2][1], p_[mt2][2], p_[mt2][3],
                             vh_[g][su], vh_[g][su + 1]);
                    mma16816(acc2[mt2][nt], p_[mt2][0], p_[mt2][1], p_[mt2][2], p_[mt2][3],
                             vl_[g][su], vl_[g][su + 1]);
                }
            }
        }
    }

    // ---- epilogue: normalize, single fp16 write [B*T, H*D]
    __syncthreads();
    int b = bh >> 4, h = bh & 15;
#pragma unroll
    for (int mt2 = 0; mt2 < 2; mt2++) {
#pragma unroll
        for (int rh = 0; rh < 2; rh++) {
            int r = Wm2 + mt2 * 16 + (lane >> 2) + rh * 8;
            float inv = 1.0f / smL[r];
            int t = (qi << 7) + r;
            size_t rowbase = ((size_t)(b * Tt + t)) * (Hh * Dd) + h * Dd;
#pragma unroll
            for (int nt = 0; nt < 4; nt++) {
                int d = Wd + nt * 8 + ((lane & 3) << 1);
                float v0 = acc2[mt2][nt][rh * 2] * inv;
                float v1 = acc2[mt2][nt][rh * 2 + 1] * inv;
                *(u32*)(g_a + rowbase + d) =
                    pack_f16(__float2half_rn(v0), __float2half_rn(v1));
            }
        }
    }
}

// ---------------------------------------------------------------------------
extern "C" void kernel_launch(void* const* d_in, const int* in_sizes, int n_in,
                              void* d_out, int out_size) {
    const float* x  = (const float*)d_in[0];
    const float* Wq = (const float*)d_in[1];
    const float* Wk = (const float*)d_in[2];
    const float* Wv = (const float*)d_in[3];
    const float* Wo = (const float*)d_in[4];
    float* out = (float*)d_out;

    cudaFuncSetAttribute(qkv_mma, cudaFuncAttributeMaxDynamicSharedMemorySize, QKV_SMEM);
    cudaFuncSetAttribute(out_mma, cudaFuncAttributeMaxDynamicSharedMemorySize, OUT_SMEM);
    cudaFuncSetAttribute(attn_mma, cudaFuncAttributeMaxDynamicSharedMemorySize, ATTN_SMEM);

    conv_x<<<8192, 256>>>(x);
    prep_wqkv<<<dim3(2, 32, 48), 256>>>(Wq, Wk, Wv);
    prep_wo<<<dim3(32, 32), 256>>>(Wo);
    qkv_mma<<<dim3(24, 64), 256, QKV_SMEM>>>();
    attn_mma<<<dim3(Tt / 128, Bb * Hh), 256, ATTN_SMEM>>>();
    out_mma<<<dim3(8, 64), 256, OUT_SMEM>>>(out);
}

// round 9
// speedup vs baseline: 6.3026x; 1.2914x over previous
#include <cuda_runtime.h>
#include <cuda_fp16.h>

#define Bb 4
#define Tt 2048
#define Ee 1024
#define Hh 16
#define Dd 64
#define MT (Bb * Tt)   // 8192 rows

typedef unsigned long long ull;
typedef unsigned int u32;

// ---------------- device scratch (allocation-free rule) ----------------
__device__ __align__(16) __half g_x[(size_t)MT * Ee];               // x single fp16
__device__ __align__(16) __half g_wt[(size_t)3 * Hh * Dd * Ee];     // [mat][h*64+d][e], Wq pre-scaled 1/8
__device__ __align__(16) __half g_wot[(size_t)Ee * Ee];             // [n][e] single fp16
__device__ __align__(16) __half g_a[(size_t)MT * Ee];               // attn out, single fp16
// layout [bh][t][d]
__device__ __align__(16) __half g_qhi[(size_t)Bb * Hh * Tt * Dd];
__device__ __align__(16) __half g_qlo[(size_t)Bb * Hh * Tt * Dd];
__device__ __align__(16) __half g_kk[(size_t)Bb * Hh * Tt * Dd];    // K single fp16
__device__ __align__(16) __half g_vhi[(size_t)Bb * Hh * Tt * Dd];
__device__ __align__(16) __half g_vlo[(size_t)Bb * Hh * Tt * Dd];

// ---------------- PTX helpers ----------------
__device__ __forceinline__ u32 smem_u32(const void* p) {
    u32 a;
    asm("{ .reg .u64 t; cvta.to.shared.u64 t, %1; cvt.u32.u64 %0, t; }"
        : "=r"(a) : "l"(p));
    return a;
}
__device__ __forceinline__ void cpa16(u32 dst, const void* src) {
    asm volatile("cp.async.cg.shared.global [%0], [%1], 16;"
                 :: "r"(dst), "l"(src) : "memory");
}
#define CP_COMMIT() asm volatile("cp.async.commit_group;" ::: "memory")
#define CP_WAIT1()  asm volatile("cp.async.wait_group 1;" ::: "memory")
#define CP_WAIT0()  asm volatile("cp.async.wait_group 0;" ::: "memory")

__device__ __forceinline__ void ldsm4(u32 addr, u32& r0, u32& r1, u32& r2, u32& r3) {
    asm volatile("ldmatrix.sync.aligned.m8n8.x4.shared.b16 {%0,%1,%2,%3}, [%4];"
                 : "=r"(r0), "=r"(r1), "=r"(r2), "=r"(r3) : "r"(addr));
}
__device__ __forceinline__ void ldsm4t(u32 addr, u32& r0, u32& r1, u32& r2, u32& r3) {
    asm volatile("ldmatrix.sync.aligned.m8n8.x4.trans.shared.b16 {%0,%1,%2,%3}, [%4];"
                 : "=r"(r0), "=r"(r1), "=r"(r2), "=r"(r3) : "r"(addr));
}
__device__ __forceinline__ void mma16816(float* d, u32 a0, u32 a1, u32 a2, u32 a3,
                                         u32 b0, u32 b1) {
    asm volatile(
        "mma.sync.aligned.m16n8k16.row.col.f32.f16.f16.f32 "
        "{%0,%1,%2,%3},{%4,%5,%6,%7},{%8,%9},{%0,%1,%2,%3};"
        : "+f"(d[0]), "+f"(d[1]), "+f"(d[2]), "+f"(d[3])
        : "r"(a0), "r"(a1), "r"(a2), "r"(a3), "r"(b0), "r"(b1));
}
__device__ __forceinline__ float ex2f(float x) {
    float r; asm("ex2.approx.f32 %0,%1;" : "=f"(r) : "f"(x)); return r;
}
__device__ __forceinline__ void split_f16(float v, __half& hi, __half& lo) {
    hi = __float2half_rn(v);
    lo = __float2half_rn(v - __half2float(hi));
}
__device__ __forceinline__ u32 pack_f16(__half a, __half b) {
    __half2 t = __halves2half2(a, b);
    return *(u32*)&t;
}

#define L2E 1.4426950408889634f

// ---------------------------------------------------------------------------
// Prep kernels
// ---------------------------------------------------------------------------
__global__ void __launch_bounds__(256) conv_x(const float* __restrict__ x) {
    size_t i = ((size_t)blockIdx.x * 256 + threadIdx.x) * 4;
    float4 v = *(const float4*)&x[i];
    *(u32*)(g_x + i) = pack_f16(__float2half_rn(v.x), __float2half_rn(v.y));
    *(u32*)(g_x + i + 2) = pack_f16(__float2half_rn(v.z), __float2half_rn(v.w));
}

__global__ void __launch_bounds__(256) prep_wqkv(
    const float* __restrict__ Wq, const float* __restrict__ Wk,
    const float* __restrict__ Wv)
{
    __shared__ float tile[32][33];
    int z = blockIdx.z;
    int mat = z >> 4, h = z & 15;
    const float* W = (mat == 0 ? Wq : (mat == 1 ? Wk : Wv)) + (size_t)h * Ee * Dd;
    float scale = (mat == 0) ? 0.125f : 1.0f;   // fold D^-1/2 into Wq
    __half* dst = g_wt + ((size_t)mat * Hh + h) * Dd * Ee;
    int e0 = blockIdx.y << 5, d0 = blockIdx.x << 5;
    int tx = threadIdx.x & 31, ty = threadIdx.x >> 5;
#pragma unroll
    for (int j = 0; j < 4; j++)
        tile[ty + j * 8][tx] = W[(size_t)(e0 + ty + j * 8) * Dd + d0 + tx];
    __syncthreads();
#pragma unroll
    for (int j = 0; j < 4; j++) {
        int rr = ty + j * 8;
        dst[(size_t)(d0 + rr) * Ee + e0 + tx] = __float2half_rn(tile[tx][rr] * scale);
    }
}

__global__ void __launch_bounds__(256) prep_wo(const float* __restrict__ Wo) {
    __shared__ float tile[32][33];
    int n0 = blockIdx.x << 5, e0 = blockIdx.y << 5;
    int tx = threadIdx.x & 31, ty = threadIdx.x >> 5;
#pragma unroll
    for (int j = 0; j < 4; j++)
        tile[ty + j * 8][tx] = Wo[(size_t)(e0 + ty + j * 8) * Ee + n0 + tx];
    __syncthreads();
#pragma unroll
    for (int j = 0; j < 4; j++) {
        int rr = ty + j * 8;
        g_wot[(size_t)(n0 + rr) * Ee + e0 + tx] = __float2half_rn(tile[tx][rr]);
    }
}

// ---------------------------------------------------------------------------
// mma.sync GEMM machinery
// ---------------------------------------------------------------------------
#define TILE_B   16384u
#define G1_BUF   32768u
#define G1_SMEM  (2u * G1_BUF)

__device__ __forceinline__ void copy_tile_async(u32 tb, const __half* sp, int tid) {
#pragma unroll
    for (int it = 0; it < 4; it++) {
        int cid = it * 256 + tid;
        int row = cid >> 3, c = cid & 7;
        u32 dst = tb + (u32)(row << 7) + (u32)(((c ^ (row & 7))) << 4);
        cpa16(dst, sp + (size_t)row * Ee + c * 8);
    }
}
__device__ __forceinline__ void copy_tile_c(u32 tb, const __half* sp, int tid) {
#pragma unroll
    for (int it = 0; it < 4; it++) {
        int cid = it * 256 + tid;
        int row = cid >> 3, c = cid & 7;
        u32 dst = tb + (u32)(row << 7) + (u32)(((c ^ (row & 7))) << 4);
        cpa16(dst, sp + (size_t)cid * 8);
    }
}

__device__ __forceinline__ void frag_setup(int lane, int Wm, int Wn,
                                           u32* aoff, u32* a7, u32& cA,
                                           u32* boff, u32* b7, u32& cB) {
#pragma unroll
    for (int mt = 0; mt < 4; mt++) {
        int r = Wm + mt * 16 + (lane & 15);
        aoff[mt] = (u32)(r << 7);
        a7[mt] = (u32)(r & 7);
    }
#pragma unroll
    for (int np = 0; np < 2; np++) {
        int r = Wn + np * 16 + ((lane >> 4) << 3) + (lane & 7);
        boff[np] = (u32)(r << 7);
        b7[np] = (u32)(r & 7);
    }
    cA = (u32)(lane >> 4);
    cB = (u32)((lane >> 3) & 1);
}

// 1-pass chunk: single A, single B (QKV, out projection)
__device__ __forceinline__ void gemm_chunk1(
    u32 sA, u32 sB,
    const u32* aoff, const u32* a7, u32 cA,
    const u32* boff, const u32* b7, u32 cB,
    float acc[4][4][4])
{
#pragma unroll
    for (int s = 0; s < 4; s++) {
        u32 a_[4][4], b_[2][4];
#pragma unroll
        for (int mt = 0; mt < 4; mt++) {
            u32 ca = (u32)(((2 * s + cA) ^ a7[mt]) << 4);
            ldsm4(sA + aoff[mt] + ca, a_[mt][0], a_[mt][1], a_[mt][2], a_[mt][3]);
        }
#pragma unroll
        for (int np = 0; np < 2; np++) {
            u32 cb = (u32)(((2 * s + cB) ^ b7[np]) << 4);
            ldsm4(sB + boff[np] + cb, b_[np][0], b_[np][1], b_[np][2], b_[np][3]);
        }
#pragma unroll
        for (int mt = 0; mt < 4; mt++) {
#pragma unroll
            for (int nt = 0; nt < 4; nt++) {
                int np = nt >> 1, sel = (nt & 1) << 1;
                mma16816(acc[mt][nt], a_[mt][0], a_[mt][1], a_[mt][2], a_[mt][3],
                         b_[np][sel], b_[np][sel + 1]);
            }
        }
    }
}

// 2-pass chunk: A split hi/lo, B single (attention S)
__device__ __forceinline__ void gemm_chunk2A(
    u32 sAh, u32 sAl, u32 sB,
    const u32* aoff, const u32* a7, u32 cA,
    const u32* boff, const u32* b7, u32 cB,
    float acc[4][4][4])
{
#pragma unroll
    for (int s = 0; s < 4; s++) {
        u32 ah[4][4], al[4][4], b_[2][4];
#pragma unroll
        for (int mt = 0; mt < 4; mt++) {
            u32 ca = (u32)(((2 * s + cA) ^ a7[mt]) << 4);
            ldsm4(sAh + aoff[mt] + ca, ah[mt][0], ah[mt][1], ah[mt][2], ah[mt][3]);
            ldsm4(sAl + aoff[mt] + ca, al[mt][0], al[mt][1], al[mt][2], al[mt][3]);
        }
#pragma unroll
        for (int np = 0; np < 2; np++) {
            u32 cb = (u32)(((2 * s + cB) ^ b7[np]) << 4);
            ldsm4(sB + boff[np] + cb, b_[np][0], b_[np][1], b_[np][2], b_[np][3]);
        }
#pragma unroll
        for (int mt = 0; mt < 4; mt++) {
#pragma unroll
            for (int nt = 0; nt < 4; nt++) {
                int np = nt >> 1, sel = (nt & 1) << 1;
                mma16816(acc[mt][nt], ah[mt][0], ah[mt][1], ah[mt][2], ah[mt][3],
                         b_[np][sel], b_[np][sel + 1]);
                mma16816(acc[mt][nt], al[mt][0], al[mt][1], al[mt][2], al[mt][3],
                         b_[np][sel], b_[np][sel + 1]);
            }
        }
    }
}

// ---------------------------------------------------------------------------
// QKV projection (1-pass, 2 CTA/SM) -> q hi/lo, k single, v hi/lo.
// grid (24, 64), block 256, 64KB smem.
// ---------------------------------------------------------------------------
__global__ void __launch_bounds__(256, 2) qkv_mma() {
    extern __shared__ char smraw[];
    u32 sbase = smem_u32(smraw);

    int tid = threadIdx.x;
    int lane = tid & 31, w = tid >> 5;
    int Wm = (w & 1) << 6, Wn = (w >> 1) << 5;

    int n0 = blockIdx.x << 7;
    int m0 = blockIdx.y << 7;
    int mat = n0 >> 10;
    int nb = n0 & 1023;

    const __half* A = g_x + (size_t)m0 * Ee;
    const __half* Bw = g_wt + (size_t)mat * Hh * Dd * Ee + (size_t)nb * Ee;

    u32 aoff[4], a7[4], boff[2], b7[2], cA, cB;
    frag_setup(lane, Wm, Wn, aoff, a7, cA, boff, b7, cB);

    float acc[4][4][4] = {};

    copy_tile_async(sbase + 0 * TILE_B, A, tid);
    copy_tile_async(sbase + 1 * TILE_B, Bw, tid);
    CP_COMMIT();

    for (int c = 0; c < 16; c++) {
        CP_WAIT0();
        __syncthreads();
        if (c < 15) {
            u32 nb_ = sbase + ((u32)(c + 1) & 1u) * G1_BUF;
            int k0 = (c + 1) << 6;
            copy_tile_async(nb_ + 0 * TILE_B, A + k0, tid);
            copy_tile_async(nb_ + 1 * TILE_B, Bw + k0, tid);
            CP_COMMIT();
        }
        u32 sb = sbase + ((u32)c & 1u) * G1_BUF;
        gemm_chunk1(sb, sb + TILE_B, aoff, a7, cA, boff, b7, cB, acc);
    }

#pragma unroll
    for (int mt = 0; mt < 4; mt++) {
#pragma unroll
        for (int nt = 0; nt < 4; nt++) {
            int n = nb + Wn + nt * 8 + ((lane & 3) << 1);
            int h = n >> 6, d = n & 63;
            int m = m0 + Wm + mt * 16 + (lane >> 2);
            int b = m >> 11, t = m & 2047;
            size_t base = (((size_t)(b * Hh + h)) * Tt + t) * Dd + d;
            if (mat == 1) {
                *(u32*)(g_kk + base) = pack_f16(__float2half_rn(acc[mt][nt][0]),
                                                __float2half_rn(acc[mt][nt][1]));
                *(u32*)(g_kk + base + 8 * Dd) = pack_f16(__float2half_rn(acc[mt][nt][2]),
                                                         __float2half_rn(acc[mt][nt][3]));
            } else {
                __half* outh = (mat == 0) ? g_qhi : g_vhi;
                __half* outl = (mat == 0) ? g_qlo : g_vlo;
                __half h0, h1, l0, l1;
                split_f16(acc[mt][nt][0], h0, l0);
                split_f16(acc[mt][nt][1], h1, l1);
                *(u32*)(outh + base) = pack_f16(h0, h1);
                *(u32*)(outl + base) = pack_f16(l0, l1);
                split_f16(acc[mt][nt][2], h0, l0);
                split_f16(acc[mt][nt][3], h1, l1);
                *(u32*)(outh + base + 8 * Dd) = pack_f16(h0, h1);
                *(u32*)(outl + base + 8 * Dd) = pack_f16(l0, l1);
            }
        }
    }
}

// ---------------------------------------------------------------------------
// Out projection (1-pass, 2 CTA/SM): out[8192,1024] = A_f16 * Wo_f16.
// grid (8, 64), block 256.
// ---------------------------------------------------------------------------
__global__ void __launch_bounds__(256, 2) out_mma(float* __restrict__ out) {
    extern __shared__ char smraw[];
    u32 sbase = smem_u32(smraw);

    int tid = threadIdx.x;
    int lane = tid & 31, w = tid >> 5;
    int Wm = (w & 1) << 6, Wn = (w >> 1) << 5;

    int n0 = blockIdx.x << 7;
    int m0 = blockIdx.y << 7;

    const __half* A = g_a + (size_t)m0 * Ee;
    const __half* B = g_wot + (size_t)n0 * Ee;

    u32 aoff[4], a7[4], boff[2], b7[2], cA, cB;
    frag_setup(lane, Wm, Wn, aoff, a7, cA, boff, b7, cB);

    float acc[4][4][4] = {};

    copy_tile_async(sbase + 0 * TILE_B, A, tid);
    copy_tile_async(sbase + 1 * TILE_B, B, tid);
    CP_COMMIT();

    for (int c = 0; c < 16; c++) {
        CP_WAIT0();
        __syncthreads();
        if (c < 15) {
            u32 nb_ = sbase + ((u32)(c + 1) & 1u) * G1_BUF;
            int k0 = (c + 1) << 6;
            copy_tile_async(nb_ + 0 * TILE_B, A + k0, tid);
            copy_tile_async(nb_ + 1 * TILE_B, B + k0, tid);
            CP_COMMIT();
        }
        u32 sb = sbase + ((u32)c & 1u) * G1_BUF;
        gemm_chunk1(sb, sb + TILE_B, aoff, a7, cA, boff, b7, cB, acc);
    }

#pragma unroll
    for (int mt = 0; mt < 4; mt++) {
#pragma unroll
        for (int nt = 0; nt < 4; nt++) {
            int n = n0 + Wn + nt * 8 + ((lane & 3) << 1);
            int m = m0 + Wm + mt * 16 + (lane >> 2);
            *(float2*)&out[(size_t)m * Ee + n] = make_float2(acc[mt][nt][0], acc[mt][nt][1]);
            *(float2*)&out[(size_t)(m + 8) * Ee + n] = make_float2(acc[mt][nt][2], acc[mt][nt][3]);
        }
    }
}

// ---------------------------------------------------------------------------
// Tensor-core causal flash attention (unchanged from R7).
// S: 2-pass (Q hi/lo, K single); PV: 2-pass (P single, V hi/lo).
// grid (16 reversed, 64), block 256, ~133.5KB dynamic smem.
// ---------------------------------------------------------------------------
#define AQH 0u
#define AQL 16384u
#define AKB0 32768u
#define AKB1 49152u
#define AVH 65536u
#define AVL 81920u
#define APH 98304u
#define ASMM 131072u
#define ASML 131584u
#define ASSC 132096u
#define APM  132608u
#define APS  134656u
#define ATTN_SMEM 136704u

__global__ void __launch_bounds__(256, 1) attn_mma() {
    extern __shared__ char smraw[];
    u32 sb = smem_u32(smraw);
    float* smM = (float*)(smraw + ASMM);
    float* smL = (float*)(smraw + ASML);
    float* smSC = (float*)(smraw + ASSC);
    float* smPM = (float*)(smraw + APM);
    float* smPS = (float*)(smraw + APS);

    int tid = threadIdx.x, lane = tid & 31, w = tid >> 5;
    int qi = (int)gridDim.x - 1 - (int)blockIdx.x;
    int bh = blockIdx.y;
    size_t tbase = (size_t)bh * Tt * Dd;
    const __half* qhp = g_qhi + tbase + ((size_t)qi << 7) * Dd;
    const __half* qlp = g_qlo + tbase + ((size_t)qi << 7) * Dd;
    const __half* kp  = g_kk  + tbase;
    const __half* vhp = g_vhi + tbase;
    const __half* vlp = g_vlo + tbase;

    int Wm = (w & 1) << 6, Wn = (w >> 1) << 5;
    u32 aoff[4], a7[4], boff[2], b7[2], cA, cB;
    frag_setup(lane, Wm, Wn, aoff, a7, cA, boff, b7, cB);
    int wn = w >> 1;

    int Wm2 = (w & 3) << 5, Wd = (w >> 2) << 5;
    u32 p_aoff[2], p_a7[2];
#pragma unroll
    for (int mt2 = 0; mt2 < 2; mt2++) {
        int r = Wm2 + mt2 * 16 + (lane & 15);
        p_aoff[mt2] = (u32)(r << 8);
        p_a7[mt2] = (u32)(r & 7);
    }
    u32 p_cA = (u32)(lane >> 4);
    int vj = lane >> 3;
    int v_rbase = ((vj & 1) << 3) + (lane & 7);
    u32 v_cb = (u32)(Wd >> 3) + (u32)(vj >> 1);

    if (tid < 128) { smM[tid] = -1e30f; smL[tid] = 0.f; }

    copy_tile_c(sb + AQH, qhp, tid);
    copy_tile_c(sb + AQL, qlp, tid);
    copy_tile_c(sb + AKB0, kp, tid);
    CP_COMMIT();

    float acc2[2][4][4] = {};

    for (int j = 0; j <= qi; j++) {
        int kb = j & 1;
        CP_WAIT0();
        __syncthreads();

        copy_tile_c(sb + AVH, vhp + ((size_t)j << 7) * Dd, tid);
        copy_tile_c(sb + AVL, vlp + ((size_t)j << 7) * Dd, tid);
        CP_COMMIT();

        float sacc[4][4][4] = {};
        gemm_chunk2A(sb + AQH, sb + AQL, sb + (kb ? AKB1 : AKB0),
                     aoff, a7, cA, boff, b7, cB, sacc);

        if (j < qi) {
            copy_tile_c(sb + (kb ? AKB0 : AKB1), kp + ((size_t)(j + 1) << 7) * Dd, tid);
            CP_COMMIT();
        }

        if (j == qi) {
#pragma unroll
            for (int mt = 0; mt < 4; mt++)
#pragma unroll
                for (int nt = 0; nt < 4; nt++)
#pragma unroll
                    for (int rg = 0; rg < 4; rg++) {
                        int r = Wm + mt * 16 + (lane >> 2) + ((rg >> 1) << 3);
                        int c = Wn + nt * 8 + ((lane & 3) << 1) + (rg & 1);
                        if (c > r) sacc[mt][nt][rg] = -1e30f;
                    }
        }

#pragma unroll
        for (int mt = 0; mt < 4; mt++) {
#pragma unroll
            for (int rh = 0; rh < 2; rh++) {
                float mx = sacc[mt][0][rh * 2];
#pragma unroll
                for (int nt = 0; nt < 4; nt++) {
                    mx = fmaxf(mx, sacc[mt][nt][rh * 2]);
                    mx = fmaxf(mx, sacc[mt][nt][rh * 2 + 1]);
                }
                mx = fmaxf(mx, __shfl_xor_sync(0xffffffffu, mx, 1));
                mx = fmaxf(mx, __shfl_xor_sync(0xffffffffu, mx, 2));
                if ((lane & 3) == 0)
                    smPM[wn * 128 + Wm + mt * 16 + (lane >> 2) + rh * 8] = mx;
            }
        }
        __syncthreads();

        if (tid < 128) {
            float old = smM[tid];
            float mn = fmaxf(fmaxf(smPM[tid], smPM[128 + tid]),
                             fmaxf(smPM[256 + tid], smPM[384 + tid]));
            mn = fmaxf(mn, old);
            smSC[tid] = ex2f((old - mn) * L2E);
            smM[tid] = mn;
        }
        __syncthreads();

#pragma unroll
        for (int mt = 0; mt < 4; mt++) {
#pragma unroll
            for (int rh = 0; rh < 2; rh++) {
                int r = Wm + mt * 16 + (lane >> 2) + rh * 8;
                float mnl = smM[r] * L2E;
                float rowsum = 0.f;
#pragma unroll
                for (int nt = 0; nt < 4; nt++) {
                    float p0 = ex2f(fmaf(sacc[mt][nt][rh * 2], L2E, -mnl));
                    float p1 = ex2f(fmaf(sacc[mt][nt][rh * 2 + 1], L2E, -mnl));
                    rowsum += p0 + p1;
                    u32 ch = ((u32)((Wn >> 3) + nt) ^ (u32)(r & 7)) << 4;
                    u32 off = (u32)(r << 8) + ch + ((u32)(lane & 3) << 2);
                    *(u32*)(smraw + APH + off) =
                        pack_f16(__float2half_rn(p0), __float2half_rn(p1));
                }
                rowsum += __shfl_xor_sync(0xffffffffu, rowsum, 1);
                rowsum += __shfl_xor_sync(0xffffffffu, rowsum, 2);
                if ((lane & 3) == 0) smPS[wn * 128 + r] = rowsum;
            }
        }
        if (j < qi) { CP_WAIT1(); } else { CP_WAIT0(); }
        __syncthreads();

        if (tid < 128) {
            smL[tid] = smL[tid] * smSC[tid] +
                       (smPS[tid] + smPS[128 + tid] + smPS[256 + tid] + smPS[384 + tid]);
        }

#pragma unroll
        for (int mt2 = 0; mt2 < 2; mt2++) {
            float sc0 = smSC[Wm2 + mt2 * 16 + (lane >> 2)];
            float sc1 = smSC[Wm2 + mt2 * 16 + (lane >> 2) + 8];
#pragma unroll
            for (int nt = 0; nt < 4; nt++) {
                acc2[mt2][nt][0] *= sc0;
                acc2[mt2][nt][1] *= sc0;
                acc2[mt2][nt][2] *= sc1;
                acc2[mt2][nt][3] *= sc1;
            }
        }

#pragma unroll
        for (int s = 0; s < 8; s++) {
            u32 p_[2][4];
#pragma unroll
            for (int mt2 = 0; mt2 < 2; mt2++) {
                u32 ch = (((2 * (u32)s + p_cA) ^ p_a7[mt2]) << 4);
                ldsm4(sb + APH + p_aoff[mt2] + ch,
                      p_[mt2][0], p_[mt2][1], p_[mt2][2], p_[mt2][3]);
            }
            int vrow = (s << 4) + v_rbase;
            u32 vro = (u32)(vrow << 7);
            u32 v7 = (u32)(vrow & 7);
            u32 vh_[2][4], vl_[2][4];
#pragma unroll
            for (int g = 0; g < 2; g++) {
                u32 ch = (((v_cb + 2u * g) ^ v7) << 4);
                ldsm4t(sb + AVH + vro + ch, vh_[g][0], vh_[g][1], vh_[g][2], vh_[g][3]);
                ldsm4t(sb + AVL + vro + ch, vl_[g][0], vl_[g][1], vl_[g][2], vl_[g][3]);
            }
#pragma unroll
            for (int mt2 = 0; mt2 < 2; mt2++) {
#pragma unroll
                for (int nt = 0; nt < 4; nt++) {
                    int g = nt >> 1, su = (nt & 1) << 1;
                    mma16816(acc2[mt2][nt], p_[mt2][0], p_[mt2][1], p_[mt2][2], p_[mt2][3],
                             vh_[g][su], vh_[g][su + 1]);
                    mma16816(acc2[mt2][nt], p_[mt2][0], p_[mt2][1], p_[mt2][2], p_[mt2][3],
                             vl_[g][su], vl_[g][su + 1]);
                }
            }
        }
    }

    __syncthreads();
    int b = bh >> 4, h = bh & 15;
#pragma unroll
    for (int mt2 = 0; mt2 < 2; mt2++) {
#pragma unroll
        for (int rh = 0; rh < 2; rh++) {
            int r = Wm2 + mt2 * 16 + (lane >> 2) + rh * 8;
            float inv = 1.0f / smL[r];
            int t = (qi << 7) + r;
            size_t rowbase = ((size_t)(b * Tt + t)) * (Hh * Dd) + h * Dd;
#pragma unroll
            for (int nt = 0; nt < 4; nt++) {
                int d = Wd + nt * 8 + ((lane & 3) << 1);
                float v0 = acc2[mt2][nt][rh * 2] * inv;
                float v1 = acc2[mt2][nt][rh * 2 + 1] * inv;
                *(u32*)(g_a + rowbase + d) =
                    pack_f16(__float2half_rn(v0), __float2half_rn(v1));
            }
        }
    }
}

// ---------------------------------------------------------------------------
extern "C" void kernel_launch(void* const* d_in, const int* in_sizes, int n_in,
                              void* d_out, int out_size) {
    const float* x  = (const float*)d_in[0];
    const float* Wq = (const float*)d_in[1];
    const float* Wk = (const float*)d_in[2];
    const float* Wv = (const float*)d_in[3];
    const float* Wo = (const float*)d_in[4];
    float* out = (float*)d_out;

    cudaFuncSetAttribute(qkv_mma, cudaFuncAttributeMaxDynamicSharedMemorySize, G1_SMEM);
    cudaFuncSetAttribute(out_mma, cudaFuncAttributeMaxDynamicSharedMemorySize, G1_SMEM);
    cudaFuncSetAttribute(attn_mma, cudaFuncAttributeMaxDynamicSharedMemorySize, ATTN_SMEM);

    conv_x<<<8192, 256>>>(x);
    prep_wqkv<<<dim3(2, 32, 48), 256>>>(Wq, Wk, Wv);
    prep_wo<<<dim3(32, 32), 256>>>(Wo);
    qkv_mma<<<dim3(24, 64), 256, G1_SMEM>>>();
    attn_mma<<<dim3(Tt / 128, Bb * Hh), 256, ATTN_SMEM>>>();
    out_mma<<<dim3(8, 64), 256, G1_SMEM>>>(out);
}

// round 10
// speedup vs baseline: 7.6217x; 1.2093x over previous
#include <cuda_runtime.h>
#include <cuda_fp16.h>

#define Bb 4
#define Tt 2048
#define Ee 1024
#define Hh 16
#define Dd 64
#define MT (Bb * Tt)   // 8192 rows

typedef unsigned long long ull;
typedef unsigned int u32;

// ---------------- device scratch (allocation-free rule) ----------------
__device__ __align__(16) __half g_x[(size_t)MT * Ee];               // x single fp16
__device__ __align__(16) __half g_wt[(size_t)3 * Hh * Dd * Ee];     // [mat][h*64+d][e], Wq pre-scaled 1/8
__device__ __align__(16) __half g_wot[(size_t)Ee * Ee];             // [n][e] single fp16
__device__ __align__(16) __half g_a[(size_t)MT * Ee];               // attn out, single fp16
// layout [bh][t][d], all single fp16
__device__ __align__(16) __half g_q[(size_t)Bb * Hh * Tt * Dd];
__device__ __align__(16) __half g_k[(size_t)Bb * Hh * Tt * Dd];
__device__ __align__(16) __half g_v[(size_t)Bb * Hh * Tt * Dd];

// ---------------- PTX helpers ----------------
__device__ __forceinline__ u32 smem_u32(const void* p) {
    u32 a;
    asm("{ .reg .u64 t; cvta.to.shared.u64 t, %1; cvt.u32.u64 %0, t; }"
        : "=r"(a) : "l"(p));
    return a;
}
__device__ __forceinline__ void cpa16(u32 dst, const void* src) {
    asm volatile("cp.async.cg.shared.global [%0], [%1], 16;"
                 :: "r"(dst), "l"(src) : "memory");
}
#define CP_COMMIT() asm volatile("cp.async.commit_group;" ::: "memory")
#define CP_WAIT1()  asm volatile("cp.async.wait_group 1;" ::: "memory")
#define CP_WAIT0()  asm volatile("cp.async.wait_group 0;" ::: "memory")

__device__ __forceinline__ void ldsm4(u32 addr, u32& r0, u32& r1, u32& r2, u32& r3) {
    asm volatile("ldmatrix.sync.aligned.m8n8.x4.shared.b16 {%0,%1,%2,%3}, [%4];"
                 : "=r"(r0), "=r"(r1), "=r"(r2), "=r"(r3) : "r"(addr));
}
__device__ __forceinline__ void ldsm4t(u32 addr, u32& r0, u32& r1, u32& r2, u32& r3) {
    asm volatile("ldmatrix.sync.aligned.m8n8.x4.trans.shared.b16 {%0,%1,%2,%3}, [%4];"
                 : "=r"(r0), "=r"(r1), "=r"(r2), "=r"(r3) : "r"(addr));
}
__device__ __forceinline__ void mma16816(float* d, u32 a0, u32 a1, u32 a2, u32 a3,
                                         u32 b0, u32 b1) {
    asm volatile(
        "mma.sync.aligned.m16n8k16.row.col.f32.f16.f16.f32 "
        "{%0,%1,%2,%3},{%4,%5,%6,%7},{%8,%9},{%0,%1,%2,%3};"
        : "+f"(d[0]), "+f"(d[1]), "+f"(d[2]), "+f"(d[3])
        : "r"(a0), "r"(a1), "r"(a2), "r"(a3), "r"(b0), "r"(b1));
}
__device__ __forceinline__ float ex2f(float x) {
    float r; asm("ex2.approx.f32 %0,%1;" : "=f"(r) : "f"(x)); return r;
}
__device__ __forceinline__ u32 pack_f16(__half a, __half b) {
    __half2 t = __halves2half2(a, b);
    return *(u32*)&t;
}

#define L2E 1.4426950408889634f

// ---------------------------------------------------------------------------
// Prep kernels
// ---------------------------------------------------------------------------
__global__ void __launch_bounds__(256) conv_x(const float* __restrict__ x) {
    size_t i = ((size_t)blockIdx.x * 256 + threadIdx.x) * 4;
    float4 v = *(const float4*)&x[i];
    *(u32*)(g_x + i) = pack_f16(__float2half_rn(v.x), __float2half_rn(v.y));
    *(u32*)(g_x + i + 2) = pack_f16(__float2half_rn(v.z), __float2half_rn(v.w));
}

__global__ void __launch_bounds__(256) prep_wqkv(
    const float* __restrict__ Wq, const float* __restrict__ Wk,
    const float* __restrict__ Wv)
{
    __shared__ float tile[32][33];
    int z = blockIdx.z;
    int mat = z >> 4, h = z & 15;
    const float* W = (mat == 0 ? Wq : (mat == 1 ? Wk : Wv)) + (size_t)h * Ee * Dd;
    float scale = (mat == 0) ? 0.125f : 1.0f;   // fold D^-1/2 into Wq
    __half* dst = g_wt + ((size_t)mat * Hh + h) * Dd * Ee;
    int e0 = blockIdx.y << 5, d0 = blockIdx.x << 5;
    int tx = threadIdx.x & 31, ty = threadIdx.x >> 5;
#pragma unroll
    for (int j = 0; j < 4; j++)
        tile[ty + j * 8][tx] = W[(size_t)(e0 + ty + j * 8) * Dd + d0 + tx];
    __syncthreads();
#pragma unroll
    for (int j = 0; j < 4; j++) {
        int rr = ty + j * 8;
        dst[(size_t)(d0 + rr) * Ee + e0 + tx] = __float2half_rn(tile[tx][rr] * scale);
    }
}

__global__ void __launch_bounds__(256) prep_wo(const float* __restrict__ Wo) {
    __shared__ float tile[32][33];
    int n0 = blockIdx.x << 5, e0 = blockIdx.y << 5;
    int tx = threadIdx.x & 31, ty = threadIdx.x >> 5;
#pragma unroll
    for (int j = 0; j < 4; j++)
        tile[ty + j * 8][tx] = Wo[(size_t)(e0 + ty + j * 8) * Ee + n0 + tx];
    __syncthreads();
#pragma unroll
    for (int j = 0; j < 4; j++) {
        int rr = ty + j * 8;
        g_wot[(size_t)(n0 + rr) * Ee + e0 + tx] = __float2half_rn(tile[tx][rr]);
    }
}

// ---------------------------------------------------------------------------
// mma.sync GEMM machinery
// ---------------------------------------------------------------------------
#define TILE_B   16384u
#define G1_BUF   32768u
#define G1_SMEM  (2u * G1_BUF)

__device__ __forceinline__ void copy_tile_async(u32 tb, const __half* sp, int tid) {
#pragma unroll
    for (int it = 0; it < 4; it++) {
        int cid = it * 256 + tid;
        int row = cid >> 3, c = cid & 7;
        u32 dst = tb + (u32)(row << 7) + (u32)(((c ^ (row & 7))) << 4);
        cpa16(dst, sp + (size_t)row * Ee + c * 8);
    }
}
__device__ __forceinline__ void copy_tile_c(u32 tb, const __half* sp, int tid) {
#pragma unroll
    for (int it = 0; it < 4; it++) {
        int cid = it * 256 + tid;
        int row = cid >> 3, c = cid & 7;
        u32 dst = tb + (u32)(row << 7) + (u32)(((c ^ (row & 7))) << 4);
        cpa16(dst, sp + (size_t)cid * 8);
    }
}

__device__ __forceinline__ void frag_setup(int lane, int Wm, int Wn,
                                           u32* aoff, u32* a7, u32& cA,
                                           u32* boff, u32* b7, u32& cB) {
#pragma unroll
    for (int mt = 0; mt < 4; mt++) {
        int r = Wm + mt * 16 + (lane & 15);
        aoff[mt] = (u32)(r << 7);
        a7[mt] = (u32)(r & 7);
    }
#pragma unroll
    for (int np = 0; np < 2; np++) {
        int r = Wn + np * 16 + ((lane >> 4) << 3) + (lane & 7);
        boff[np] = (u32)(r << 7);
        b7[np] = (u32)(r & 7);
    }
    cA = (u32)(lane >> 4);
    cB = (u32)((lane >> 3) & 1);
}

// 1-pass chunk: single A, single B
__device__ __forceinline__ void gemm_chunk1(
    u32 sA, u32 sB,
    const u32* aoff, const u32* a7, u32 cA,
    const u32* boff, const u32* b7, u32 cB,
    float acc[4][4][4])
{
#pragma unroll
    for (int s = 0; s < 4; s++) {
        u32 a_[4][4], b_[2][4];
#pragma unroll
        for (int mt = 0; mt < 4; mt++) {
            u32 ca = (u32)(((2 * s + cA) ^ a7[mt]) << 4);
            ldsm4(sA + aoff[mt] + ca, a_[mt][0], a_[mt][1], a_[mt][2], a_[mt][3]);
        }
#pragma unroll
        for (int np = 0; np < 2; np++) {
            u32 cb = (u32)(((2 * s + cB) ^ b7[np]) << 4);
            ldsm4(sB + boff[np] + cb, b_[np][0], b_[np][1], b_[np][2], b_[np][3]);
        }
#pragma unroll
        for (int mt = 0; mt < 4; mt++) {
#pragma unroll
            for (int nt = 0; nt < 4; nt++) {
                int np = nt >> 1, sel = (nt & 1) << 1;
                mma16816(acc[mt][nt], a_[mt][0], a_[mt][1], a_[mt][2], a_[mt][3],
                         b_[np][sel], b_[np][sel + 1]);
            }
        }
    }
}

// ---------------------------------------------------------------------------
// QKV projection (1-pass, 2 CTA/SM) -> q/k/v single fp16.
// grid (24, 64), block 256, 64KB smem.
// ---------------------------------------------------------------------------
__global__ void __launch_bounds__(256, 2) qkv_mma() {
    extern __shared__ char smraw[];
    u32 sbase = smem_u32(smraw);

    int tid = threadIdx.x;
    int lane = tid & 31, w = tid >> 5;
    int Wm = (w & 1) << 6, Wn = (w >> 1) << 5;

    int n0 = blockIdx.x << 7;
    int m0 = blockIdx.y << 7;
    int mat = n0 >> 10;
    int nb = n0 & 1023;

    const __half* A = g_x + (size_t)m0 * Ee;
    const __half* Bw = g_wt + (size_t)mat * Hh * Dd * Ee + (size_t)nb * Ee;

    u32 aoff[4], a7[4], boff[2], b7[2], cA, cB;
    frag_setup(lane, Wm, Wn, aoff, a7, cA, boff, b7, cB);

    float acc[4][4][4] = {};

    copy_tile_async(sbase + 0 * TILE_B, A, tid);
    copy_tile_async(sbase + 1 * TILE_B, Bw, tid);
    CP_COMMIT();

    for (int c = 0; c < 16; c++) {
        CP_WAIT0();
        __syncthreads();
        if (c < 15) {
            u32 nb_ = sbase + ((u32)(c + 1) & 1u) * G1_BUF;
            int k0 = (c + 1) << 6;
            copy_tile_async(nb_ + 0 * TILE_B, A + k0, tid);
            copy_tile_async(nb_ + 1 * TILE_B, Bw + k0, tid);
            CP_COMMIT();
        }
        u32 sb = sbase + ((u32)c & 1u) * G1_BUF;
        gemm_chunk1(sb, sb + TILE_B, aoff, a7, cA, boff, b7, cB, acc);
    }

    __half* outp = (mat == 0) ? g_q : (mat == 1) ? g_k : g_v;
#pragma unroll
    for (int mt = 0; mt < 4; mt++) {
#pragma unroll
        for (int nt = 0; nt < 4; nt++) {
            int n = nb + Wn + nt * 8 + ((lane & 3) << 1);
            int h = n >> 6, d = n & 63;
            int m = m0 + Wm + mt * 16 + (lane >> 2);
            int b = m >> 11, t = m & 2047;
            size_t base = (((size_t)(b * Hh + h)) * Tt + t) * Dd + d;
            *(u32*)(outp + base) = pack_f16(__float2half_rn(acc[mt][nt][0]),
                                            __float2half_rn(acc[mt][nt][1]));
            *(u32*)(outp + base + 8 * Dd) = pack_f16(__float2half_rn(acc[mt][nt][2]),
                                                     __float2half_rn(acc[mt][nt][3]));
        }
    }
}

// ---------------------------------------------------------------------------
// Out projection (1-pass, 2 CTA/SM): out[8192,1024] = A_f16 * Wo_f16.
// grid (8, 64), block 256.
// ---------------------------------------------------------------------------
__global__ void __launch_bounds__(256, 2) out_mma(float* __restrict__ out) {
    extern __shared__ char smraw[];
    u32 sbase = smem_u32(smraw);

    int tid = threadIdx.x;
    int lane = tid & 31, w = tid >> 5;
    int Wm = (w & 1) << 6, Wn = (w >> 1) << 5;

    int n0 = blockIdx.x << 7;
    int m0 = blockIdx.y << 7;

    const __half* A = g_a + (size_t)m0 * Ee;
    const __half* B = g_wot + (size_t)n0 * Ee;

    u32 aoff[4], a7[4], boff[2], b7[2], cA, cB;
    frag_setup(lane, Wm, Wn, aoff, a7, cA, boff, b7, cB);

    float acc[4][4][4] = {};

    copy_tile_async(sbase + 0 * TILE_B, A, tid);
    copy_tile_async(sbase + 1 * TILE_B, B, tid);
    CP_COMMIT();

    for (int c = 0; c < 16; c++) {
        CP_WAIT0();
        __syncthreads();
        if (c < 15) {
            u32 nb_ = sbase + ((u32)(c + 1) & 1u) * G1_BUF;
            int k0 = (c + 1) << 6;
            copy_tile_async(nb_ + 0 * TILE_B, A + k0, tid);
            copy_tile_async(nb_ + 1 * TILE_B, B + k0, tid);
            CP_COMMIT();
        }
        u32 sb = sbase + ((u32)c & 1u) * G1_BUF;
        gemm_chunk1(sb, sb + TILE_B, aoff, a7, cA, boff, b7, cB, acc);
    }

#pragma unroll
    for (int mt = 0; mt < 4; mt++) {
#pragma unroll
        for (int nt = 0; nt < 4; nt++) {
            int n = n0 + Wn + nt * 8 + ((lane & 3) << 1);
            int m = m0 + Wm + mt * 16 + (lane >> 2);
            *(float2*)&out[(size_t)m * Ee + n] = make_float2(acc[mt][nt][0], acc[mt][nt][1]);
            *(float2*)&out[(size_t)(m + 8) * Ee + n] = make_float2(acc[mt][nt][2], acc[mt][nt][3]);
        }
    }
}

// ---------------------------------------------------------------------------
// Tensor-core causal flash attention. S: 1-pass; PV: 1-pass.
// grid (16 reversed, 64), block 256, ~102KB dynamic smem.
// ---------------------------------------------------------------------------
#define AQ   0u
#define AKB0 16384u
#define AKB1 32768u
#define AV   49152u
#define AP   65536u
#define ASMM 98304u
#define ASML 98816u
#define ASSC 99328u
#define APM  99840u
#define APS  101888u
#define ATTN_SMEM 103936u

__global__ void __launch_bounds__(256, 1) attn_mma() {
    extern __shared__ char smraw[];
    u32 sb = smem_u32(smraw);
    float* smM = (float*)(smraw + ASMM);
    float* smL = (float*)(smraw + ASML);
    float* smSC = (float*)(smraw + ASSC);
    float* smPM = (float*)(smraw + APM);
    float* smPS = (float*)(smraw + APS);

    int tid = threadIdx.x, lane = tid & 31, w = tid >> 5;
    int qi = (int)gridDim.x - 1 - (int)blockIdx.x;
    int bh = blockIdx.y;
    size_t tbase = (size_t)bh * Tt * Dd;
    const __half* qp = g_q + tbase + ((size_t)qi << 7) * Dd;
    const __half* kp = g_k + tbase;
    const __half* vp = g_v + tbase;

    int Wm = (w & 1) << 6, Wn = (w >> 1) << 5;
    u32 aoff[4], a7[4], boff[2], b7[2], cA, cB;
    frag_setup(lane, Wm, Wn, aoff, a7, cA, boff, b7, cB);
    int wn = w >> 1;

    int Wm2 = (w & 3) << 5, Wd = (w >> 2) << 5;
    u32 p_aoff[2], p_a7[2];
#pragma unroll
    for (int mt2 = 0; mt2 < 2; mt2++) {
        int r = Wm2 + mt2 * 16 + (lane & 15);
        p_aoff[mt2] = (u32)(r << 8);    // P rows are 256B (128 fp16)
        p_a7[mt2] = (u32)(r & 7);
    }
    u32 p_cA = (u32)(lane >> 4);
    int vj = lane >> 3;
    int v_rbase = ((vj & 1) << 3) + (lane & 7);
    u32 v_cb = (u32)(Wd >> 3) + (u32)(vj >> 1);

    if (tid < 128) { smM[tid] = -1e30f; smL[tid] = 0.f; }

    copy_tile_c(sb + AQ, qp, tid);
    copy_tile_c(sb + AKB0, kp, tid);
    CP_COMMIT();

    float acc2[2][4][4] = {};

    for (int j = 0; j <= qi; j++) {
        int kb = j & 1;
        CP_WAIT0();
        __syncthreads();

        copy_tile_c(sb + AV, vp + ((size_t)j << 7) * Dd, tid);
        CP_COMMIT();

        // ---- S = Q . K^T (1-pass)
        float sacc[4][4][4] = {};
        gemm_chunk1(sb + AQ, sb + (kb ? AKB1 : AKB0),
                    aoff, a7, cA, boff, b7, cB, sacc);

        if (j < qi) {
            copy_tile_c(sb + (kb ? AKB0 : AKB1), kp + ((size_t)(j + 1) << 7) * Dd, tid);
            CP_COMMIT();
        }

        if (j == qi) {
#pragma unroll
            for (int mt = 0; mt < 4; mt++)
#pragma unroll
                for (int nt = 0; nt < 4; nt++)
#pragma unroll
                    for (int rg = 0; rg < 4; rg++) {
                        int r = Wm + mt * 16 + (lane >> 2) + ((rg >> 1) << 3);
                        int c = Wn + nt * 8 + ((lane & 3) << 1) + (rg & 1);
                        if (c > r) sacc[mt][nt][rg] = -1e30f;
                    }
        }

        // ---- softmax: per-warp partial row max
#pragma unroll
        for (int mt = 0; mt < 4; mt++) {
#pragma unroll
            for (int rh = 0; rh < 2; rh++) {
                float mx = sacc[mt][0][rh * 2];
#pragma unroll
                for (int nt = 0; nt < 4; nt++) {
                    mx = fmaxf(mx, sacc[mt][nt][rh * 2]);
                    mx = fmaxf(mx, sacc[mt][nt][rh * 2 + 1]);
                }
                mx = fmaxf(mx, __shfl_xor_sync(0xffffffffu, mx, 1));
                mx = fmaxf(mx, __shfl_xor_sync(0xffffffffu, mx, 2));
                if ((lane & 3) == 0)
                    smPM[wn * 128 + Wm + mt * 16 + (lane >> 2) + rh * 8] = mx;
            }
        }
        __syncthreads();

        if (tid < 128) {
            float old = smM[tid];
            float mn = fmaxf(fmaxf(smPM[tid], smPM[128 + tid]),
                             fmaxf(smPM[256 + tid], smPM[384 + tid]));
            mn = fmaxf(mn, old);
            smSC[tid] = ex2f((old - mn) * L2E);
            smM[tid] = mn;
        }
        __syncthreads();

        // ---- exp, single-fp16 P store, partial row sums
#pragma unroll
        for (int mt = 0; mt < 4; mt++) {
#pragma unroll
            for (int rh = 0; rh < 2; rh++) {
                int r = Wm + mt * 16 + (lane >> 2) + rh * 8;
                float mnl = smM[r] * L2E;
                float rowsum = 0.f;
#pragma unroll
                for (int nt = 0; nt < 4; nt++) {
                    float p0 = ex2f(fmaf(sacc[mt][nt][rh * 2], L2E, -mnl));
                    float p1 = ex2f(fmaf(sacc[mt][nt][rh * 2 + 1], L2E, -mnl));
                    rowsum += p0 + p1;
                    u32 ch = ((u32)((Wn >> 3) + nt) ^ (u32)(r & 7)) << 4;
                    u32 off = (u32)(r << 8) + ch + ((u32)(lane & 3) << 2);
                    *(u32*)(smraw + AP + off) =
                        pack_f16(__float2half_rn(p0), __float2half_rn(p1));
                }
                rowsum += __shfl_xor_sync(0xffffffffu, rowsum, 1);
                rowsum += __shfl_xor_sync(0xffffffffu, rowsum, 2);
                if ((lane & 3) == 0) smPS[wn * 128 + r] = rowsum;
            }
        }
        if (j < qi) { CP_WAIT1(); } else { CP_WAIT0(); }  // V(j) done
        __syncthreads();

        if (tid < 128) {
            smL[tid] = smL[tid] * smSC[tid] +
                       (smPS[tid] + smPS[128 + tid] + smPS[256 + tid] + smPS[384 + tid]);
        }

        // ---- rescale O
#pragma unroll
        for (int mt2 = 0; mt2 < 2; mt2++) {
            float sc0 = smSC[Wm2 + mt2 * 16 + (lane >> 2)];
            float sc1 = smSC[Wm2 + mt2 * 16 + (lane >> 2) + 8];
#pragma unroll
            for (int nt = 0; nt < 4; nt++) {
                acc2[mt2][nt][0] *= sc0;
                acc2[mt2][nt][1] *= sc0;
                acc2[mt2][nt][2] *= sc1;
                acc2[mt2][nt][3] *= sc1;
            }
        }

        // ---- O += P . V (1-pass: P single, V single)
#pragma unroll
        for (int s = 0; s < 8; s++) {
            u32 p_[2][4];
#pragma unroll
            for (int mt2 = 0; mt2 < 2; mt2++) {
                u32 ch = (((2 * (u32)s + p_cA) ^ p_a7[mt2]) << 4);
                ldsm4(sb + AP + p_aoff[mt2] + ch,
                      p_[mt2][0], p_[mt2][1], p_[mt2][2], p_[mt2][3]);
            }
            int vrow = (s << 4) + v_rbase;
            u32 vro = (u32)(vrow << 7);
            u32 v7 = (u32)(vrow & 7);
            u32 v_[2][4];
#pragma unroll
            for (int g = 0; g < 2; g++) {
                u32 ch = (((v_cb + 2u * g) ^ v7) << 4);
                ldsm4t(sb + AV + vro + ch, v_[g][0], v_[g][1], v_[g][2], v_[g][3]);
            }
#pragma unroll
            for (int mt2 = 0; mt2 < 2; mt2++) {
#pragma unroll
                for (int nt = 0; nt < 4; nt++) {
                    int g = nt >> 1, su = (nt & 1) << 1;
                    mma16816(acc2[mt2][nt], p_[mt2][0], p_[mt2][1], p_[mt2][2], p_[mt2][3],
                             v_[g][su], v_[g][su + 1]);
                }
            }
        }
    }

    // ---- epilogue: normalize, single fp16 write [B*T, H*D]
    __syncthreads();
    int b = bh >> 4, h = bh & 15;
#pragma unroll
    for (int mt2 = 0; mt2 < 2; mt2++) {
#pragma unroll
        for (int rh = 0; rh < 2; rh++) {
            int r = Wm2 + mt2 * 16 + (lane >> 2) + rh * 8;
            float inv = 1.0f / smL[r];
            int t = (qi << 7) + r;
            size_t rowbase = ((size_t)(b * Tt + t)) * (Hh * Dd) + h * Dd;
#pragma unroll
            for (int nt = 0; nt < 4; nt++) {
                int d = Wd + nt * 8 + ((lane & 3) << 1);
                float v0 = acc2[mt2][nt][rh * 2] * inv;
                float v1 = acc2[mt2][nt][rh * 2 + 1] * inv;
                *(u32*)(g_a + rowbase + d) =
                    pack_f16(__float2half_rn(v0), __float2half_rn(v1));
            }
        }
    }
}

// ---------------------------------------------------------------------------
extern "C" void kernel_launch(void* const* d_in, const int* in_sizes, int n_in,
                              void* d_out, int out_size) {
    const float* x  = (const float*)d_in[0];
    const float* Wq = (const float*)d_in[1];
    const float* Wk = (const float*)d_in[2];
    const float* Wv = (const float*)d_in[3];
    const float* Wo = (const float*)d_in[4];
    float* out = (float*)d_out;

    cudaFuncSetAttribute(qkv_mma, cudaFuncAttributeMaxDynamicSharedMemorySize, G1_SMEM);
    cudaFuncSetAttribute(out_mma, cudaFuncAttributeMaxDynamicSharedMemorySize, G1_SMEM);
    cudaFuncSetAttribute(attn_mma, cudaFuncAttributeMaxDynamicSharedMemorySize, ATTN_SMEM);

    conv_x<<<8192, 256>>>(x);
    prep_wqkv<<<dim3(2, 32, 48), 256>>>(Wq, Wk, Wv);
    prep_wo<<<dim3(32, 32), 256>>>(Wo);
    qkv_mma<<<dim3(24, 64), 256, G1_SMEM>>>();
    attn_mma<<<dim3(Tt / 128, Bb * Hh), 256, ATTN_SMEM>>>();
    out_mma<<<dim3(8, 64), 256, G1_SMEM>>>(out);
}

// round 11
// speedup vs baseline: 8.7593x; 1.1493x over previous
#include <cuda_runtime.h>
#include <cuda_fp16.h>

#define Bb 4
#define Tt 2048
#define Ee 1024
#define Hh 16
#define Dd 64
#define MT (Bb * Tt)   // 8192 rows

typedef unsigned long long ull;
typedef unsigned int u32;

// ---------------- device scratch (allocation-free rule) ----------------
__device__ __align__(16) __half g_x[(size_t)MT * Ee];               // x single fp16
__device__ __align__(16) __half g_wt[(size_t)3 * Hh * Dd * Ee];     // [mat][h*64+d][e], Wq pre-scaled 1/8
__device__ __align__(16) __half g_wot[(size_t)Ee * Ee];             // [n][e] single fp16
__device__ __align__(16) __half g_a[(size_t)MT * Ee];               // attn out, single fp16
// layout [bh][t][d], all single fp16
__device__ __align__(16) __half g_q[(size_t)Bb * Hh * Tt * Dd];
__device__ __align__(16) __half g_k[(size_t)Bb * Hh * Tt * Dd];
__device__ __align__(16) __half g_v[(size_t)Bb * Hh * Tt * Dd];

// ---------------- PTX helpers ----------------
__device__ __forceinline__ u32 smem_u32(const void* p) {
    u32 a;
    asm("{ .reg .u64 t; cvta.to.shared.u64 t, %1; cvt.u32.u64 %0, t; }"
        : "=r"(a) : "l"(p));
    return a;
}
__device__ __forceinline__ void cpa16(u32 dst, const void* src) {
    asm volatile("cp.async.cg.shared.global [%0], [%1], 16;"
                 :: "r"(dst), "l"(src) : "memory");
}
#define CP_COMMIT() asm volatile("cp.async.commit_group;" ::: "memory")
#define CP_WAIT1()  asm volatile("cp.async.wait_group 1;" ::: "memory")
#define CP_WAIT0()  asm volatile("cp.async.wait_group 0;" ::: "memory")

__device__ __forceinline__ void ldsm4(u32 addr, u32& r0, u32& r1, u32& r2, u32& r3) {
    asm volatile("ldmatrix.sync.aligned.m8n8.x4.shared.b16 {%0,%1,%2,%3}, [%4];"
                 : "=r"(r0), "=r"(r1), "=r"(r2), "=r"(r3) : "r"(addr));
}
__device__ __forceinline__ void ldsm4t(u32 addr, u32& r0, u32& r1, u32& r2, u32& r3) {
    asm volatile("ldmatrix.sync.aligned.m8n8.x4.trans.shared.b16 {%0,%1,%2,%3}, [%4];"
                 : "=r"(r0), "=r"(r1), "=r"(r2), "=r"(r3) : "r"(addr));
}
__device__ __forceinline__ void mma16816(float* d, u32 a0, u32 a1, u32 a2, u32 a3,
                                         u32 b0, u32 b1) {
    asm volatile(
        "mma.sync.aligned.m16n8k16.row.col.f32.f16.f16.f32 "
        "{%0,%1,%2,%3},{%4,%5,%6,%7},{%8,%9},{%0,%1,%2,%3};"
        : "+f"(d[0]), "+f"(d[1]), "+f"(d[2]), "+f"(d[3])
        : "r"(a0), "r"(a1), "r"(a2), "r"(a3), "r"(b0), "r"(b1));
}
__device__ __forceinline__ float ex2f(float x) {
    float r; asm("ex2.approx.f32 %0,%1;" : "=f"(r) : "f"(x)); return r;
}
__device__ __forceinline__ u32 pack_f16(__half a, __half b) {
    __half2 t = __halves2half2(a, b);
    return *(u32*)&t;
}

#define L2E 1.4426950408889634f

// ---------------------------------------------------------------------------
// Prep kernels
// ---------------------------------------------------------------------------
__global__ void __launch_bounds__(256) conv_x(const float* __restrict__ x) {
    size_t i = ((size_t)blockIdx.x * 256 + threadIdx.x) * 4;
    float4 v = *(const float4*)&x[i];
    *(u32*)(g_x + i) = pack_f16(__float2half_rn(v.x), __float2half_rn(v.y));
    *(u32*)(g_x + i + 2) = pack_f16(__float2half_rn(v.z), __float2half_rn(v.w));
}

__global__ void __launch_bounds__(256) prep_wqkv(
    const float* __restrict__ Wq, const float* __restrict__ Wk,
    const float* __restrict__ Wv)
{
    __shared__ float tile[32][33];
    int z = blockIdx.z;
    int mat = z >> 4, h = z & 15;
    const float* W = (mat == 0 ? Wq : (mat == 1 ? Wk : Wv)) + (size_t)h * Ee * Dd;
    float scale = (mat == 0) ? 0.125f : 1.0f;   // fold D^-1/2 into Wq
    __half* dst = g_wt + ((size_t)mat * Hh + h) * Dd * Ee;
    int e0 = blockIdx.y << 5, d0 = blockIdx.x << 5;
    int tx = threadIdx.x & 31, ty = threadIdx.x >> 5;
#pragma unroll
    for (int j = 0; j < 4; j++)
        tile[ty + j * 8][tx] = W[(size_t)(e0 + ty + j * 8) * Dd + d0 + tx];
    __syncthreads();
#pragma unroll
    for (int j = 0; j < 4; j++) {
        int rr = ty + j * 8;
        dst[(size_t)(d0 + rr) * Ee + e0 + tx] = __float2half_rn(tile[tx][rr] * scale);
    }
}

__global__ void __launch_bounds__(256) prep_wo(const float* __restrict__ Wo) {
    __shared__ float tile[32][33];
    int n0 = blockIdx.x << 5, e0 = blockIdx.y << 5;
    int tx = threadIdx.x & 31, ty = threadIdx.x >> 5;
#pragma unroll
    for (int j = 0; j < 4; j++)
        tile[ty + j * 8][tx] = Wo[(size_t)(e0 + ty + j * 8) * Ee + n0 + tx];
    __syncthreads();
#pragma unroll
    for (int j = 0; j < 4; j++) {
        int rr = ty + j * 8;
        g_wot[(size_t)(n0 + rr) * Ee + e0 + tx] = __float2half_rn(tile[tx][rr]);
    }
}

// ---------------------------------------------------------------------------
// mma.sync GEMM machinery (3-stage pipelined dense GEMMs)
// ---------------------------------------------------------------------------
#define TILE_B   16384u
#define G1_BUF   32768u
#define G1_SMEM  (3u * G1_BUF)   // 96KB, 2 CTA/SM

__device__ __forceinline__ void copy_tile_async(u32 tb, const __half* sp, int tid) {
#pragma unroll
    for (int it = 0; it < 4; it++) {
        int cid = it * 256 + tid;
        int row = cid >> 3, c = cid & 7;
        u32 dst = tb + (u32)(row << 7) + (u32)(((c ^ (row & 7))) << 4);
        cpa16(dst, sp + (size_t)row * Ee + c * 8);
    }
}
__device__ __forceinline__ void copy_tile_c(u32 tb, const __half* sp, int tid) {
#pragma unroll
    for (int it = 0; it < 4; it++) {
        int cid = it * 256 + tid;
        int row = cid >> 3, c = cid & 7;
        u32 dst = tb + (u32)(row << 7) + (u32)(((c ^ (row & 7))) << 4);
        cpa16(dst, sp + (size_t)cid * 8);
    }
}

__device__ __forceinline__ void frag_setup(int lane, int Wm, int Wn,
                                           u32* aoff, u32* a7, u32& cA,
                                           u32* boff, u32* b7, u32& cB) {
#pragma unroll
    for (int mt = 0; mt < 4; mt++) {
        int r = Wm + mt * 16 + (lane & 15);
        aoff[mt] = (u32)(r << 7);
        a7[mt] = (u32)(r & 7);
    }
#pragma unroll
    for (int np = 0; np < 2; np++) {
        int r = Wn + np * 16 + ((lane >> 4) << 3) + (lane & 7);
        boff[np] = (u32)(r << 7);
        b7[np] = (u32)(r & 7);
    }
    cA = (u32)(lane >> 4);
    cB = (u32)((lane >> 3) & 1);
}

// 1-pass chunk: single A, single B
__device__ __forceinline__ void gemm_chunk1(
    u32 sA, u32 sB,
    const u32* aoff, const u32* a7, u32 cA,
    const u32* boff, const u32* b7, u32 cB,
    float acc[4][4][4])
{
#pragma unroll
    for (int s = 0; s < 4; s++) {
        u32 a_[4][4], b_[2][4];
#pragma unroll
        for (int mt = 0; mt < 4; mt++) {
            u32 ca = (u32)(((2 * s + cA) ^ a7[mt]) << 4);
            ldsm4(sA + aoff[mt] + ca, a_[mt][0], a_[mt][1], a_[mt][2], a_[mt][3]);
        }
#pragma unroll
        for (int np = 0; np < 2; np++) {
            u32 cb = (u32)(((2 * s + cB) ^ b7[np]) << 4);
            ldsm4(sB + boff[np] + cb, b_[np][0], b_[np][1], b_[np][2], b_[np][3]);
        }
#pragma unroll
        for (int mt = 0; mt < 4; mt++) {
#pragma unroll
            for (int nt = 0; nt < 4; nt++) {
                int np = nt >> 1, sel = (nt & 1) << 1;
                mma16816(acc[mt][nt], a_[mt][0], a_[mt][1], a_[mt][2], a_[mt][3],
                         b_[np][sel], b_[np][sel + 1]);
            }
        }
    }
}

// ---------------------------------------------------------------------------
// QKV projection (1-pass, 3-stage, 2 CTA/SM) -> q/k/v single fp16.
// grid (24, 64), block 256, 96KB smem.
// ---------------------------------------------------------------------------
__global__ void __launch_bounds__(256, 2) qkv_mma() {
    extern __shared__ char smraw[];
    u32 sbase = smem_u32(smraw);

    int tid = threadIdx.x;
    int lane = tid & 31, w = tid >> 5;
    int Wm = (w & 1) << 6, Wn = (w >> 1) << 5;

    int n0 = blockIdx.x << 7;
    int m0 = blockIdx.y << 7;
    int mat = n0 >> 10;
    int nb = n0 & 1023;

    const __half* A = g_x + (size_t)m0 * Ee;
    const __half* Bw = g_wt + (size_t)mat * Hh * Dd * Ee + (size_t)nb * Ee;

    u32 aoff[4], a7[4], boff[2], b7[2], cA, cB;
    frag_setup(lane, Wm, Wn, aoff, a7, cA, boff, b7, cB);

    float acc[4][4][4] = {};

    // prologue: chunks 0,1
#pragma unroll
    for (int c = 0; c < 2; c++) {
        u32 bu = sbase + (u32)c * G1_BUF;
        copy_tile_async(bu, A + (c << 6), tid);
        copy_tile_async(bu + TILE_B, Bw + (c << 6), tid);
        CP_COMMIT();
    }

    for (int c = 0; c < 16; c++) {
        if (c == 15) { CP_WAIT0(); } else { CP_WAIT1(); }
        __syncthreads();
        if (c < 14) {
            u32 bu = sbase + (u32)((c + 2) % 3) * G1_BUF;
            int k0 = (c + 2) << 6;
            copy_tile_async(bu, A + k0, tid);
            copy_tile_async(bu + TILE_B, Bw + k0, tid);
            CP_COMMIT();
        }
        u32 sb = sbase + (u32)(c % 3) * G1_BUF;
        gemm_chunk1(sb, sb + TILE_B, aoff, a7, cA, boff, b7, cB, acc);
    }

    __half* outp = (mat == 0) ? g_q : (mat == 1) ? g_k : g_v;
#pragma unroll
    for (int mt = 0; mt < 4; mt++) {
#pragma unroll
        for (int nt = 0; nt < 4; nt++) {
            int n = nb + Wn + nt * 8 + ((lane & 3) << 1);
            int h = n >> 6, d = n & 63;
            int m = m0 + Wm + mt * 16 + (lane >> 2);
            int b = m >> 11, t = m & 2047;
            size_t base = (((size_t)(b * Hh + h)) * Tt + t) * Dd + d;
            *(u32*)(outp + base) = pack_f16(__float2half_rn(acc[mt][nt][0]),
                                            __float2half_rn(acc[mt][nt][1]));
            *(u32*)(outp + base + 8 * Dd) = pack_f16(__float2half_rn(acc[mt][nt][2]),
                                                     __float2half_rn(acc[mt][nt][3]));
        }
    }
}

// ---------------------------------------------------------------------------
// Out projection (1-pass, 3-stage, 2 CTA/SM): out = A_f16 * Wo_f16.
// grid (8, 64), block 256.
// ---------------------------------------------------------------------------
__global__ void __launch_bounds__(256, 2) out_mma(float* __restrict__ out) {
    extern __shared__ char smraw[];
    u32 sbase = smem_u32(smraw);

    int tid = threadIdx.x;
    int lane = tid & 31, w = tid >> 5;
    int Wm = (w & 1) << 6, Wn = (w >> 1) << 5;

    int n0 = blockIdx.x << 7;
    int m0 = blockIdx.y << 7;

    const __half* A = g_a + (size_t)m0 * Ee;
    const __half* B = g_wot + (size_t)n0 * Ee;

    u32 aoff[4], a7[4], boff[2], b7[2], cA, cB;
    frag_setup(lane, Wm, Wn, aoff, a7, cA, boff, b7, cB);

    float acc[4][4][4] = {};

#pragma unroll
    for (int c = 0; c < 2; c++) {
        u32 bu = sbase + (u32)c * G1_BUF;
        copy_tile_async(bu, A + (c << 6), tid);
        copy_tile_async(bu + TILE_B, B + (c << 6), tid);
        CP_COMMIT();
    }

    for (int c = 0; c < 16; c++) {
        if (c == 15) { CP_WAIT0(); } else { CP_WAIT1(); }
        __syncthreads();
        if (c < 14) {
            u32 bu = sbase + (u32)((c + 2) % 3) * G1_BUF;
            int k0 = (c + 2) << 6;
            copy_tile_async(bu, A + k0, tid);
            copy_tile_async(bu + TILE_B, B + k0, tid);
            CP_COMMIT();
        }
        u32 sb = sbase + (u32)(c % 3) * G1_BUF;
        gemm_chunk1(sb, sb + TILE_B, aoff, a7, cA, boff, b7, cB, acc);
    }

#pragma unroll
    for (int mt = 0; mt < 4; mt++) {
#pragma unroll
        for (int nt = 0; nt < 4; nt++) {
            int n = n0 + Wn + nt * 8 + ((lane & 3) << 1);
            int m = m0 + Wm + mt * 16 + (lane >> 2);
            *(float2*)&out[(size_t)m * Ee + n] = make_float2(acc[mt][nt][0], acc[mt][nt][1]);
            *(float2*)&out[(size_t)(m + 8) * Ee + n] = make_float2(acc[mt][nt][2], acc[mt][nt][3]);
        }
    }
}

// ---------------------------------------------------------------------------
// FA2-style tensor-core causal flash attention.
// Warp owns 16 query rows: in-warp softmax, P stays in registers.
// grid (16 reversed, 64), block 256, 80KB dynamic smem. 1 sync per j-tile.
// ---------------------------------------------------------------------------
#define AQ  0u
#define AK0 16384u
#define AK1 32768u
#define AV0 49152u
#define AV1 65536u
#define ATTN_SMEM 81920u

__global__ void __launch_bounds__(256, 1) attn_mma() {
    extern __shared__ char smraw[];
    u32 sb = smem_u32(smraw);

    int tid = threadIdx.x, lane = tid & 31, w = tid >> 5;
    int qi = (int)gridDim.x - 1 - (int)blockIdx.x;
    int bh = blockIdx.y;
    size_t tbase = (size_t)bh * Tt * Dd;
    const __half* qp = g_q + tbase + ((size_t)qi << 7) * Dd;
    const __half* kp = g_k + tbase;
    const __half* vp = g_v + tbase;

    int Wm = w << 4;   // warp owns q rows [Wm, Wm+16)

    // S A-frag (Q rows)
    int ar = Wm + (lane & 15);
    u32 aoff = (u32)(ar << 7), a7 = (u32)(ar & 7);
    u32 cA = (u32)(lane >> 4);
    // S B-frags (K rows 0..127, 8 groups of n16)
    u32 boff[8], b7[8];
#pragma unroll
    for (int np = 0; np < 8; np++) {
        int r = np * 16 + ((lane >> 4) << 3) + (lane & 7);
        boff[np] = (u32)(r << 7);
        b7[np] = (u32)(r & 7);
    }
    u32 cB = (u32)((lane >> 3) & 1);
    // PV V-frags (ldsm4t)
    int vj = lane >> 3;
    int v_rbase = ((vj & 1) << 3) + (lane & 7);
    u32 v_cb = (u32)(vj >> 1);

    float m_[2] = {-1e30f, -1e30f};
    float l_[2] = {0.f, 0.f};
    float acc2[8][4] = {};

    // prologue: Q + K(0) + V(0)
    copy_tile_c(sb + AQ, qp, tid);
    copy_tile_c(sb + AK0, kp, tid);
    copy_tile_c(sb + AV0, vp, tid);
    CP_COMMIT();

    for (int j = 0; j <= qi; j++) {
        int buf = j & 1;
        CP_WAIT0();
        __syncthreads();      // K/V(j) visible; all warps done with j-1 buffers

        if (j < qi) {         // prefetch K/V(j+1) into the other buffers
            copy_tile_c(sb + (buf ? AK0 : AK1), kp + ((size_t)(j + 1) << 7) * Dd, tid);
            copy_tile_c(sb + (buf ? AV0 : AV1), vp + ((size_t)(j + 1) << 7) * Dd, tid);
            CP_COMMIT();
        }
        u32 sK = sb + (buf ? AK1 : AK0);
        u32 sV = sb + (buf ? AV1 : AV0);

        // ---- S = Q . K^T  (warp: m16 x n128)
        float sacc[16][4] = {};
#pragma unroll
        for (int s = 0; s < 4; s++) {
            u32 a0, a1, a2, a3;
            ldsm4(sb + AQ + aoff + (((2 * (u32)s + cA) ^ a7) << 4), a0, a1, a2, a3);
#pragma unroll
            for (int np = 0; np < 8; np++) {
                u32 q0, q1, q2, q3;
                ldsm4(sK + boff[np] + (((2 * (u32)s + cB) ^ b7[np]) << 4), q0, q1, q2, q3);
                mma16816(sacc[2 * np], a0, a1, a2, a3, q0, q1);
                mma16816(sacc[2 * np + 1], a0, a1, a2, a3, q2, q3);
            }
        }

        // ---- causal mask on diagonal tile
        if (j == qi) {
#pragma unroll
            for (int nt = 0; nt < 16; nt++)
#pragma unroll
                for (int rg = 0; rg < 4; rg++) {
                    int r = Wm + (lane >> 2) + ((rg >> 1) << 3);
                    int c = nt * 8 + ((lane & 3) << 1) + (rg & 1);
                    if (c > r) sacc[nt][rg] = -1e30f;
                }
        }

        // ---- in-warp online softmax; P -> fp16 A-fragments in registers
        u32 paf[8][4];
#pragma unroll
        for (int rh = 0; rh < 2; rh++) {
            float mx = -1e30f;
#pragma unroll
            for (int nt = 0; nt < 16; nt++) {
                mx = fmaxf(mx, sacc[nt][rh * 2]);
                mx = fmaxf(mx, sacc[nt][rh * 2 + 1]);
            }
            mx = fmaxf(mx, __shfl_xor_sync(0xffffffffu, mx, 1));
            mx = fmaxf(mx, __shfl_xor_sync(0xffffffffu, mx, 2));
            float mn = fmaxf(m_[rh], mx);
            float sc = ex2f((m_[rh] - mn) * L2E);
            float mnl = mn * L2E;
            float rs = 0.f;
#pragma unroll
            for (int nt = 0; nt < 16; nt++) {
                float p0 = ex2f(fmaf(sacc[nt][rh * 2], L2E, -mnl));
                float p1 = ex2f(fmaf(sacc[nt][rh * 2 + 1], L2E, -mnl));
                rs += p0 + p1;
                paf[nt >> 1][((nt & 1) << 1) + rh] =
                    pack_f16(__float2half_rn(p0), __float2half_rn(p1));
            }
            rs += __shfl_xor_sync(0xffffffffu, rs, 1);
            rs += __shfl_xor_sync(0xffffffffu, rs, 2);
            l_[rh] = l_[rh] * sc + rs;
            m_[rh] = mn;
#pragma unroll
            for (int ntd = 0; ntd < 8; ntd++) {
                acc2[ntd][rh * 2] *= sc;
                acc2[ntd][rh * 2 + 1] *= sc;
            }
        }

        // ---- O += P . V  (P from registers, V via ldsm4t)
#pragma unroll
        for (int s = 0; s < 8; s++) {
            int vrow = (s << 4) + v_rbase;
            u32 vro = (u32)(vrow << 7);
            u32 v7 = (u32)(vrow & 7);
            u32 v_[4][4];
#pragma unroll
            for (int g = 0; g < 4; g++) {
                u32 ch = (((v_cb + 2u * g) ^ v7) << 4);
                ldsm4t(sV + vro + ch, v_[g][0], v_[g][1], v_[g][2], v_[g][3]);
            }
#pragma unroll
            for (int ntd = 0; ntd < 8; ntd++) {
                int g = ntd >> 1, su = (ntd & 1) << 1;
                mma16816(acc2[ntd], paf[s][0], paf[s][1], paf[s][2], paf[s][3],
                         v_[g][su], v_[g][su + 1]);
            }
        }
    }

    // ---- epilogue: normalize (l in registers), fp16 write [B*T, H*D]
    int b = bh >> 4, h = bh & 15;
#pragma unroll
    for (int rh = 0; rh < 2; rh++) {
        float inv = 1.0f / l_[rh];
        int t = (qi << 7) + Wm + (lane >> 2) + rh * 8;
        size_t rowbase = ((size_t)(b * Tt + t)) * (Hh * Dd) + h * Dd;
#pragma unroll
        for (int ntd = 0; ntd < 8; ntd++) {
            int d = ntd * 8 + ((lane & 3) << 1);
            *(u32*)(g_a + rowbase + d) =
                pack_f16(__float2half_rn(acc2[ntd][rh * 2] * inv),
                         __float2half_rn(acc2[ntd][rh * 2 + 1] * inv));
        }
    }
}

// ---------------------------------------------------------------------------
extern "C" void kernel_launch(void* const* d_in, const int* in_sizes, int n_in,
                              void* d_out, int out_size) {
    const float* x  = (const float*)d_in[0];
    const float* Wq = (const float*)d_in[1];
    const float* Wk = (const float*)d_in[2];
    const float* Wv = (const float*)d_in[3];
    const float* Wo = (const float*)d_in[4];
    float* out = (float*)d_out;

    cudaFuncSetAttribute(qkv_mma, cudaFuncAttributeMaxDynamicSharedMemorySize, G1_SMEM);
    cudaFuncSetAttribute(out_mma, cudaFuncAttributeMaxDynamicSharedMemorySize, G1_SMEM);
    cudaFuncSetAttribute(attn_mma, cudaFuncAttributeMaxDynamicSharedMemorySize, ATTN_SMEM);

    conv_x<<<8192, 256>>>(x);
    prep_wqkv<<<dim3(2, 32, 48), 256>>>(Wq, Wk, Wv);
    prep_wo<<<dim3(32, 32), 256>>>(Wo);
    qkv_mma<<<dim3(24, 64), 256, G1_SMEM>>>();
    attn_mma<<<dim3(Tt / 128, Bb * Hh), 256, ATTN_SMEM>>>();
    out_mma<<<dim3(8, 64), 256, G1_SMEM>>>(out);
}

// round 12
// speedup vs baseline: 8.7700x; 1.0012x over previous
#include <cuda_runtime.h>
#include <cuda_fp16.h>

#define Bb 4
#define Tt 2048
#define Ee 1024
#define Hh 16
#define Dd 64
#define MT (Bb * Tt)   // 8192 rows

typedef unsigned long long ull;
typedef unsigned int u32;

// ---------------- device scratch (allocation-free rule) ----------------
__device__ __align__(16) __half g_x[(size_t)MT * Ee];               // x single fp16
__device__ __align__(16) __half g_wt[(size_t)3 * Hh * Dd * Ee];     // [mat][h*64+d][e], Wq pre-scaled 1/8
__device__ __align__(16) __half g_wot[(size_t)Ee * Ee];             // [n][e] single fp16
__device__ __align__(16) __half g_a[(size_t)MT * Ee];               // attn out, single fp16
// layout [bh][t][d], all single fp16
__device__ __align__(16) __half g_q[(size_t)Bb * Hh * Tt * Dd];
__device__ __align__(16) __half g_k[(size_t)Bb * Hh * Tt * Dd];
__device__ __align__(16) __half g_v[(size_t)Bb * Hh * Tt * Dd];

// ---------------- PTX helpers ----------------
__device__ __forceinline__ u32 smem_u32(const void* p) {
    u32 a;
    asm("{ .reg .u64 t; cvta.to.shared.u64 t, %1; cvt.u32.u64 %0, t; }"
        : "=r"(a) : "l"(p));
    return a;
}
__device__ __forceinline__ void cpa16(u32 dst, const void* src) {
    asm volatile("cp.async.cg.shared.global [%0], [%1], 16;"
                 :: "r"(dst), "l"(src) : "memory");
}
#define CP_COMMIT() asm volatile("cp.async.commit_group;" ::: "memory")
#define CP_WAIT1()  asm volatile("cp.async.wait_group 1;" ::: "memory")
#define CP_WAIT0()  asm volatile("cp.async.wait_group 0;" ::: "memory")

__device__ __forceinline__ void ldsm4(u32 addr, u32& r0, u32& r1, u32& r2, u32& r3) {
    asm volatile("ldmatrix.sync.aligned.m8n8.x4.shared.b16 {%0,%1,%2,%3}, [%4];"
                 : "=r"(r0), "=r"(r1), "=r"(r2), "=r"(r3) : "r"(addr));
}
__device__ __forceinline__ void ldsm4t(u32 addr, u32& r0, u32& r1, u32& r2, u32& r3) {
    asm volatile("ldmatrix.sync.aligned.m8n8.x4.trans.shared.b16 {%0,%1,%2,%3}, [%4];"
                 : "=r"(r0), "=r"(r1), "=r"(r2), "=r"(r3) : "r"(addr));
}
__device__ __forceinline__ void mma16816(float* d, u32 a0, u32 a1, u32 a2, u32 a3,
                                         u32 b0, u32 b1) {
    asm volatile(
        "mma.sync.aligned.m16n8k16.row.col.f32.f16.f16.f32 "
        "{%0,%1,%2,%3},{%4,%5,%6,%7},{%8,%9},{%0,%1,%2,%3};"
        : "+f"(d[0]), "+f"(d[1]), "+f"(d[2]), "+f"(d[3])
        : "r"(a0), "r"(a1), "r"(a2), "r"(a3), "r"(b0), "r"(b1));
}
__device__ __forceinline__ float ex2f(float x) {
    float r; asm("ex2.approx.f32 %0,%1;" : "=f"(r) : "f"(x)); return r;
}
__device__ __forceinline__ u32 pack_f16(__half a, __half b) {
    __half2 t = __halves2half2(a, b);
    return *(u32*)&t;
}

#define L2E 1.4426950408889634f

// ---------------------------------------------------------------------------
// Prep kernels
// ---------------------------------------------------------------------------
__global__ void __launch_bounds__(256) conv_x(const float* __restrict__ x) {
    size_t i = ((size_t)blockIdx.x * 256 + threadIdx.x) * 4;
    float4 v = *(const float4*)&x[i];
    *(u32*)(g_x + i) = pack_f16(__float2half_rn(v.x), __float2half_rn(v.y));
    *(u32*)(g_x + i + 2) = pack_f16(__float2half_rn(v.z), __float2half_rn(v.w));
}

__global__ void __launch_bounds__(256) prep_wqkv(
    const float* __restrict__ Wq, const float* __restrict__ Wk,
    const float* __restrict__ Wv)
{
    __shared__ float tile[32][33];
    int z = blockIdx.z;
    int mat = z >> 4, h = z & 15;
    const float* W = (mat == 0 ? Wq : (mat == 1 ? Wk : Wv)) + (size_t)h * Ee * Dd;
    float scale = (mat == 0) ? 0.125f : 1.0f;   // fold D^-1/2 into Wq
    __half* dst = g_wt + ((size_t)mat * Hh + h) * Dd * Ee;
    int e0 = blockIdx.y << 5, d0 = blockIdx.x << 5;
    int tx = threadIdx.x & 31, ty = threadIdx.x >> 5;
#pragma unroll
    for (int j = 0; j < 4; j++)
        tile[ty + j * 8][tx] = W[(size_t)(e0 + ty + j * 8) * Dd + d0 + tx];
    __syncthreads();
#pragma unroll
    for (int j = 0; j < 4; j++) {
        int rr = ty + j * 8;
        dst[(size_t)(d0 + rr) * Ee + e0 + tx] = __float2half_rn(tile[tx][rr] * scale);
    }
}

__global__ void __launch_bounds__(256) prep_wo(const float* __restrict__ Wo) {
    __shared__ float tile[32][33];
    int n0 = blockIdx.x << 5, e0 = blockIdx.y << 5;
    int tx = threadIdx.x & 31, ty = threadIdx.x >> 5;
#pragma unroll
    for (int j = 0; j < 4; j++)
        tile[ty + j * 8][tx] = Wo[(size_t)(e0 + ty + j * 8) * Ee + n0 + tx];
    __syncthreads();
#pragma unroll
    for (int j = 0; j < 4; j++) {
        int rr = ty + j * 8;
        g_wot[(size_t)(n0 + rr) * Ee + e0 + tx] = __float2half_rn(tile[tx][rr]);
    }
}

// ---------------------------------------------------------------------------
// mma.sync GEMM machinery (3-stage pipelined dense GEMMs)
// ---------------------------------------------------------------------------
#define TILE_B   16384u
#define G1_BUF   32768u
#define G1_SMEM  (3u * G1_BUF)   // 96KB, 2 CTA/SM

__device__ __forceinline__ void copy_tile_async(u32 tb, const __half* sp, int tid) {
#pragma unroll
    for (int it = 0; it < 4; it++) {
        int cid = it * 256 + tid;
        int row = cid >> 3, c = cid & 7;
        u32 dst = tb + (u32)(row << 7) + (u32)(((c ^ (row & 7))) << 4);
        cpa16(dst, sp + (size_t)row * Ee + c * 8);
    }
}
__device__ __forceinline__ void copy_tile_c(u32 tb, const __half* sp, int tid) {
#pragma unroll
    for (int it = 0; it < 4; it++) {
        int cid = it * 256 + tid;
        int row = cid >> 3, c = cid & 7;
        u32 dst = tb + (u32)(row << 7) + (u32)(((c ^ (row & 7))) << 4);
        cpa16(dst, sp + (size_t)cid * 8);
    }
}

__device__ __forceinline__ void frag_setup(int lane, int Wm, int Wn,
                                           u32* aoff, u32* a7, u32& cA,
                                           u32* boff, u32* b7, u32& cB) {
#pragma unroll
    for (int mt = 0; mt < 4; mt++) {
        int r = Wm + mt * 16 + (lane & 15);
        aoff[mt] = (u32)(r << 7);
        a7[mt] = (u32)(r & 7);
    }
#pragma unroll
    for (int np = 0; np < 2; np++) {
        int r = Wn + np * 16 + ((lane >> 4) << 3) + (lane & 7);
        boff[np] = (u32)(r << 7);
        b7[np] = (u32)(r & 7);
    }
    cA = (u32)(lane >> 4);
    cB = (u32)((lane >> 3) & 1);
}

// 1-pass chunk: single A, single B
__device__ __forceinline__ void gemm_chunk1(
    u32 sA, u32 sB,
    const u32* aoff, const u32* a7, u32 cA,
    const u32* boff, const u32* b7, u32 cB,
    float acc[4][4][4])
{
#pragma unroll
    for (int s = 0; s < 4; s++) {
        u32 a_[4][4], b_[2][4];
#pragma unroll
        for (int mt = 0; mt < 4; mt++) {
            u32 ca = (u32)(((2 * s + cA) ^ a7[mt]) << 4);
            ldsm4(sA + aoff[mt] + ca, a_[mt][0], a_[mt][1], a_[mt][2], a_[mt][3]);
        }
#pragma unroll
        for (int np = 0; np < 2; np++) {
            u32 cb = (u32)(((2 * s + cB) ^ b7[np]) << 4);
            ldsm4(sB + boff[np] + cb, b_[np][0], b_[np][1], b_[np][2], b_[np][3]);
        }
#pragma unroll
        for (int mt = 0; mt < 4; mt++) {
#pragma unroll
            for (int nt = 0; nt < 4; nt++) {
                int np = nt >> 1, sel = (nt & 1) << 1;
                mma16816(acc[mt][nt], a_[mt][0], a_[mt][1], a_[mt][2], a_[mt][3],
                         b_[np][sel], b_[np][sel + 1]);
            }
        }
    }
}

// ---------------------------------------------------------------------------
// QKV projection (1-pass, 3-stage, 2 CTA/SM) -> q/k/v single fp16.
// grid (24, 64), block 256, 96KB smem.
// ---------------------------------------------------------------------------
__global__ void __launch_bounds__(256, 2) qkv_mma() {
    extern __shared__ char smraw[];
    u32 sbase = smem_u32(smraw);

    int tid = threadIdx.x;
    int lane = tid & 31, w = tid >> 5;
    int Wm = (w & 1) << 6, Wn = (w >> 1) << 5;

    int n0 = blockIdx.x << 7;
    int m0 = blockIdx.y << 7;
    int mat = n0 >> 10;
    int nb = n0 & 1023;

    const __half* A = g_x + (size_t)m0 * Ee;
    const __half* Bw = g_wt + (size_t)mat * Hh * Dd * Ee + (size_t)nb * Ee;

    u32 aoff[4], a7[4], boff[2], b7[2], cA, cB;
    frag_setup(lane, Wm, Wn, aoff, a7, cA, boff, b7, cB);

    float acc[4][4][4] = {};

#pragma unroll
    for (int c = 0; c < 2; c++) {
        u32 bu = sbase + (u32)c * G1_BUF;
        copy_tile_async(bu, A + (c << 6), tid);
        copy_tile_async(bu + TILE_B, Bw + (c << 6), tid);
        CP_COMMIT();
    }

    for (int c = 0; c < 16; c++) {
        if (c == 15) { CP_WAIT0(); } else { CP_WAIT1(); }
        __syncthreads();
        if (c < 14) {
            u32 bu = sbase + (u32)((c + 2) % 3) * G1_BUF;
            int k0 = (c + 2) << 6;
            copy_tile_async(bu, A + k0, tid);
            copy_tile_async(bu + TILE_B, Bw + k0, tid);
            CP_COMMIT();
        }
        u32 sb = sbase + (u32)(c % 3) * G1_BUF;
        gemm_chunk1(sb, sb + TILE_B, aoff, a7, cA, boff, b7, cB, acc);
    }

    __half* outp = (mat == 0) ? g_q : (mat == 1) ? g_k : g_v;
#pragma unroll
    for (int mt = 0; mt < 4; mt++) {
#pragma unroll
        for (int nt = 0; nt < 4; nt++) {
            int n = nb + Wn + nt * 8 + ((lane & 3) << 1);
            int h = n >> 6, d = n & 63;
            int m = m0 + Wm + mt * 16 + (lane >> 2);
            int b = m >> 11, t = m & 2047;
            size_t base = (((size_t)(b * Hh + h)) * Tt + t) * Dd + d;
            *(u32*)(outp + base) = pack_f16(__float2half_rn(acc[mt][nt][0]),
                                            __float2half_rn(acc[mt][nt][1]));
            *(u32*)(outp + base + 8 * Dd) = pack_f16(__float2half_rn(acc[mt][nt][2]),
                                                     __float2half_rn(acc[mt][nt][3]));
        }
    }
}

// ---------------------------------------------------------------------------
// Out projection (1-pass, 3-stage, 2 CTA/SM): out = A_f16 * Wo_f16.
// grid (8, 64), block 256.
// ---------------------------------------------------------------------------
__global__ void __launch_bounds__(256, 2) out_mma(float* __restrict__ out) {
    extern __shared__ char smraw[];
    u32 sbase = smem_u32(smraw);

    int tid = threadIdx.x;
    int lane = tid & 31, w = tid >> 5;
    int Wm = (w & 1) << 6, Wn = (w >> 1) << 5;

    int n0 = blockIdx.x << 7;
    int m0 = blockIdx.y << 7;

    const __half* A = g_a + (size_t)m0 * Ee;
    const __half* B = g_wot + (size_t)n0 * Ee;

    u32 aoff[4], a7[4], boff[2], b7[2], cA, cB;
    frag_setup(lane, Wm, Wn, aoff, a7, cA, boff, b7, cB);

    float acc[4][4][4] = {};

#pragma unroll
    for (int c = 0; c < 2; c++) {
        u32 bu = sbase + (u32)c * G1_BUF;
        copy_tile_async(bu, A + (c << 6), tid);
        copy_tile_async(bu + TILE_B, B + (c << 6), tid);
        CP_COMMIT();
    }

    for (int c = 0; c < 16; c++) {
        if (c == 15) { CP_WAIT0(); } else { CP_WAIT1(); }
        __syncthreads();
        if (c < 14) {
            u32 bu = sbase + (u32)((c + 2) % 3) * G1_BUF;
            int k0 = (c + 2) << 6;
            copy_tile_async(bu, A + k0, tid);
            copy_tile_async(bu + TILE_B, B + k0, tid);
            CP_COMMIT();
        }
        u32 sb = sbase + (u32)(c % 3) * G1_BUF;
        gemm_chunk1(sb, sb + TILE_B, aoff, a7, cA, boff, b7, cB, acc);
    }

#pragma unroll
    for (int mt = 0; mt < 4; mt++) {
#pragma unroll
        for (int nt = 0; nt < 4; nt++) {
            int n = n0 + Wn + nt * 8 + ((lane & 3) << 1);
            int m = m0 + Wm + mt * 16 + (lane >> 2);
            *(float2*)&out[(size_t)m * Ee + n] = make_float2(acc[mt][nt][0], acc[mt][nt][1]);
            *(float2*)&out[(size_t)(m + 8) * Ee + n] = make_float2(acc[mt][nt][2], acc[mt][nt][3]);
        }
    }
}

// ---------------------------------------------------------------------------
// FA2-style tensor-core causal flash attention, 2 CTA/SM (16 warps).
// Warp owns 16 query rows: in-warp softmax, P stays in registers.
// grid (16 reversed, 64), block 256, 80KB dynamic smem.
// ---------------------------------------------------------------------------
#define AQ  0u
#define AK0 16384u
#define AK1 32768u
#define AV0 49152u
#define AV1 65536u
#define ATTN_SMEM 81920u

__global__ void __launch_bounds__(256, 2) attn_mma() {
    extern __shared__ char smraw[];
    u32 sb = smem_u32(smraw);

    int tid = threadIdx.x, lane = tid & 31, w = tid >> 5;
    int qi = (int)gridDim.x - 1 - (int)blockIdx.x;
    int bh = blockIdx.y;
    size_t tbase = (size_t)bh * Tt * Dd;
    const __half* qp = g_q + tbase + ((size_t)qi << 7) * Dd;
    const __half* kp = g_k + tbase;
    const __half* vp = g_v + tbase;

    int Wm = w << 4;   // warp owns q rows [Wm, Wm+16)

    // S A-frag (Q rows)
    int ar = Wm + (lane & 15);
    u32 aoff = (u32)(ar << 7), a7 = (u32)(ar & 7);
    u32 cA = (u32)(lane >> 4);
    // S B-frags (K rows 0..127, 8 groups of n16)
    u32 boff[8], b7[8];
#pragma unroll
    for (int np = 0; np < 8; np++) {
        int r = np * 16 + ((lane >> 4) << 3) + (lane & 7);
        boff[np] = (u32)(r << 7);
        b7[np] = (u32)(r & 7);
    }
    u32 cB = (u32)((lane >> 3) & 1);
    // PV V-frags (ldsm4t)
    int vj = lane >> 3;
    int v_rbase = ((vj & 1) << 3) + (lane & 7);
    u32 v_cb = (u32)(vj >> 1);

    float m_[2] = {-1e30f, -1e30f};
    float l_[2] = {0.f, 0.f};
    float acc2[8][4] = {};

    // prologue: Q + K(0) + V(0)
    copy_tile_c(sb + AQ, qp, tid);
    copy_tile_c(sb + AK0, kp, tid);
    copy_tile_c(sb + AV0, vp, tid);
    CP_COMMIT();

    for (int j = 0; j <= qi; j++) {
        int buf = j & 1;
        CP_WAIT0();
        __syncthreads();      // K/V(j) visible; all warps done with j-1 buffers

        if (j < qi) {         // prefetch K/V(j+1) into the other buffers
            copy_tile_c(sb + (buf ? AK0 : AK1), kp + ((size_t)(j + 1) << 7) * Dd, tid);
            copy_tile_c(sb + (buf ? AV0 : AV1), vp + ((size_t)(j + 1) << 7) * Dd, tid);
            CP_COMMIT();
        }
        u32 sK = sb + (buf ? AK1 : AK0);
        u32 sV = sb + (buf ? AV1 : AV0);

        // ---- S = Q . K^T  (warp: m16 x n128)
        float sacc[16][4] = {};
#pragma unroll
        for (int s = 0; s < 4; s++) {
            u32 a0, a1, a2, a3;
            ldsm4(sb + AQ + aoff + (((2 * (u32)s + cA) ^ a7) << 4), a0, a1, a2, a3);
#pragma unroll
            for (int np = 0; np < 8; np++) {
                u32 q0, q1, q2, q3;
                ldsm4(sK + boff[np] + (((2 * (u32)s + cB) ^ b7[np]) << 4), q0, q1, q2, q3);
                mma16816(sacc[2 * np], a0, a1, a2, a3, q0, q1);
                mma16816(sacc[2 * np + 1], a0, a1, a2, a3, q2, q3);
            }
        }

        // ---- causal mask on diagonal tile
        if (j == qi) {
#pragma unroll
            for (int nt = 0; nt < 16; nt++)
#pragma unroll
                for (int rg = 0; rg < 4; rg++) {
                    int r = Wm + (lane >> 2) + ((rg >> 1) << 3);
                    int c = nt * 8 + ((lane & 3) << 1) + (rg & 1);
                    if (c > r) sacc[nt][rg] = -1e30f;
                }
        }

        // ---- in-warp online softmax; P -> fp16 A-fragments in registers
        u32 paf[8][4];
#pragma unroll
        for (int rh = 0; rh < 2; rh++) {
            float mx = -1e30f;
#pragma unroll
            for (int nt = 0; nt < 16; nt++) {
                mx = fmaxf(mx, sacc[nt][rh * 2]);
                mx = fmaxf(mx, sacc[nt][rh * 2 + 1]);
            }
            mx = fmaxf(mx, __shfl_xor_sync(0xffffffffu, mx, 1));
            mx = fmaxf(mx, __shfl_xor_sync(0xffffffffu, mx, 2));
            float mn = fmaxf(m_[rh], mx);
            float sc = ex2f((m_[rh] - mn) * L2E);
            float mnl = mn * L2E;
            float rs = 0.f;
#pragma unroll
            for (int nt = 0; nt < 16; nt++) {
                float p0 = ex2f(fmaf(sacc[nt][rh * 2], L2E, -mnl));
                float p1 = ex2f(fmaf(sacc[nt][rh * 2 + 1], L2E, -mnl));
                rs += p0 + p1;
                paf[nt >> 1][((nt & 1) << 1) + rh] =
                    pack_f16(__float2half_rn(p0), __float2half_rn(p1));
            }
            rs += __shfl_xor_sync(0xffffffffu, rs, 1);
            rs += __shfl_xor_sync(0xffffffffu, rs, 2);
            l_[rh] = l_[rh] * sc + rs;
            m_[rh] = mn;
#pragma unroll
            for (int ntd = 0; ntd < 8; ntd++) {
                acc2[ntd][rh * 2] *= sc;
                acc2[ntd][rh * 2 + 1] *= sc;
            }
        }

        // ---- O += P . V  (P from registers, V via ldsm4t)
#pragma unroll
        for (int s = 0; s < 8; s++) {
            int vrow = (s << 4) + v_rbase;
            u32 vro = (u32)(vrow << 7);
            u32 v7 = (u32)(vrow & 7);
            u32 v_[4][4];
#pragma unroll
            for (int g = 0; g < 4; g++) {
                u32 ch = (((v_cb + 2u * g) ^ v7) << 4);
                ldsm4t(sV + vro + ch, v_[g][0], v_[g][1], v_[g][2], v_[g][3]);
            }
#pragma unroll
            for (int ntd = 0; ntd < 8; ntd++) {
                int g = ntd >> 1, su = (ntd & 1) << 1;
                mma16816(acc2[ntd], paf[s][0], paf[s][1], paf[s][2], paf[s][3],
                         v_[g][su], v_[g][su + 1]);
            }
        }
    }

    // ---- epilogue: normalize (l in registers), fp16 write [B*T, H*D]
    int b = bh >> 4, h = bh & 15;
#pragma unroll
    for (int rh = 0; rh < 2; rh++) {
        float inv = 1.0f / l_[rh];
        int t = (qi << 7) + Wm + (lane >> 2) + rh * 8;
        size_t rowbase = ((size_t)(b * Tt + t)) * (Hh * Dd) + h * Dd;
#pragma unroll
        for (int ntd = 0; ntd < 8; ntd++) {
            int d = ntd * 8 + ((lane & 3) << 1);
            *(u32*)(g_a + rowbase + d) =
                pack_f16(__float2half_rn(acc2[ntd][rh * 2] * inv),
                         __float2half_rn(acc2[ntd][rh * 2 + 1] * inv));
        }
    }
}

// ---------------------------------------------------------------------------
extern "C" void kernel_launch(void* const* d_in, const int* in_sizes, int n_in,
                              void* d_out, int out_size) {
    const float* x  = (const float*)d_in[0];
    const float* Wq = (const float*)d_in[1];
    const float* Wk = (const float*)d_in[2];
    const float* Wv = (const float*)d_in[3];
    const float* Wo = (const float*)d_in[4];
    float* out = (float*)d_out;

    cudaFuncSetAttribute(qkv_mma, cudaFuncAttributeMaxDynamicSharedMemorySize, G1_SMEM);
    cudaFuncSetAttribute(out_mma, cudaFuncAttributeMaxDynamicSharedMemorySize, G1_SMEM);
    cudaFuncSetAttribute(attn_mma, cudaFuncAttributeMaxDynamicSharedMemorySize, ATTN_SMEM);

    conv_x<<<8192, 256>>>(x);
    prep_wqkv<<<dim3(2, 32, 48), 256>>>(Wq, Wk, Wv);
    prep_wo<<<dim3(32, 32), 256>>>(Wo);
    qkv_mma<<<dim3(24, 64), 256, G1_SMEM>>>();
    attn_mma<<<dim3(Tt / 128, Bb * Hh), 256, ATTN_SMEM>>>();
    out_mma<<<dim3(8, 64), 256, G1_SMEM>>>(out);
}